// round 5
// baseline (speedup 1.0000x reference)
#include <cuda_runtime.h>
#include <math.h>

#define BB 32
#define NN 1024
#define CC 14
#define KK 9
#define EE 128
#define HH 128
#define NCC 25
#define NODES (BB*NN)

// output layout: logits (B,N,25) | X_out (B,N,14,3) | pd (B,N,9)
#define L_SZ (NODES*NCC)
#define X_SZ (NODES*CC*3)
#define XOFF L_SZ
#define POFF (L_SZ + X_SZ)

// scratch (allowed: __device__ globals, no runtime alloc)
__device__ float g_Hh[NODES*EE];
__device__ float g_Hn[NODES*EE];
__device__ int   g_idx[NODES*KK];

__device__ __forceinline__ float silu_f(float x){ return x/(1.0f+expf(-x)); }
__device__ __forceinline__ float sigm_f(float x){ return 1.0f/(1.0f+expf(-x)); }

// ---------------- K1: Hh = emb[S] + time_emb(t) ----------------
__global__ __launch_bounds__(128) void k_hh(
    const float* __restrict__ t, const int* __restrict__ S,
    const float* __restrict__ emb,
    const float* __restrict__ Wt1, const float* __restrict__ bt1,
    const float* __restrict__ Wt2, const float* __restrict__ bt2)
{
    int node = blockIdx.x;
    int j = threadIdx.x;
    __shared__ float g[128], h[128];
    float tv = t[node];
    float d = tv - (float)j*(1.0f/127.0f) + 1e-6f;
    g[j] = expf(-8064.5f*d*d);
    __syncthreads();
    float a = bt1[j];
    #pragma unroll 4
    for (int i = 0; i < 128; i++) a += g[i]*Wt1[i*128+j];
    h[j] = fmaxf(a, 0.0f);
    __syncthreads();
    float a2 = bt2[j];
    #pragma unroll 4
    for (int i = 0; i < 128; i++) a2 += h[i]*Wt2[i*128+j];
    g_Hh[node*128+j] = emb[S[node]*128+j] + a2;
}

// ---------------- K2: top-9 nearest neighbors on ca = X[:,:,1,:] ----------------
__global__ __launch_bounds__(128) void k_knn(const float* __restrict__ X)
{
    __shared__ float sca[NN*3];
    int b = blockIdx.x >> 3;      // 8 tiles of 128 queries per batch
    int tile = blockIdx.x & 7;
    int tj = threadIdx.x;
    for (int u = tj; u < NN*3; u += 128) {
        int n = u/3, d = u - n*3;
        sca[u] = X[((b*NN + n)*CC + 1)*3 + d];
    }
    __syncthreads();
    int n = tile*128 + tj;
    float qx = sca[n*3+0], qy = sca[n*3+1], qz = sca[n*3+2];
    float bd[KK]; int bi[KK];
    #pragma unroll
    for (int i = 0; i < KK; i++){ bd[i] = 1e30f; bi[i] = 0; }
    for (int j = 0; j < NN; j++) {
        float dx = qx - sca[j*3+0];
        float dy = qy - sca[j*3+1];
        float dz = qz - sca[j*3+2];
        float d = dx*dx + dy*dy + dz*dz;
        if (j == n) d = 1e30f;               // eye * 1e10 exclusion
        if (d < bd[KK-1]) {                  // strict <: stable tie order (lower index wins)
            bd[KK-1] = d; bi[KK-1] = j;
            #pragma unroll
            for (int q = KK-1; q > 0; q--) {
                if (bd[q] < bd[q-1]) {
                    float td = bd[q]; bd[q] = bd[q-1]; bd[q-1] = td;
                    int   ti = bi[q]; bi[q] = bi[q-1]; bi[q-1] = ti;
                }
            }
        }
    }
    #pragma unroll
    for (int k = 0; k < KK; k++) g_idx[(b*NN + n)*KK + k] = bi[k];
}

// ---------------- K3: per-node edge FFNs + X_out + Hn + gate + logits ----------------
__global__ __launch_bounds__(128) void k_edge(
    const float* __restrict__ X, const int* __restrict__ S, const float* __restrict__ emb,
    const float* __restrict__ We1, const float* __restrict__ be1,
    const float* __restrict__ We2, const float* __restrict__ be2,
    const float* __restrict__ Wx1, const float* __restrict__ bx1,
    const float* __restrict__ Wx2, const float* __restrict__ bx2,
    const float* __restrict__ Wh1, const float* __restrict__ bh1,
    const float* __restrict__ Wh2, const float* __restrict__ bh2,
    const float* __restrict__ Wp1, const float* __restrict__ bp1,
    const float* __restrict__ Wr1, const float* __restrict__ br1,
    const float* __restrict__ Wr2, const float* __restrict__ br2,
    float* __restrict__ out)
{
    int node = blockIdx.x;
    int tj = threadIdx.x;
    int b = node >> 10;

    __shared__ float shc[128], hcr[128];       // silu(Hh center), raw Hh center
    __shared__ float xcen[42];                 // center coords (14x3)
    __shared__ int   nbr[KK];
    __shared__ float xs[KK][324];              // [silu(Hnb)(128) | silu(radial)(196)]
    __shared__ float relb[KK][42];
    __shared__ float sh1[KK][128];             // silu(h1)
    __shared__ float sm [KK][128];             // silu(m)
    __shared__ float sbuf[KK][128];            // silu(h2)*Wx2
    __shared__ float msum[128], smsum[128];    // sum_k m, silu of it (reused later)
    __shared__ float wk[KK];
    __shared__ float wx2s[128];
    __shared__ float tmpv[128];

    {
        float hv = g_Hh[node*128 + tj];
        hcr[tj] = hv;
        shc[tj] = silu_f(hv);
        wx2s[tj] = Wx2[tj];
        if (tj < 42) xcen[tj] = X[node*CC*3 + tj];
        if (tj < KK) nbr[tj] = g_idx[node*KK + tj];
    }
    __syncthreads();

    // neighbor features + rel vectors
    for (int u = tj; u < KK*128; u += 128) {
        int k = u >> 7, i = u & 127;
        xs[k][i] = silu_f(g_Hh[(b*NN + nbr[k])*128 + i]);
    }
    for (int u = tj; u < KK*42; u += 128) {
        int k = u/42, i = u - k*42;
        relb[k][i] = xcen[i] - X[(b*NN + nbr[k])*CC*3 + i];
    }
    __syncthreads();

    // radial = rel @ rel^T / C  (14x14 Gram), then silu
    for (int u = tj; u < KK*196; u += 128) {
        int k = u/196, i = u - k*196;
        int c = i/14, e = i - c*14;
        const float* r1 = &relb[k][c*3];
        const float* r2 = &relb[k][e*3];
        float rv = (r1[0]*r2[0] + r1[1]*r2[1] + r1[2]*r2[2]) * (1.0f/14.0f);
        xs[k][128 + i] = silu_f(rv);
    }
    __syncthreads();

    float acc[KK];

    // GEMM1: 452 -> 128 (center rows shared across all 9 edges)
    {
        float base = be1[tj];
        #pragma unroll 4
        for (int i = 0; i < 128; i++) base += shc[i]*We1[i*128 + tj];
        #pragma unroll
        for (int k = 0; k < KK; k++) acc[k] = base;
        #pragma unroll 2
        for (int i = 0; i < 324; i++) {
            float wv = We1[(128 + i)*128 + tj];
            #pragma unroll
            for (int k = 0; k < KK; k++) acc[k] += xs[k][i]*wv;
        }
        #pragma unroll
        for (int k = 0; k < KK; k++) sh1[k][tj] = silu_f(acc[k]);
    }
    __syncthreads();

    // GEMM2: m = silu(h1) @ We2 + be2 ; msum
    {
        float bv = be2[tj];
        #pragma unroll
        for (int k = 0; k < KK; k++) acc[k] = bv;
        #pragma unroll 2
        for (int i = 0; i < 128; i++) {
            float wv = We2[i*128 + tj];
            #pragma unroll
            for (int k = 0; k < KK; k++) acc[k] += sh1[k][i]*wv;
        }
        float msv = 0.0f;
        #pragma unroll
        for (int k = 0; k < KK; k++) { msv += acc[k]; sm[k][tj] = silu_f(acc[k]); }
        msum[tj] = msv;
        smsum[tj] = silu_f(msv);
    }
    __syncthreads();

    // GEMM3: h2 = silu(m) @ Wx1 + bx1 ; stage silu(h2)*Wx2 for reduction
    {
        float bv = bx1[tj];
        #pragma unroll
        for (int k = 0; k < KK; k++) acc[k] = bv;
        #pragma unroll 2
        for (int i = 0; i < 128; i++) {
            float wv = Wx1[i*128 + tj];
            #pragma unroll
            for (int k = 0; k < KK; k++) acc[k] += sm[k][i]*wv;
        }
        #pragma unroll
        for (int k = 0; k < KK; k++) sbuf[k][tj] = silu_f(acc[k]) * wx2s[tj];
    }
    __syncthreads();

    if (tj < KK) {
        float s = bx2[0];
        for (int i = 0; i < 128; i++) s += sbuf[tj][i];
        wk[tj] = s;
    }
    __syncthreads();

    // X_out = X + mean_k(rel * w)
    if (tj < 42) {
        float s = 0.0f;
        #pragma unroll
        for (int k = 0; k < KK; k++) s += relb[k][tj]*wk[k];
        out[XOFF + node*42 + tj] = xcen[tj] + s*(1.0f/9.0f);
    }

    // Hn = Hh + FFN([Hh, msum])
    {
        float a = bh1[tj];
        #pragma unroll 4
        for (int i = 0; i < 128; i++) a += shc[i]*Wh1[i*128 + tj];
        #pragma unroll 4
        for (int i = 0; i < 128; i++) a += smsum[i]*Wh1[(128 + i)*128 + tj];
        tmpv[tj] = silu_f(a);
    }
    __syncthreads();
    {
        float hn = hcr[tj] + bh2[tj];
        #pragma unroll 4
        for (int i = 0; i < 128; i++) hn += tmpv[i]*Wh2[i*128 + tj];
        g_Hn[node*128 + tj] = hn;
        msum[tj] = silu_f(hn);     // reuse buffer: silu(Hn)
    }
    __syncthreads();

    // gate = sigmoid(silu(Hn)@Wp1 + bp1) ; x0 = H0*gate
    {
        float a = bp1[tj];
        #pragma unroll 4
        for (int i = 0; i < 128; i++) a += msum[i]*Wp1[i*128 + tj];
        float gate = sigm_f(a);
        float h0 = emb[S[node]*128 + tj];
        smsum[tj] = silu_f(h0*gate);    // reuse: silu(x0)
    }
    __syncthreads();
    {
        float a = br1[tj];
        #pragma unroll 4
        for (int i = 0; i < 128; i++) a += smsum[i]*Wr1[i*128 + tj];
        tmpv[tj] = silu_f(a);
    }
    __syncthreads();
    if (tj < NCC) {
        float a = br2[tj];
        for (int i = 0; i < 128; i++) a += tmpv[i]*Wr2[i*NCC + tj];
        out[node*NCC + tj] = a;
    }
}

// ---------------- K4: pd (bidirectional pair FFN) ----------------
__global__ __launch_bounds__(128) void k_pd(
    const float* __restrict__ Wd1, const float* __restrict__ bd1,
    const float* __restrict__ Wd2, const float* __restrict__ bd2,
    float* __restrict__ out)
{
    int node = blockIdx.x;
    int tj = threadIdx.x;
    int b = node >> 10;

    __shared__ float shc[128];
    __shared__ int   nbr[KK];
    __shared__ float xsd[KK][128];
    __shared__ float sA[KK][128], sB[KK][128];

    shc[tj] = silu_f(g_Hn[node*128 + tj]);
    if (tj < KK) nbr[tj] = g_idx[node*KK + tj];
    __syncthreads();
    for (int u = tj; u < KK*128; u += 128) {
        int k = u >> 7, i = u & 127;
        xsd[k][i] = silu_f(g_Hn[(b*NN + nbr[k])*128 + i]);
    }
    __syncthreads();

    float aA[KK], aB[KK];
    float bv = bd1[tj];
    #pragma unroll
    for (int k = 0; k < KK; k++){ aA[k] = bv; aB[k] = bv; }
    #pragma unroll 2
    for (int i = 0; i < 128; i++) {
        float w1 = Wd1[i*128 + tj];
        float w2 = Wd1[(128 + i)*128 + tj];
        float hc = shc[i];
        #pragma unroll
        for (int k = 0; k < KK; k++) {
            float hd = xsd[k][i];
            aA[k] += hc*w1 + hd*w2;   // concat [Hs, Hd]
            aB[k] += hd*w1 + hc*w2;   // concat [Hd, Hs]
        }
    }
    float wd2 = Wd2[tj];
    #pragma unroll
    for (int k = 0; k < KK; k++) {
        sA[k][tj] = silu_f(aA[k]) * wd2;
        sB[k][tj] = silu_f(aB[k]) * wd2;
    }
    __syncthreads();
    if (tj < KK) {
        float s = 2.0f*bd2[0];
        for (int i = 0; i < 128; i++) s += sA[tj][i] + sB[tj][i];
        out[POFF + node*KK + tj] = s;
    }
}

// ---------------- launcher ----------------
extern "C" void kernel_launch(void* const* d_in, const int* in_sizes, int n_in,
                              void* d_out, int out_size)
{
    const float* X   = (const float*)d_in[0];
    const int*   S   = (const int*)  d_in[1];
    const float* t   = (const float*)d_in[2];
    const float* emb = (const float*)d_in[3];
    const float* Wt1 = (const float*)d_in[4];
    const float* bt1 = (const float*)d_in[5];
    const float* Wt2 = (const float*)d_in[6];
    const float* bt2 = (const float*)d_in[7];
    const float* We1 = (const float*)d_in[8];
    const float* be1 = (const float*)d_in[9];
    const float* We2 = (const float*)d_in[10];
    const float* be2 = (const float*)d_in[11];
    const float* Wx1 = (const float*)d_in[12];
    const float* bx1 = (const float*)d_in[13];
    const float* Wx2 = (const float*)d_in[14];
    const float* bx2 = (const float*)d_in[15];
    const float* Wh1 = (const float*)d_in[16];
    const float* bh1 = (const float*)d_in[17];
    const float* Wh2 = (const float*)d_in[18];
    const float* bh2 = (const float*)d_in[19];
    const float* Wd1 = (const float*)d_in[20];
    const float* bd1 = (const float*)d_in[21];
    const float* Wd2 = (const float*)d_in[22];
    const float* bd2 = (const float*)d_in[23];
    const float* Wp1 = (const float*)d_in[24];
    const float* bp1 = (const float*)d_in[25];
    const float* Wr1 = (const float*)d_in[26];
    const float* br1 = (const float*)d_in[27];
    const float* Wr2 = (const float*)d_in[28];
    const float* br2 = (const float*)d_in[29];
    float* out = (float*)d_out;

    k_hh<<<NODES, 128>>>(t, S, emb, Wt1, bt1, Wt2, bt2);
    k_knn<<<BB*(NN/128), 128>>>(X);
    k_edge<<<NODES, 128>>>(X, S, emb,
                           We1, be1, We2, be2,
                           Wx1, bx1, Wx2, bx2,
                           Wh1, bh1, Wh2, bh2,
                           Wp1, bp1, Wr1, br1, Wr2, br2,
                           out);
    k_pd<<<NODES, 128>>>(Wd1, bd1, Wd2, bd2, out);
}

// round 6
// speedup vs baseline: 1.5853x; 1.5853x over previous
#include <cuda_runtime.h>
#include <math.h>

#define BB 32
#define NN 1024
#define CC 14
#define KK 9
#define EE 128
#define HH 128
#define NCC 25
#define NODES (BB*NN)

// output layout: logits (B,N,25) | X_out (B,N,14,3) | pd (B,N,9)
#define L_SZ (NODES*NCC)
#define X_SZ (NODES*CC*3)
#define XOFF L_SZ
#define POFF (L_SZ + X_SZ)

// scratch (allowed: __device__ globals, no runtime alloc)
__device__ float g_Hh[NODES*EE];
__device__ float g_Hn[NODES*EE];
__device__ int   g_idx[NODES*KK];

// fast transcendentals: MUFU.EX2 + MUFU.RCP (~2^-21 rel err; budget is 1e-3)
__device__ __forceinline__ float silu_f(float x){ return __fdividef(x, 1.0f + __expf(-x)); }
__device__ __forceinline__ float sigm_f(float x){ return __fdividef(1.0f, 1.0f + __expf(-x)); }

// ---------------- K1: Hh = emb[S] + time_emb(t) ----------------
__global__ __launch_bounds__(128) void k_hh(
    const float* __restrict__ t, const int* __restrict__ S,
    const float* __restrict__ emb,
    const float* __restrict__ Wt1, const float* __restrict__ bt1,
    const float* __restrict__ Wt2, const float* __restrict__ bt2)
{
    int node = blockIdx.x;
    int j = threadIdx.x;
    __shared__ float4 g4[32], h4[32];
    float tv = t[node];
    float d = tv - (float)j*(1.0f/127.0f) + 1e-6f;
    ((float*)g4)[j] = expf(-8064.5f*d*d);   // keep precise exp here (argument can be large)
    __syncthreads();
    float a = bt1[j];
    #pragma unroll 8
    for (int i4 = 0; i4 < 32; i4++) {
        float4 g = g4[i4];
        int i = 4*i4;
        a += g.x*Wt1[(i+0)*128+j] + g.y*Wt1[(i+1)*128+j]
           + g.z*Wt1[(i+2)*128+j] + g.w*Wt1[(i+3)*128+j];
    }
    ((float*)h4)[j] = fmaxf(a, 0.0f);
    __syncthreads();
    float a2 = bt2[j];
    #pragma unroll 8
    for (int i4 = 0; i4 < 32; i4++) {
        float4 h = h4[i4];
        int i = 4*i4;
        a2 += h.x*Wt2[(i+0)*128+j] + h.y*Wt2[(i+1)*128+j]
            + h.z*Wt2[(i+2)*128+j] + h.w*Wt2[(i+3)*128+j];
    }
    g_Hh[node*128+j] = emb[S[node]*128+j] + a2;
}

// ---------------- K2: top-9 nearest neighbors on ca = X[:,:,1,:] ----------------
__global__ __launch_bounds__(128) void k_knn(const float* __restrict__ X)
{
    __shared__ float sca[NN*3];
    int b = blockIdx.x >> 3;
    int tile = blockIdx.x & 7;
    int tj = threadIdx.x;
    for (int u = tj; u < NN*3; u += 128) {
        int n = u/3, d = u - n*3;
        sca[u] = X[((b*NN + n)*CC + 1)*3 + d];
    }
    __syncthreads();
    int n = tile*128 + tj;
    float qx = sca[n*3+0], qy = sca[n*3+1], qz = sca[n*3+2];
    float bd[KK]; int bi[KK];
    #pragma unroll
    for (int i = 0; i < KK; i++){ bd[i] = 1e30f; bi[i] = 0; }
    for (int j = 0; j < NN; j++) {
        float dx = qx - sca[j*3+0];
        float dy = qy - sca[j*3+1];
        float dz = qz - sca[j*3+2];
        float d = dx*dx + dy*dy + dz*dz;
        if (j == n) d = 1e30f;
        if (d < bd[KK-1]) {                  // strict <: stable tie order
            bd[KK-1] = d; bi[KK-1] = j;
            #pragma unroll
            for (int q = KK-1; q > 0; q--) {
                if (bd[q] < bd[q-1]) {
                    float td = bd[q]; bd[q] = bd[q-1]; bd[q-1] = td;
                    int   ti = bi[q]; bi[q] = bi[q-1]; bi[q-1] = ti;
                }
            }
        }
    }
    #pragma unroll
    for (int k = 0; k < KK; k++) g_idx[(b*NN + n)*KK + k] = bi[k];
}

// ---------------- K3: per-node edge FFNs + X_out + Hn + gate + logits ----------------
__global__ __launch_bounds__(128) void k_edge(
    const float* __restrict__ X, const int* __restrict__ S, const float* __restrict__ emb,
    const float* __restrict__ We1, const float* __restrict__ be1,
    const float* __restrict__ We2, const float* __restrict__ be2,
    const float* __restrict__ Wx1, const float* __restrict__ bx1,
    const float* __restrict__ Wx2, const float* __restrict__ bx2,
    const float* __restrict__ Wh1, const float* __restrict__ bh1,
    const float* __restrict__ Wh2, const float* __restrict__ bh2,
    const float* __restrict__ Wp1, const float* __restrict__ bp1,
    const float* __restrict__ Wr1, const float* __restrict__ br1,
    const float* __restrict__ Wr2, const float* __restrict__ br2,
    float* __restrict__ out)
{
    int node = blockIdx.x;
    int tj = threadIdx.x;
    int b = node >> 10;

    __shared__ float4 shc4[32];            // silu(Hh center)
    __shared__ float  hcr[128];            // raw Hh center
    __shared__ float  xcen[42];
    __shared__ int    nbr[KK];
    __shared__ float4 xs4[KK][81];         // [silu(Hnb)(128) | silu(radial)(196)] = 324 floats
    __shared__ float  relb[KK][42];
    __shared__ float4 sh14[KK][32];        // silu(h1)
    __shared__ float4 sm4 [KK][32];        // silu(m)
    __shared__ float4 sbuf4[KK][32];       // silu(h2)*Wx2
    __shared__ float  msumS[128];          // sum_k m
    __shared__ float4 smsum4[32];          // silu(sum_k m)
    __shared__ float  wk[KK];
    __shared__ float  wx2s[128];
    __shared__ float4 tmpv4[32];           // silu of hidden layers
    __shared__ float4 snn4[32];            // silu(Hn)
    __shared__ float4 sx04[32];            // silu(H0*gate)

    {
        float hv = g_Hh[node*128 + tj];
        hcr[tj] = hv;
        ((float*)shc4)[tj] = silu_f(hv);
        wx2s[tj] = Wx2[tj];
        if (tj < 42) xcen[tj] = X[node*CC*3 + tj];
        if (tj < KK) nbr[tj] = g_idx[node*KK + tj];
    }
    __syncthreads();

    // neighbor features + rel vectors
    for (int u = tj; u < KK*128; u += 128) {
        int k = u >> 7, i = u & 127;
        ((float*)xs4[k])[i] = silu_f(g_Hh[(b*NN + nbr[k])*128 + i]);
    }
    for (int u = tj; u < KK*42; u += 128) {
        int k = u/42, i = u - k*42;
        relb[k][i] = xcen[i] - X[(b*NN + nbr[k])*CC*3 + i];
    }
    __syncthreads();

    // radial = rel @ rel^T / C (14x14 Gram), silu'd, into xs rows 128..323
    for (int u = tj; u < KK*196; u += 128) {
        int k = u/196, i = u - k*196;
        int c = i/14, e = i - c*14;
        const float* r1 = &relb[k][c*3];
        const float* r2 = &relb[k][e*3];
        float rv = (r1[0]*r2[0] + r1[1]*r2[1] + r1[2]*r2[2]) * (1.0f/14.0f);
        ((float*)xs4[k])[128 + i] = silu_f(rv);
    }
    __syncthreads();

    float acc[KK];

    // GEMM1: 452 -> 128 (center rows shared across all 9 edges)
    {
        float base = be1[tj];
        #pragma unroll 4
        for (int i4 = 0; i4 < 32; i4++) {
            float4 a = shc4[i4];
            int i = 4*i4;
            base += a.x*We1[(i+0)*128+tj] + a.y*We1[(i+1)*128+tj]
                  + a.z*We1[(i+2)*128+tj] + a.w*We1[(i+3)*128+tj];
        }
        #pragma unroll
        for (int k = 0; k < KK; k++) acc[k] = base;
        #pragma unroll 3
        for (int i4 = 0; i4 < 81; i4++) {
            int ib = 128 + 4*i4;
            float w0 = We1[(ib+0)*128+tj];
            float w1 = We1[(ib+1)*128+tj];
            float w2 = We1[(ib+2)*128+tj];
            float w3 = We1[(ib+3)*128+tj];
            #pragma unroll
            for (int k = 0; k < KK; k++) {
                float4 a = xs4[k][i4];
                acc[k] += a.x*w0 + a.y*w1 + a.z*w2 + a.w*w3;
            }
        }
        #pragma unroll
        for (int k = 0; k < KK; k++) ((float*)sh14[k])[tj] = silu_f(acc[k]);
    }
    __syncthreads();

    // GEMM2: m = silu(h1) @ We2 + be2 ; msum
    {
        float bv = be2[tj];
        #pragma unroll
        for (int k = 0; k < KK; k++) acc[k] = bv;
        #pragma unroll 2
        for (int i4 = 0; i4 < 32; i4++) {
            int i = 4*i4;
            float w0 = We2[(i+0)*128+tj];
            float w1 = We2[(i+1)*128+tj];
            float w2 = We2[(i+2)*128+tj];
            float w3 = We2[(i+3)*128+tj];
            #pragma unroll
            for (int k = 0; k < KK; k++) {
                float4 a = sh14[k][i4];
                acc[k] += a.x*w0 + a.y*w1 + a.z*w2 + a.w*w3;
            }
        }
        float msv = 0.0f;
        #pragma unroll
        for (int k = 0; k < KK; k++) { msv += acc[k]; ((float*)sm4[k])[tj] = silu_f(acc[k]); }
        msumS[tj] = msv;
        ((float*)smsum4)[tj] = silu_f(msv);
    }
    __syncthreads();

    // GEMM3: h2 = silu(m) @ Wx1 + bx1 ; stage silu(h2)*Wx2
    {
        float bv = bx1[tj];
        #pragma unroll
        for (int k = 0; k < KK; k++) acc[k] = bv;
        #pragma unroll 2
        for (int i4 = 0; i4 < 32; i4++) {
            int i = 4*i4;
            float w0 = Wx1[(i+0)*128+tj];
            float w1 = Wx1[(i+1)*128+tj];
            float w2 = Wx1[(i+2)*128+tj];
            float w3 = Wx1[(i+3)*128+tj];
            #pragma unroll
            for (int k = 0; k < KK; k++) {
                float4 a = sm4[k][i4];
                acc[k] += a.x*w0 + a.y*w1 + a.z*w2 + a.w*w3;
            }
        }
        float wxv = wx2s[tj];
        #pragma unroll
        for (int k = 0; k < KK; k++) ((float*)sbuf4[k])[tj] = silu_f(acc[k]) * wxv;
    }
    __syncthreads();

    if (tj < KK) {
        float4 s4 = make_float4(0.f,0.f,0.f,0.f);
        #pragma unroll 8
        for (int i4 = 0; i4 < 32; i4++) {
            float4 v = sbuf4[tj][i4];
            s4.x += v.x; s4.y += v.y; s4.z += v.z; s4.w += v.w;
        }
        wk[tj] = bx2[0] + s4.x + s4.y + s4.z + s4.w;
    }
    __syncthreads();

    // X_out = X + mean_k(rel * w)
    if (tj < 42) {
        float s = 0.0f;
        #pragma unroll
        for (int k = 0; k < KK; k++) s += relb[k][tj]*wk[k];
        out[XOFF + node*42 + tj] = xcen[tj] + s*(1.0f/9.0f);
    }

    // Hn = Hh + FFN([Hh, msum])
    {
        float a = bh1[tj];
        #pragma unroll 4
        for (int i4 = 0; i4 < 32; i4++) {
            float4 h = shc4[i4];
            int i = 4*i4;
            a += h.x*Wh1[(i+0)*128+tj] + h.y*Wh1[(i+1)*128+tj]
               + h.z*Wh1[(i+2)*128+tj] + h.w*Wh1[(i+3)*128+tj];
        }
        #pragma unroll 4
        for (int i4 = 0; i4 < 32; i4++) {
            float4 h = smsum4[i4];
            int i = 128 + 4*i4;
            a += h.x*Wh1[(i+0)*128+tj] + h.y*Wh1[(i+1)*128+tj]
               + h.z*Wh1[(i+2)*128+tj] + h.w*Wh1[(i+3)*128+tj];
        }
        ((float*)tmpv4)[tj] = silu_f(a);
    }
    __syncthreads();
    {
        float hn = hcr[tj] + bh2[tj];
        #pragma unroll 4
        for (int i4 = 0; i4 < 32; i4++) {
            float4 h = tmpv4[i4];
            int i = 4*i4;
            hn += h.x*Wh2[(i+0)*128+tj] + h.y*Wh2[(i+1)*128+tj]
                + h.z*Wh2[(i+2)*128+tj] + h.w*Wh2[(i+3)*128+tj];
        }
        g_Hn[node*128 + tj] = hn;
        ((float*)snn4)[tj] = silu_f(hn);
    }
    __syncthreads();

    // gate = sigmoid(silu(Hn)@Wp1 + bp1) ; x0 = H0*gate
    {
        float a = bp1[tj];
        #pragma unroll 4
        for (int i4 = 0; i4 < 32; i4++) {
            float4 h = snn4[i4];
            int i = 4*i4;
            a += h.x*Wp1[(i+0)*128+tj] + h.y*Wp1[(i+1)*128+tj]
               + h.z*Wp1[(i+2)*128+tj] + h.w*Wp1[(i+3)*128+tj];
        }
        float gate = sigm_f(a);
        float h0 = emb[S[node]*128 + tj];
        ((float*)sx04)[tj] = silu_f(h0*gate);
    }
    __syncthreads();
    {
        float a = br1[tj];
        #pragma unroll 4
        for (int i4 = 0; i4 < 32; i4++) {
            float4 h = sx04[i4];
            int i = 4*i4;
            a += h.x*Wr1[(i+0)*128+tj] + h.y*Wr1[(i+1)*128+tj]
               + h.z*Wr1[(i+2)*128+tj] + h.w*Wr1[(i+3)*128+tj];
        }
        ((float*)tmpv4)[tj] = silu_f(a);
    }
    __syncthreads();
    if (tj < NCC) {
        float a = br2[tj];
        #pragma unroll 4
        for (int i4 = 0; i4 < 32; i4++) {
            float4 h = tmpv4[i4];
            int i = 4*i4;
            a += h.x*Wr2[(i+0)*NCC+tj] + h.y*Wr2[(i+1)*NCC+tj]
               + h.z*Wr2[(i+2)*NCC+tj] + h.w*Wr2[(i+3)*NCC+tj];
        }
        out[node*NCC + tj] = a;
    }
}

// ---------------- K4: pd (bidirectional pair FFN) ----------------
__global__ __launch_bounds__(128) void k_pd(
    const float* __restrict__ Wd1, const float* __restrict__ bd1,
    const float* __restrict__ Wd2, const float* __restrict__ bd2,
    float* __restrict__ out)
{
    int node = blockIdx.x;
    int tj = threadIdx.x;
    int b = node >> 10;

    __shared__ float4 shc4[32];
    __shared__ int    nbr[KK];
    __shared__ float4 xsd4[KK][32];
    __shared__ float4 sA4[KK][32], sB4[KK][32];

    ((float*)shc4)[tj] = silu_f(g_Hn[node*128 + tj]);
    if (tj < KK) nbr[tj] = g_idx[node*KK + tj];
    __syncthreads();
    for (int u = tj; u < KK*128; u += 128) {
        int k = u >> 7, i = u & 127;
        ((float*)xsd4[k])[i] = silu_f(g_Hn[(b*NN + nbr[k])*128 + i]);
    }
    __syncthreads();

    float aA[KK], aB[KK];
    float bv = bd1[tj];
    #pragma unroll
    for (int k = 0; k < KK; k++){ aA[k] = bv; aB[k] = bv; }
    #pragma unroll 2
    for (int i4 = 0; i4 < 32; i4++) {
        int i = 4*i4;
        float w10 = Wd1[(i+0)*128+tj], w11 = Wd1[(i+1)*128+tj];
        float w12 = Wd1[(i+2)*128+tj], w13 = Wd1[(i+3)*128+tj];
        float w20 = Wd1[(128+i+0)*128+tj], w21 = Wd1[(128+i+1)*128+tj];
        float w22 = Wd1[(128+i+2)*128+tj], w23 = Wd1[(128+i+3)*128+tj];
        float4 hc = shc4[i4];
        #pragma unroll
        for (int k = 0; k < KK; k++) {
            float4 hd = xsd4[k][i4];
            aA[k] += hc.x*w10 + hc.y*w11 + hc.z*w12 + hc.w*w13
                   + hd.x*w20 + hd.y*w21 + hd.z*w22 + hd.w*w23;
            aB[k] += hd.x*w10 + hd.y*w11 + hd.z*w12 + hd.w*w13
                   + hc.x*w20 + hc.y*w21 + hc.z*w22 + hc.w*w23;
        }
    }
    float wd2 = Wd2[tj];
    #pragma unroll
    for (int k = 0; k < KK; k++) {
        ((float*)sA4[k])[tj] = silu_f(aA[k]) * wd2;
        ((float*)sB4[k])[tj] = silu_f(aB[k]) * wd2;
    }
    __syncthreads();
    if (tj < KK) {
        float4 s4 = make_float4(0.f,0.f,0.f,0.f);
        #pragma unroll 8
        for (int i4 = 0; i4 < 32; i4++) {
            float4 va = sA4[tj][i4];
            float4 vb = sB4[tj][i4];
            s4.x += va.x + vb.x; s4.y += va.y + vb.y;
            s4.z += va.z + vb.z; s4.w += va.w + vb.w;
        }
        out[POFF + node*KK + tj] = 2.0f*bd2[0] + s4.x + s4.y + s4.z + s4.w;
    }
}

// ---------------- launcher ----------------
extern "C" void kernel_launch(void* const* d_in, const int* in_sizes, int n_in,
                              void* d_out, int out_size)
{
    const float* X   = (const float*)d_in[0];
    const int*   S   = (const int*)  d_in[1];
    const float* t   = (const float*)d_in[2];
    const float* emb = (const float*)d_in[3];
    const float* Wt1 = (const float*)d_in[4];
    const float* bt1 = (const float*)d_in[5];
    const float* Wt2 = (const float*)d_in[6];
    const float* bt2 = (const float*)d_in[7];
    const float* We1 = (const float*)d_in[8];
    const float* be1 = (const float*)d_in[9];
    const float* We2 = (const float*)d_in[10];
    const float* be2 = (const float*)d_in[11];
    const float* Wx1 = (const float*)d_in[12];
    const float* bx1 = (const float*)d_in[13];
    const float* Wx2 = (const float*)d_in[14];
    const float* bx2 = (const float*)d_in[15];
    const float* Wh1 = (const float*)d_in[16];
    const float* bh1 = (const float*)d_in[17];
    const float* Wh2 = (const float*)d_in[18];
    const float* bh2 = (const float*)d_in[19];
    const float* Wd1 = (const float*)d_in[20];
    const float* bd1 = (const float*)d_in[21];
    const float* Wd2 = (const float*)d_in[22];
    const float* bd2 = (const float*)d_in[23];
    const float* Wp1 = (const float*)d_in[24];
    const float* bp1 = (const float*)d_in[25];
    const float* Wr1 = (const float*)d_in[26];
    const float* br1 = (const float*)d_in[27];
    const float* Wr2 = (const float*)d_in[28];
    const float* br2 = (const float*)d_in[29];
    float* out = (float*)d_out;

    k_hh<<<NODES, 128>>>(t, S, emb, Wt1, bt1, Wt2, bt2);
    k_knn<<<BB*(NN/128), 128>>>(X);
    k_edge<<<NODES, 128>>>(X, S, emb,
                           We1, be1, We2, be2,
                           Wx1, bx1, Wx2, bx2,
                           Wh1, bh1, Wh2, bh2,
                           Wp1, bp1, Wr1, br1, Wr2, br2,
                           out);
    k_pd<<<NODES, 128>>>(Wd1, bd1, Wd2, bd2, out);
}

// round 8
// speedup vs baseline: 1.6801x; 1.0598x over previous
#include <cuda_runtime.h>
#include <math.h>

#define BB 32
#define NN 1024
#define CC 14
#define KK 9
#define EE 128
#define HH 128
#define NCC 25
#define NODES (BB*NN)

// output layout: logits (B,N,25) | X_out (B,N,14,3) | pd (B,N,9)
#define L_SZ (NODES*NCC)
#define X_SZ (NODES*CC*3)
#define XOFF L_SZ
#define POFF (L_SZ + X_SZ)

// scratch (allowed: __device__ globals, no runtime alloc)
__device__ float g_Hh[NODES*EE];    // raw Hh
__device__ float g_sHh[NODES*EE];   // silu(Hh)
__device__ float g_Hn[NODES*EE];    // raw Hn
__device__ float g_sHn[NODES*EE];   // silu(Hn)
__device__ int   g_idx[NODES*KK];

// fast transcendentals: MUFU.EX2 + MUFU.RCP (~2^-21 rel err; budget is 1e-3)
__device__ __forceinline__ float silu_f(float x){ return __fdividef(x, 1.0f + __expf(-x)); }
__device__ __forceinline__ float sigm_f(float x){ return __fdividef(1.0f, 1.0f + __expf(-x)); }

// ---------------- K1: Hh = emb[S] + time_emb(t) ----------------
__global__ __launch_bounds__(128) void k_hh(
    const float* __restrict__ t, const int* __restrict__ S,
    const float* __restrict__ emb,
    const float* __restrict__ Wt1, const float* __restrict__ bt1,
    const float* __restrict__ Wt2, const float* __restrict__ bt2)
{
    int node = blockIdx.x;
    int j = threadIdx.x;
    __shared__ float4 g4[32], h4[32];
    float tv = t[node];
    float d = tv - (float)j*(1.0f/127.0f) + 1e-6f;
    ((float*)g4)[j] = expf(-8064.5f*d*d);   // precise exp (large args)
    __syncthreads();
    float a = bt1[j];
    #pragma unroll 8
    for (int i4 = 0; i4 < 32; i4++) {
        float4 g = g4[i4];
        int i = 4*i4;
        a += g.x*Wt1[(i+0)*128+j] + g.y*Wt1[(i+1)*128+j]
           + g.z*Wt1[(i+2)*128+j] + g.w*Wt1[(i+3)*128+j];
    }
    ((float*)h4)[j] = fmaxf(a, 0.0f);
    __syncthreads();
    float a2 = bt2[j];
    #pragma unroll 8
    for (int i4 = 0; i4 < 32; i4++) {
        float4 h = h4[i4];
        int i = 4*i4;
        a2 += h.x*Wt2[(i+0)*128+j] + h.y*Wt2[(i+1)*128+j]
            + h.z*Wt2[(i+2)*128+j] + h.w*Wt2[(i+3)*128+j];
    }
    float hv = emb[S[node]*128+j] + a2;
    g_Hh[node*128+j]  = hv;
    g_sHh[node*128+j] = silu_f(hv);
}

// ---------------- K2: top-9 nearest neighbors on ca = X[:,:,1,:] ----------------
__global__ __launch_bounds__(128) void k_knn(const float* __restrict__ X)
{
    __shared__ float sca[NN*3];
    int b = blockIdx.x >> 3;
    int tile = blockIdx.x & 7;
    int tj = threadIdx.x;
    for (int u = tj; u < NN*3; u += 128) {
        int n = u/3, d = u - n*3;
        sca[u] = X[((b*NN + n)*CC + 1)*3 + d];
    }
    __syncthreads();
    int n = tile*128 + tj;
    float qx = sca[n*3+0], qy = sca[n*3+1], qz = sca[n*3+2];
    float bd[KK]; int bi[KK];
    #pragma unroll
    for (int i = 0; i < KK; i++){ bd[i] = 1e30f; bi[i] = 0; }
    for (int j = 0; j < NN; j++) {
        float dx = qx - sca[j*3+0];
        float dy = qy - sca[j*3+1];
        float dz = qz - sca[j*3+2];
        float d = dx*dx + dy*dy + dz*dz;
        if (j == n) d = 1e30f;
        if (d < bd[KK-1]) {                  // strict <: stable tie order
            bd[KK-1] = d; bi[KK-1] = j;
            #pragma unroll
            for (int q = KK-1; q > 0; q--) {
                if (bd[q] < bd[q-1]) {
                    float td = bd[q]; bd[q] = bd[q-1]; bd[q-1] = td;
                    int   ti = bi[q]; bi[q] = bi[q-1]; bi[q-1] = ti;
                }
            }
        }
    }
    #pragma unroll
    for (int k = 0; k < KK; k++) g_idx[(b*NN + n)*KK + k] = bi[k];
}

// ---------------- K3: per-node edge FFNs + X_out + Hn + gate + logits ----------------
__global__ __launch_bounds__(128) void k_edge(
    const float* __restrict__ X, const int* __restrict__ S, const float* __restrict__ emb,
    const float* __restrict__ We1, const float* __restrict__ be1,
    const float* __restrict__ We2, const float* __restrict__ be2,
    const float* __restrict__ Wx1, const float* __restrict__ bx1,
    const float* __restrict__ Wx2, const float* __restrict__ bx2,
    const float* __restrict__ Wh1, const float* __restrict__ bh1,
    const float* __restrict__ Wh2, const float* __restrict__ bh2,
    const float* __restrict__ Wp1, const float* __restrict__ bp1,
    const float* __restrict__ Wr1, const float* __restrict__ br1,
    const float* __restrict__ Wr2, const float* __restrict__ br2,
    float* __restrict__ out)
{
    int node = blockIdx.x;
    int tj = threadIdx.x;
    int b = node >> 10;

    __shared__ float4 shc4[32];            // silu(Hh center)
    __shared__ float  hcr[128];            // raw Hh center
    __shared__ float  xcen[42];
    __shared__ int    nbr[KK];
    __shared__ float4 xs4[KK][81];         // [silu(Hnb)(128) | silu(radial)(196)]
    __shared__ float  relb[KK][42];
    __shared__ float4 sh14[KK][32];        // silu(h1)
    __shared__ float4 sm4 [KK][32];        // silu(m)
    __shared__ float4 sbuf4[KK][32];       // silu(h2)*Wx2
    __shared__ float4 smsum4[32];          // silu(sum_k m)
    __shared__ float  wk[KK];
    __shared__ float  wx2s[128];
    __shared__ float4 tmpv4[32];
    __shared__ float4 snn4[32];            // silu(Hn)
    __shared__ float4 sx04[32];            // silu(H0*gate)

    {
        hcr[tj] = g_Hh[node*128 + tj];
        ((float*)shc4)[tj] = g_sHh[node*128 + tj];
        wx2s[tj] = Wx2[tj];
        if (tj < 42) xcen[tj] = X[node*CC*3 + tj];
        if (tj < KK) nbr[tj] = g_idx[node*KK + tj];
    }
    __syncthreads();

    // neighbor features (pre-silu'd) + rel vectors
    for (int u = tj; u < KK*128; u += 128) {
        int k = u >> 7, i = u & 127;
        ((float*)xs4[k])[i] = g_sHh[(b*NN + nbr[k])*128 + i];
    }
    for (int u = tj; u < KK*42; u += 128) {
        int k = u/42, i = u - k*42;
        relb[k][i] = xcen[i] - X[(b*NN + nbr[k])*CC*3 + i];
    }
    __syncthreads();

    // radial = rel @ rel^T / C (14x14 Gram), silu'd
    for (int u = tj; u < KK*196; u += 128) {
        int k = u/196, i = u - k*196;
        int c = i/14, e = i - c*14;
        const float* r1 = &relb[k][c*3];
        const float* r2 = &relb[k][e*3];
        float rv = (r1[0]*r2[0] + r1[1]*r2[1] + r1[2]*r2[2]) * (1.0f/14.0f);
        ((float*)xs4[k])[128 + i] = silu_f(rv);
    }
    __syncthreads();

    float acc[KK];

    // GEMM1: 452 -> 128 (center rows shared across all 9 edges)
    {
        float base = be1[tj];
        #pragma unroll 4
        for (int i4 = 0; i4 < 32; i4++) {
            float4 a = shc4[i4];
            int i = 4*i4;
            base += a.x*We1[(i+0)*128+tj] + a.y*We1[(i+1)*128+tj]
                  + a.z*We1[(i+2)*128+tj] + a.w*We1[(i+3)*128+tj];
        }
        #pragma unroll
        for (int k = 0; k < KK; k++) acc[k] = base;
        #pragma unroll 3
        for (int i4 = 0; i4 < 81; i4++) {
            int ib = 128 + 4*i4;
            float w0 = We1[(ib+0)*128+tj];
            float w1 = We1[(ib+1)*128+tj];
            float w2 = We1[(ib+2)*128+tj];
            float w3 = We1[(ib+3)*128+tj];
            #pragma unroll
            for (int k = 0; k < KK; k++) {
                float4 a = xs4[k][i4];
                acc[k] += a.x*w0 + a.y*w1 + a.z*w2 + a.w*w3;
            }
        }
        #pragma unroll
        for (int k = 0; k < KK; k++) ((float*)sh14[k])[tj] = silu_f(acc[k]);
    }
    __syncthreads();

    // GEMM2: m = silu(h1) @ We2 + be2 ; msum
    {
        float bv = be2[tj];
        #pragma unroll
        for (int k = 0; k < KK; k++) acc[k] = bv;
        #pragma unroll 2
        for (int i4 = 0; i4 < 32; i4++) {
            int i = 4*i4;
            float w0 = We2[(i+0)*128+tj];
            float w1 = We2[(i+1)*128+tj];
            float w2 = We2[(i+2)*128+tj];
            float w3 = We2[(i+3)*128+tj];
            #pragma unroll
            for (int k = 0; k < KK; k++) {
                float4 a = sh14[k][i4];
                acc[k] += a.x*w0 + a.y*w1 + a.z*w2 + a.w*w3;
            }
        }
        float msv = 0.0f;
        #pragma unroll
        for (int k = 0; k < KK; k++) { msv += acc[k]; ((float*)sm4[k])[tj] = silu_f(acc[k]); }
        ((float*)smsum4)[tj] = silu_f(msv);
    }
    __syncthreads();

    // GEMM3: h2 = silu(m) @ Wx1 + bx1 ; stage silu(h2)*Wx2
    {
        float bv = bx1[tj];
        #pragma unroll
        for (int k = 0; k < KK; k++) acc[k] = bv;
        #pragma unroll 2
        for (int i4 = 0; i4 < 32; i4++) {
            int i = 4*i4;
            float w0 = Wx1[(i+0)*128+tj];
            float w1 = Wx1[(i+1)*128+tj];
            float w2 = Wx1[(i+2)*128+tj];
            float w3 = Wx1[(i+3)*128+tj];
            #pragma unroll
            for (int k = 0; k < KK; k++) {
                float4 a = sm4[k][i4];
                acc[k] += a.x*w0 + a.y*w1 + a.z*w2 + a.w*w3;
            }
        }
        float wxv = wx2s[tj];
        #pragma unroll
        for (int k = 0; k < KK; k++) ((float*)sbuf4[k])[tj] = silu_f(acc[k]) * wxv;
    }
    __syncthreads();

    if (tj < KK) {
        float4 s4 = make_float4(0.f,0.f,0.f,0.f);
        #pragma unroll 8
        for (int i4 = 0; i4 < 32; i4++) {
            float4 v = sbuf4[tj][i4];
            s4.x += v.x; s4.y += v.y; s4.z += v.z; s4.w += v.w;
        }
        wk[tj] = bx2[0] + s4.x + s4.y + s4.z + s4.w;
    }
    __syncthreads();

    // X_out = X + mean_k(rel * w)
    if (tj < 42) {
        float s = 0.0f;
        #pragma unroll
        for (int k = 0; k < KK; k++) s += relb[k][tj]*wk[k];
        out[XOFF + node*42 + tj] = xcen[tj] + s*(1.0f/9.0f);
    }

    // Hn = Hh + FFN([Hh, msum])
    {
        float a = bh1[tj];
        #pragma unroll 4
        for (int i4 = 0; i4 < 32; i4++) {
            float4 h = shc4[i4];
            int i = 4*i4;
            a += h.x*Wh1[(i+0)*128+tj] + h.y*Wh1[(i+1)*128+tj]
               + h.z*Wh1[(i+2)*128+tj] + h.w*Wh1[(i+3)*128+tj];
        }
        #pragma unroll 4
        for (int i4 = 0; i4 < 32; i4++) {
            float4 h = smsum4[i4];
            int i = 128 + 4*i4;
            a += h.x*Wh1[(i+0)*128+tj] + h.y*Wh1[(i+1)*128+tj]
               + h.z*Wh1[(i+2)*128+tj] + h.w*Wh1[(i+3)*128+tj];
        }
        ((float*)tmpv4)[tj] = silu_f(a);
    }
    __syncthreads();
    {
        float hn = hcr[tj] + bh2[tj];
        #pragma unroll 4
        for (int i4 = 0; i4 < 32; i4++) {
            float4 h = tmpv4[i4];
            int i = 4*i4;
            hn += h.x*Wh2[(i+0)*128+tj] + h.y*Wh2[(i+1)*128+tj]
                + h.z*Wh2[(i+2)*128+tj] + h.w*Wh2[(i+3)*128+tj];
        }
        float shn = silu_f(hn);
        g_Hn[node*128 + tj]  = hn;
        g_sHn[node*128 + tj] = shn;
        ((float*)snn4)[tj] = shn;
    }
    __syncthreads();

    // gate = sigmoid(silu(Hn)@Wp1 + bp1) ; x0 = H0*gate
    {
        float a = bp1[tj];
        #pragma unroll 4
        for (int i4 = 0; i4 < 32; i4++) {
            float4 h = snn4[i4];
            int i = 4*i4;
            a += h.x*Wp1[(i+0)*128+tj] + h.y*Wp1[(i+1)*128+tj]
               + h.z*Wp1[(i+2)*128+tj] + h.w*Wp1[(i+3)*128+tj];
        }
        float gate = sigm_f(a);
        float h0 = emb[S[node]*128 + tj];
        ((float*)sx04)[tj] = silu_f(h0*gate);
    }
    __syncthreads();
    {
        float a = br1[tj];
        #pragma unroll 4
        for (int i4 = 0; i4 < 32; i4++) {
            float4 h = sx04[i4];
            int i = 4*i4;
            a += h.x*Wr1[(i+0)*128+tj] + h.y*Wr1[(i+1)*128+tj]
               + h.z*Wr1[(i+2)*128+tj] + h.w*Wr1[(i+3)*128+tj];
        }
        ((float*)tmpv4)[tj] = silu_f(a);
    }
    __syncthreads();
    if (tj < NCC) {
        float a = br2[tj];
        #pragma unroll 4
        for (int i4 = 0; i4 < 32; i4++) {
            float4 h = tmpv4[i4];
            int i = 4*i4;
            a += h.x*Wr2[(i+0)*NCC+tj] + h.y*Wr2[(i+1)*NCC+tj]
               + h.z*Wr2[(i+2)*NCC+tj] + h.w*Wr2[(i+3)*NCC+tj];
        }
        out[node*NCC + tj] = a;
    }
}

// ---------------- K4: pd (bidirectional pair FFN, center terms hoisted) ----------------
// aA[k] = Wd1_top·hc + Wd1_bot·hd[k] ; aB[k] = Wd1_top·hd[k] + Wd1_bot·hc
// hc terms are k-independent -> computed once (cA, cB).
__global__ __launch_bounds__(128) void k_pd(
    const float* __restrict__ Wd1, const float* __restrict__ bd1,
    const float* __restrict__ Wd2, const float* __restrict__ bd2,
    float* __restrict__ out)
{
    int node = blockIdx.x;
    int tj = threadIdx.x;
    int b = node >> 10;

    __shared__ float4 shc4[32];
    __shared__ int    nbr[KK];
    __shared__ float4 xsd4[KK][32];
    __shared__ float4 sAB4[KK][32];   // silu(aA)+silu(aB), pre-scaled by Wd2

    ((float*)shc4)[tj] = g_sHn[node*128 + tj];
    if (tj < KK) nbr[tj] = g_idx[node*KK + tj];
    __syncthreads();
    for (int u = tj; u < KK*128; u += 128) {
        int k = u >> 7, i = u & 127;
        ((float*)xsd4[k])[i] = g_sHn[(b*NN + nbr[k])*128 + i];
    }
    __syncthreads();

    float aA[KK], aB[KK];
    float cA = bd1[tj], cB = bd1[tj];
    #pragma unroll
    for (int k = 0; k < KK; k++){ aA[k] = 0.0f; aB[k] = 0.0f; }
    #pragma unroll 2
    for (int i4 = 0; i4 < 32; i4++) {
        int i = 4*i4;
        float w10 = Wd1[(i+0)*128+tj], w11 = Wd1[(i+1)*128+tj];
        float w12 = Wd1[(i+2)*128+tj], w13 = Wd1[(i+3)*128+tj];
        float w20 = Wd1[(128+i+0)*128+tj], w21 = Wd1[(128+i+1)*128+tj];
        float w22 = Wd1[(128+i+2)*128+tj], w23 = Wd1[(128+i+3)*128+tj];
        float4 hc = shc4[i4];
        cA += hc.x*w10 + hc.y*w11 + hc.z*w12 + hc.w*w13;   // top block · hc
        cB += hc.x*w20 + hc.y*w21 + hc.z*w22 + hc.w*w23;   // bottom block · hc
        #pragma unroll
        for (int k = 0; k < KK; k++) {
            float4 hd = xsd4[k][i4];
            aA[k] += hd.x*w20 + hd.y*w21 + hd.z*w22 + hd.w*w23;  // bottom · hd
            aB[k] += hd.x*w10 + hd.y*w11 + hd.z*w12 + hd.w*w13;  // top · hd
        }
    }
    float wd2 = Wd2[tj];
    #pragma unroll
    for (int k = 0; k < KK; k++) {
        ((float*)sAB4[k])[tj] = (silu_f(cA + aA[k]) + silu_f(cB + aB[k])) * wd2;
    }
    __syncthreads();
    if (tj < KK) {
        float4 s4 = make_float4(0.f,0.f,0.f,0.f);
        #pragma unroll 8
        for (int i4 = 0; i4 < 32; i4++) {
            float4 v = sAB4[tj][i4];
            s4.x += v.x; s4.y += v.y; s4.z += v.z; s4.w += v.w;
        }
        out[POFF + node*KK + tj] = 2.0f*bd2[0] + s4.x + s4.y + s4.z + s4.w;
    }
}

// ---------------- launcher ----------------
extern "C" void kernel_launch(void* const* d_in, const int* in_sizes, int n_in,
                              void* d_out, int out_size)
{
    const float* X   = (const float*)d_in[0];
    const int*   S   = (const int*)  d_in[1];
    const float* t   = (const float*)d_in[2];
    const float* emb = (const float*)d_in[3];
    const float* Wt1 = (const float*)d_in[4];
    const float* bt1 = (const float*)d_in[5];
    const float* Wt2 = (const float*)d_in[6];
    const float* bt2 = (const float*)d_in[7];
    const float* We1 = (const float*)d_in[8];
    const float* be1 = (const float*)d_in[9];
    const float* We2 = (const float*)d_in[10];
    const float* be2 = (const float*)d_in[11];
    const float* Wx1 = (const float*)d_in[12];
    const float* bx1 = (const float*)d_in[13];
    const float* Wx2 = (const float*)d_in[14];
    const float* bx2 = (const float*)d_in[15];
    const float* Wh1 = (const float*)d_in[16];
    const float* bh1 = (const float*)d_in[17];
    const float* Wh2 = (const float*)d_in[18];
    const float* bh2 = (const float*)d_in[19];
    const float* Wd1 = (const float*)d_in[20];
    const float* bd1 = (const float*)d_in[21];
    const float* Wd2 = (const float*)d_in[22];
    const float* bd2 = (const float*)d_in[23];
    const float* Wp1 = (const float*)d_in[24];
    const float* bp1 = (const float*)d_in[25];
    const float* Wr1 = (const float*)d_in[26];
    const float* br1 = (const float*)d_in[27];
    const float* Wr2 = (const float*)d_in[28];
    const float* br2 = (const float*)d_in[29];
    float* out = (float*)d_out;

    k_hh<<<NODES, 128>>>(t, S, emb, Wt1, bt1, Wt2, bt2);
    k_knn<<<BB*(NN/128), 128>>>(X);
    k_edge<<<NODES, 128>>>(X, S, emb,
                           We1, be1, We2, be2,
                           Wx1, bx1, Wx2, bx2,
                           Wh1, bh1, Wh2, bh2,
                           Wp1, bp1, Wr1, br1, Wr2, br2,
                           out);
    k_pd<<<NODES, 128>>>(Wd1, bd1, Wd2, bd2, out);
}

// round 9
// speedup vs baseline: 1.7399x; 1.0356x over previous
#include <cuda_runtime.h>
#include <math.h>

#define BB 32
#define NN 1024
#define CC 14
#define KK 9
#define EE 128
#define HH 128
#define NCC 25
#define NODES (BB*NN)

// output layout: logits (B,N,25) | X_out (B,N,14,3) | pd (B,N,9)
#define L_SZ (NODES*NCC)
#define X_SZ (NODES*CC*3)
#define XOFF L_SZ
#define POFF (L_SZ + X_SZ)

typedef unsigned long long u64;

// scratch (allowed: __device__ globals, no runtime alloc)
__device__ float g_Hh[NODES*EE];    // raw Hh
__device__ float g_sHh[NODES*EE];   // silu(Hh)
__device__ float g_Hn[NODES*EE];    // raw Hn
__device__ float g_sHn[NODES*EE];   // silu(Hn)
__device__ int   g_idx[NODES*KK];

// fast transcendentals: MUFU.EX2 + MUFU.RCP (~2^-21 rel err; budget is 1e-3)
__device__ __forceinline__ float silu_f(float x){ return __fdividef(x, 1.0f + __expf(-x)); }
__device__ __forceinline__ float sigm_f(float x){ return __fdividef(1.0f, 1.0f + __expf(-x)); }

// ---- packed fp32 (Blackwell FFMA2; PTX-only, ptxas never auto-fuses) ----
__device__ __forceinline__ u64 pack2(float lo, float hi){
    u64 r;
    asm("mov.b64 %0, {%1, %2};" : "=l"(r) : "r"(__float_as_uint(lo)), "r"(__float_as_uint(hi)));
    return r;
}
__device__ __forceinline__ void fma2(u64 &d, u64 a, u64 b){
    asm("fma.rn.f32x2 %0, %1, %2, %0;" : "+l"(d) : "l"(a), "l"(b));
}
__device__ __forceinline__ float hsum2(u64 v){
    unsigned lo, hi;
    asm("mov.b64 {%0, %1}, %2;" : "=r"(lo), "=r"(hi) : "l"(v));
    return __uint_as_float(lo) + __uint_as_float(hi);
}

// ---------------- K1: Hh = emb[S] + time_emb(t) ----------------
__global__ __launch_bounds__(128) void k_hh(
    const float* __restrict__ t, const int* __restrict__ S,
    const float* __restrict__ emb,
    const float* __restrict__ Wt1, const float* __restrict__ bt1,
    const float* __restrict__ Wt2, const float* __restrict__ bt2)
{
    int node = blockIdx.x;
    int j = threadIdx.x;
    __shared__ float4 g4[32], h4[32];
    float tv = t[node];
    float d = tv - (float)j*(1.0f/127.0f) + 1e-6f;
    ((float*)g4)[j] = expf(-8064.5f*d*d);   // precise exp (large args)
    __syncthreads();
    float a = bt1[j];
    #pragma unroll 8
    for (int i4 = 0; i4 < 32; i4++) {
        float4 g = g4[i4];
        int i = 4*i4;
        a += g.x*Wt1[(i+0)*128+j] + g.y*Wt1[(i+1)*128+j]
           + g.z*Wt1[(i+2)*128+j] + g.w*Wt1[(i+3)*128+j];
    }
    ((float*)h4)[j] = fmaxf(a, 0.0f);
    __syncthreads();
    float a2 = bt2[j];
    #pragma unroll 8
    for (int i4 = 0; i4 < 32; i4++) {
        float4 h = h4[i4];
        int i = 4*i4;
        a2 += h.x*Wt2[(i+0)*128+j] + h.y*Wt2[(i+1)*128+j]
            + h.z*Wt2[(i+2)*128+j] + h.w*Wt2[(i+3)*128+j];
    }
    float hv = emb[S[node]*128+j] + a2;
    g_Hh[node*128+j]  = hv;
    g_sHh[node*128+j] = silu_f(hv);
}

// ---------------- K2: top-9 nearest neighbors on ca = X[:,:,1,:] ----------------
__global__ __launch_bounds__(128) void k_knn(const float* __restrict__ X)
{
    __shared__ float sca[NN*3];
    int b = blockIdx.x >> 3;
    int tile = blockIdx.x & 7;
    int tj = threadIdx.x;
    for (int u = tj; u < NN*3; u += 128) {
        int n = u/3, d = u - n*3;
        sca[u] = X[((b*NN + n)*CC + 1)*3 + d];
    }
    __syncthreads();
    int n = tile*128 + tj;
    float qx = sca[n*3+0], qy = sca[n*3+1], qz = sca[n*3+2];
    float bd[KK]; int bi[KK];
    #pragma unroll
    for (int i = 0; i < KK; i++){ bd[i] = 1e30f; bi[i] = 0; }
    for (int j = 0; j < NN; j++) {
        float dx = qx - sca[j*3+0];
        float dy = qy - sca[j*3+1];
        float dz = qz - sca[j*3+2];
        float d = dx*dx + dy*dy + dz*dz;
        if (j == n) d = 1e30f;
        if (d < bd[KK-1]) {                  // strict <: stable tie order
            bd[KK-1] = d; bi[KK-1] = j;
            #pragma unroll
            for (int q = KK-1; q > 0; q--) {
                if (bd[q] < bd[q-1]) {
                    float td = bd[q]; bd[q] = bd[q-1]; bd[q-1] = td;
                    int   ti = bi[q]; bi[q] = bi[q-1]; bi[q-1] = ti;
                }
            }
        }
    }
    #pragma unroll
    for (int k = 0; k < KK; k++) g_idx[(b*NN + n)*KK + k] = bi[k];
}

// ---------------- K3: per-node edge FFNs + X_out + Hn + gate + logits ----------------
__global__ __launch_bounds__(128) void k_edge(
    const float* __restrict__ X, const int* __restrict__ S, const float* __restrict__ emb,
    const float* __restrict__ We1, const float* __restrict__ be1,
    const float* __restrict__ We2, const float* __restrict__ be2,
    const float* __restrict__ Wx1, const float* __restrict__ bx1,
    const float* __restrict__ Wx2, const float* __restrict__ bx2,
    const float* __restrict__ Wh1, const float* __restrict__ bh1,
    const float* __restrict__ Wh2, const float* __restrict__ bh2,
    const float* __restrict__ Wp1, const float* __restrict__ bp1,
    const float* __restrict__ Wr1, const float* __restrict__ br1,
    const float* __restrict__ Wr2, const float* __restrict__ br2,
    float* __restrict__ out)
{
    int node = blockIdx.x;
    int tj = threadIdx.x;
    int b = node >> 10;

    __shared__ float4 shc4[32];            // silu(Hh center)
    __shared__ float  hcr[128];            // raw Hh center
    __shared__ float  xcen[42];
    __shared__ int    nbr[KK];
    __shared__ float4 xs4[KK][81];         // [silu(Hnb)(128) | silu(radial)(196)]
    __shared__ float  relb[KK][42];
    __shared__ float4 sh14[KK][32];        // silu(h1)
    __shared__ float4 sm4 [KK][32];        // silu(m)
    __shared__ float4 sbuf4[KK][32];       // silu(h2)*Wx2
    __shared__ float4 smsum4[32];          // silu(sum_k m)
    __shared__ float  wk[KK];
    __shared__ float  wx2s[128];
    __shared__ float4 tmpv4[32];
    __shared__ float4 snn4[32];            // silu(Hn)
    __shared__ float4 sx04[32];            // silu(H0*gate)

    {
        hcr[tj] = g_Hh[node*128 + tj];
        ((float*)shc4)[tj] = g_sHh[node*128 + tj];
        wx2s[tj] = Wx2[tj];
        if (tj < 42) xcen[tj] = X[node*CC*3 + tj];
        if (tj < KK) nbr[tj] = g_idx[node*KK + tj];
    }
    __syncthreads();

    // neighbor features (pre-silu'd) + rel vectors
    for (int u = tj; u < KK*128; u += 128) {
        int k = u >> 7, i = u & 127;
        ((float*)xs4[k])[i] = g_sHh[(b*NN + nbr[k])*128 + i];
    }
    for (int u = tj; u < KK*42; u += 128) {
        int k = u/42, i = u - k*42;
        relb[k][i] = xcen[i] - X[(b*NN + nbr[k])*CC*3 + i];
    }
    __syncthreads();

    // radial = rel @ rel^T / C (14x14 Gram), silu'd
    for (int u = tj; u < KK*196; u += 128) {
        int k = u/196, i = u - k*196;
        int c = i/14, e = i - c*14;
        const float* r1 = &relb[k][c*3];
        const float* r2 = &relb[k][e*3];
        float rv = (r1[0]*r2[0] + r1[1]*r2[1] + r1[2]*r2[2]) * (1.0f/14.0f);
        ((float*)xs4[k])[128 + i] = silu_f(rv);
    }
    __syncthreads();

    u64 acc2[KK];

    // GEMM1: 452 -> 128 (center rows shared across all 9 edges; packed f32x2 main loop)
    {
        float base = be1[tj];
        #pragma unroll 4
        for (int i4 = 0; i4 < 32; i4++) {
            float4 a = shc4[i4];
            int i = 4*i4;
            base += a.x*We1[(i+0)*128+tj] + a.y*We1[(i+1)*128+tj]
                  + a.z*We1[(i+2)*128+tj] + a.w*We1[(i+3)*128+tj];
        }
        #pragma unroll
        for (int k = 0; k < KK; k++) acc2[k] = pack2(base, 0.0f);
        #pragma unroll 3
        for (int i4 = 0; i4 < 81; i4++) {
            int ib = 128 + 4*i4;
            u64 wA = pack2(We1[(ib+0)*128+tj], We1[(ib+1)*128+tj]);
            u64 wB = pack2(We1[(ib+2)*128+tj], We1[(ib+3)*128+tj]);
            #pragma unroll
            for (int k = 0; k < KK; k++) {
                ulonglong2 a = *reinterpret_cast<const ulonglong2*>(&xs4[k][i4]);
                fma2(acc2[k], a.x, wA);
                fma2(acc2[k], a.y, wB);
            }
        }
        #pragma unroll
        for (int k = 0; k < KK; k++) ((float*)sh14[k])[tj] = silu_f(hsum2(acc2[k]));
    }
    __syncthreads();

    // GEMM2: m = silu(h1) @ We2 + be2 ; msum  (packed f32x2)
    {
        float bv = be2[tj];
        #pragma unroll
        for (int k = 0; k < KK; k++) acc2[k] = pack2(bv, 0.0f);
        #pragma unroll 2
        for (int i4 = 0; i4 < 32; i4++) {
            int i = 4*i4;
            u64 wA = pack2(We2[(i+0)*128+tj], We2[(i+1)*128+tj]);
            u64 wB = pack2(We2[(i+2)*128+tj], We2[(i+3)*128+tj]);
            #pragma unroll
            for (int k = 0; k < KK; k++) {
                ulonglong2 a = *reinterpret_cast<const ulonglong2*>(&sh14[k][i4]);
                fma2(acc2[k], a.x, wA);
                fma2(acc2[k], a.y, wB);
            }
        }
        float msv = 0.0f;
        #pragma unroll
        for (int k = 0; k < KK; k++) {
            float mv = hsum2(acc2[k]);
            msv += mv;
            ((float*)sm4[k])[tj] = silu_f(mv);
        }
        ((float*)smsum4)[tj] = silu_f(msv);
    }
    __syncthreads();

    // GEMM3: h2 = silu(m) @ Wx1 + bx1 ; stage silu(h2)*Wx2  (packed f32x2)
    {
        float bv = bx1[tj];
        #pragma unroll
        for (int k = 0; k < KK; k++) acc2[k] = pack2(bv, 0.0f);
        #pragma unroll 2
        for (int i4 = 0; i4 < 32; i4++) {
            int i = 4*i4;
            u64 wA = pack2(Wx1[(i+0)*128+tj], Wx1[(i+1)*128+tj]);
            u64 wB = pack2(Wx1[(i+2)*128+tj], Wx1[(i+3)*128+tj]);
            #pragma unroll
            for (int k = 0; k < KK; k++) {
                ulonglong2 a = *reinterpret_cast<const ulonglong2*>(&sm4[k][i4]);
                fma2(acc2[k], a.x, wA);
                fma2(acc2[k], a.y, wB);
            }
        }
        float wxv = wx2s[tj];
        #pragma unroll
        for (int k = 0; k < KK; k++) ((float*)sbuf4[k])[tj] = silu_f(hsum2(acc2[k])) * wxv;
    }
    __syncthreads();

    if (tj < KK) {
        float4 s4 = make_float4(0.f,0.f,0.f,0.f);
        #pragma unroll 8
        for (int i4 = 0; i4 < 32; i4++) {
            float4 v = sbuf4[tj][i4];
            s4.x += v.x; s4.y += v.y; s4.z += v.z; s4.w += v.w;
        }
        wk[tj] = bx2[0] + s4.x + s4.y + s4.z + s4.w;
    }
    __syncthreads();

    // X_out = X + mean_k(rel * w)
    if (tj < 42) {
        float s = 0.0f;
        #pragma unroll
        for (int k = 0; k < KK; k++) s += relb[k][tj]*wk[k];
        out[XOFF + node*42 + tj] = xcen[tj] + s*(1.0f/9.0f);
    }

    // Hn = Hh + FFN([Hh, msum])
    {
        float a = bh1[tj];
        #pragma unroll 4
        for (int i4 = 0; i4 < 32; i4++) {
            float4 h = shc4[i4];
            int i = 4*i4;
            a += h.x*Wh1[(i+0)*128+tj] + h.y*Wh1[(i+1)*128+tj]
               + h.z*Wh1[(i+2)*128+tj] + h.w*Wh1[(i+3)*128+tj];
        }
        #pragma unroll 4
        for (int i4 = 0; i4 < 32; i4++) {
            float4 h = smsum4[i4];
            int i = 128 + 4*i4;
            a += h.x*Wh1[(i+0)*128+tj] + h.y*Wh1[(i+1)*128+tj]
               + h.z*Wh1[(i+2)*128+tj] + h.w*Wh1[(i+3)*128+tj];
        }
        ((float*)tmpv4)[tj] = silu_f(a);
    }
    __syncthreads();
    {
        float hn = hcr[tj] + bh2[tj];
        #pragma unroll 4
        for (int i4 = 0; i4 < 32; i4++) {
            float4 h = tmpv4[i4];
            int i = 4*i4;
            hn += h.x*Wh2[(i+0)*128+tj] + h.y*Wh2[(i+1)*128+tj]
                + h.z*Wh2[(i+2)*128+tj] + h.w*Wh2[(i+3)*128+tj];
        }
        float shn = silu_f(hn);
        g_Hn[node*128 + tj]  = hn;
        g_sHn[node*128 + tj] = shn;
        ((float*)snn4)[tj] = shn;
    }
    __syncthreads();

    // gate = sigmoid(silu(Hn)@Wp1 + bp1) ; x0 = H0*gate
    {
        float a = bp1[tj];
        #pragma unroll 4
        for (int i4 = 0; i4 < 32; i4++) {
            float4 h = snn4[i4];
            int i = 4*i4;
            a += h.x*Wp1[(i+0)*128+tj] + h.y*Wp1[(i+1)*128+tj]
               + h.z*Wp1[(i+2)*128+tj] + h.w*Wp1[(i+3)*128+tj];
        }
        float gate = sigm_f(a);
        float h0 = emb[S[node]*128 + tj];
        ((float*)sx04)[tj] = silu_f(h0*gate);
    }
    __syncthreads();
    {
        float a = br1[tj];
        #pragma unroll 4
        for (int i4 = 0; i4 < 32; i4++) {
            float4 h = sx04[i4];
            int i = 4*i4;
            a += h.x*Wr1[(i+0)*128+tj] + h.y*Wr1[(i+1)*128+tj]
               + h.z*Wr1[(i+2)*128+tj] + h.w*Wr1[(i+3)*128+tj];
        }
        ((float*)tmpv4)[tj] = silu_f(a);
    }
    __syncthreads();
    if (tj < NCC) {
        float a = br2[tj];
        #pragma unroll 4
        for (int i4 = 0; i4 < 32; i4++) {
            float4 h = tmpv4[i4];
            int i = 4*i4;
            a += h.x*Wr2[(i+0)*NCC+tj] + h.y*Wr2[(i+1)*NCC+tj]
               + h.z*Wr2[(i+2)*NCC+tj] + h.w*Wr2[(i+3)*NCC+tj];
        }
        out[node*NCC + tj] = a;
    }
}

// ---------------- K4: pd (bidirectional pair FFN, hoisted center, packed f32x2) ----------------
__global__ __launch_bounds__(128) void k_pd(
    const float* __restrict__ Wd1, const float* __restrict__ bd1,
    const float* __restrict__ Wd2, const float* __restrict__ bd2,
    float* __restrict__ out)
{
    int node = blockIdx.x;
    int tj = threadIdx.x;
    int b = node >> 10;

    __shared__ float4 shc4[32];
    __shared__ int    nbr[KK];
    __shared__ float4 xsd4[KK][32];
    __shared__ float4 sAB4[KK][32];   // silu(aA)+silu(aB), pre-scaled by Wd2

    ((float*)shc4)[tj] = g_sHn[node*128 + tj];
    if (tj < KK) nbr[tj] = g_idx[node*KK + tj];
    __syncthreads();
    for (int u = tj; u < KK*128; u += 128) {
        int k = u >> 7, i = u & 127;
        ((float*)xsd4[k])[i] = g_sHn[(b*NN + nbr[k])*128 + i];
    }
    __syncthreads();

    u64 a2A[KK], a2B[KK];
    u64 c2A = pack2(bd1[tj], 0.0f);
    u64 c2B = c2A;
    #pragma unroll
    for (int k = 0; k < KK; k++){ a2A[k] = 0ULL; a2B[k] = 0ULL; }
    #pragma unroll 2
    for (int i4 = 0; i4 < 32; i4++) {
        int i = 4*i4;
        u64 w1A = pack2(Wd1[(i+0)*128+tj],     Wd1[(i+1)*128+tj]);
        u64 w1B = pack2(Wd1[(i+2)*128+tj],     Wd1[(i+3)*128+tj]);
        u64 w2A = pack2(Wd1[(128+i+0)*128+tj], Wd1[(128+i+1)*128+tj]);
        u64 w2B = pack2(Wd1[(128+i+2)*128+tj], Wd1[(128+i+3)*128+tj]);
        ulonglong2 hc = *reinterpret_cast<const ulonglong2*>(&shc4[i4]);
        fma2(c2A, hc.x, w1A); fma2(c2A, hc.y, w1B);   // top block · hc
        fma2(c2B, hc.x, w2A); fma2(c2B, hc.y, w2B);   // bottom block · hc
        #pragma unroll
        for (int k = 0; k < KK; k++) {
            ulonglong2 hd = *reinterpret_cast<const ulonglong2*>(&xsd4[k][i4]);
            fma2(a2A[k], hd.x, w2A); fma2(a2A[k], hd.y, w2B);  // bottom · hd
            fma2(a2B[k], hd.x, w1A); fma2(a2B[k], hd.y, w1B);  // top · hd
        }
    }
    float cA = hsum2(c2A), cB = hsum2(c2B);
    float wd2 = Wd2[tj];
    #pragma unroll
    for (int k = 0; k < KK; k++) {
        ((float*)sAB4[k])[tj] = (silu_f(cA + hsum2(a2A[k])) + silu_f(cB + hsum2(a2B[k]))) * wd2;
    }
    __syncthreads();
    if (tj < KK) {
        float4 s4 = make_float4(0.f,0.f,0.f,0.f);
        #pragma unroll 8
        for (int i4 = 0; i4 < 32; i4++) {
            float4 v = sAB4[tj][i4];
            s4.x += v.x; s4.y += v.y; s4.z += v.z; s4.w += v.w;
        }
        out[POFF + node*KK + tj] = 2.0f*bd2[0] + s4.x + s4.y + s4.z + s4.w;
    }
}

// ---------------- launcher ----------------
extern "C" void kernel_launch(void* const* d_in, const int* in_sizes, int n_in,
                              void* d_out, int out_size)
{
    const float* X   = (const float*)d_in[0];
    const int*   S   = (const int*)  d_in[1];
    const float* t   = (const float*)d_in[2];
    const float* emb = (const float*)d_in[3];
    const float* Wt1 = (const float*)d_in[4];
    const float* bt1 = (const float*)d_in[5];
    const float* Wt2 = (const float*)d_in[6];
    const float* bt2 = (const float*)d_in[7];
    const float* We1 = (const float*)d_in[8];
    const float* be1 = (const float*)d_in[9];
    const float* We2 = (const float*)d_in[10];
    const float* be2 = (const float*)d_in[11];
    const float* Wx1 = (const float*)d_in[12];
    const float* bx1 = (const float*)d_in[13];
    const float* Wx2 = (const float*)d_in[14];
    const float* bx2 = (const float*)d_in[15];
    const float* Wh1 = (const float*)d_in[16];
    const float* bh1 = (const float*)d_in[17];
    const float* Wh2 = (const float*)d_in[18];
    const float* bh2 = (const float*)d_in[19];
    const float* Wd1 = (const float*)d_in[20];
    const float* bd1 = (const float*)d_in[21];
    const float* Wd2 = (const float*)d_in[22];
    const float* bd2 = (const float*)d_in[23];
    const float* Wp1 = (const float*)d_in[24];
    const float* bp1 = (const float*)d_in[25];
    const float* Wr1 = (const float*)d_in[26];
    const float* br1 = (const float*)d_in[27];
    const float* Wr2 = (const float*)d_in[28];
    const float* br2 = (const float*)d_in[29];
    float* out = (float*)d_out;

    k_hh<<<NODES, 128>>>(t, S, emb, Wt1, bt1, Wt2, bt2);
    k_knn<<<BB*(NN/128), 128>>>(X);
    k_edge<<<NODES, 128>>>(X, S, emb,
                           We1, be1, We2, be2,
                           Wx1, bx1, Wx2, bx2,
                           Wh1, bh1, Wh2, bh2,
                           Wp1, bp1, Wr1, br1, Wr2, br2,
                           out);
    k_pd<<<NODES, 128>>>(Wd1, bd1, Wd2, bd2, out);
}

// round 10
// speedup vs baseline: 1.9125x; 1.0992x over previous
#include <cuda_runtime.h>
#include <math.h>

#define BB 32
#define NN 1024
#define CC 14
#define KK 9
#define EE 128
#define HH 128
#define NCC 25
#define NODES (BB*NN)

// output layout: logits (B,N,25) | X_out (B,N,14,3) | pd (B,N,9)
#define L_SZ (NODES*NCC)
#define X_SZ (NODES*CC*3)
#define XOFF L_SZ
#define POFF (L_SZ + X_SZ)

typedef unsigned long long u64;

// scratch (allowed: __device__ globals, no runtime alloc)
__device__ float g_Hh[NODES*EE];    // raw Hh
__device__ float g_sHh[NODES*EE];   // silu(Hh)
__device__ float g_Hn[NODES*EE];    // raw Hn
__device__ float g_sHn[NODES*EE];   // silu(Hn)
__device__ int   g_idx[NODES*KK];

// fast transcendentals: MUFU.EX2 + MUFU.RCP (~2^-21 rel err; budget is 1e-3)
__device__ __forceinline__ float silu_f(float x){ return __fdividef(x, 1.0f + __expf(-x)); }
__device__ __forceinline__ float sigm_f(float x){ return __fdividef(1.0f, 1.0f + __expf(-x)); }

// ---- packed fp32 (Blackwell FFMA2; PTX-only) ----
__device__ __forceinline__ u64 pack2(float lo, float hi){
    u64 r;
    asm("mov.b64 %0, {%1, %2};" : "=l"(r) : "r"(__float_as_uint(lo)), "r"(__float_as_uint(hi)));
    return r;
}
__device__ __forceinline__ void fma2(u64 &d, u64 a, u64 b){
    asm("fma.rn.f32x2 %0, %1, %2, %0;" : "+l"(d) : "l"(a), "l"(b));
}
__device__ __forceinline__ float hsum2(u64 v){
    unsigned lo, hi;
    asm("mov.b64 {%0, %1}, %2;" : "=r"(lo), "=r"(hi) : "l"(v));
    return __uint_as_float(lo) + __uint_as_float(hi);
}

// ---------------- K1: Hh = emb[S] + time_emb(t), 2 nodes/block ----------------
__global__ __launch_bounds__(128) void k_hh(
    const float* __restrict__ t, const int* __restrict__ S,
    const float* __restrict__ emb,
    const float* __restrict__ Wt1, const float* __restrict__ bt1,
    const float* __restrict__ Wt2, const float* __restrict__ bt2)
{
    int node0 = 2*blockIdx.x;
    int j = threadIdx.x;
    __shared__ float4 g4[2][32], h4[2][32];
    #pragma unroll
    for (int n = 0; n < 2; n++) {
        float tv = t[node0+n];
        float d = tv - (float)j*(1.0f/127.0f) + 1e-6f;
        ((float*)g4[n])[j] = expf(-8064.5f*d*d);   // precise exp (large args)
    }
    __syncthreads();
    float a[2] = {bt1[j], bt1[j]};
    #pragma unroll 4
    for (int i4 = 0; i4 < 32; i4++) {
        int i = 4*i4;
        float w0 = Wt1[(i+0)*128+j], w1 = Wt1[(i+1)*128+j];
        float w2 = Wt1[(i+2)*128+j], w3 = Wt1[(i+3)*128+j];
        #pragma unroll
        for (int n = 0; n < 2; n++) {
            float4 g = g4[n][i4];
            a[n] += g.x*w0 + g.y*w1 + g.z*w2 + g.w*w3;
        }
    }
    #pragma unroll
    for (int n = 0; n < 2; n++) ((float*)h4[n])[j] = fmaxf(a[n], 0.0f);
    __syncthreads();
    float a2[2] = {bt2[j], bt2[j]};
    #pragma unroll 4
    for (int i4 = 0; i4 < 32; i4++) {
        int i = 4*i4;
        float w0 = Wt2[(i+0)*128+j], w1 = Wt2[(i+1)*128+j];
        float w2 = Wt2[(i+2)*128+j], w3 = Wt2[(i+3)*128+j];
        #pragma unroll
        for (int n = 0; n < 2; n++) {
            float4 h = h4[n][i4];
            a2[n] += h.x*w0 + h.y*w1 + h.z*w2 + h.w*w3;
        }
    }
    #pragma unroll
    for (int n = 0; n < 2; n++) {
        float hv = emb[S[node0+n]*128+j] + a2[n];
        g_Hh[(node0+n)*128+j]  = hv;
        g_sHh[(node0+n)*128+j] = silu_f(hv);
    }
}

// ---------------- K2: top-9 nearest neighbors on ca = X[:,:,1,:] ----------------
__global__ __launch_bounds__(128) void k_knn(const float* __restrict__ X)
{
    __shared__ float sca[NN*3];
    int b = blockIdx.x >> 3;
    int tile = blockIdx.x & 7;
    int tj = threadIdx.x;
    for (int u = tj; u < NN*3; u += 128) {
        int n = u/3, d = u - n*3;
        sca[u] = X[((b*NN + n)*CC + 1)*3 + d];
    }
    __syncthreads();
    int n = tile*128 + tj;
    float qx = sca[n*3+0], qy = sca[n*3+1], qz = sca[n*3+2];
    float bd[KK]; int bi[KK];
    #pragma unroll
    for (int i = 0; i < KK; i++){ bd[i] = 1e30f; bi[i] = 0; }
    for (int j = 0; j < NN; j++) {
        float dx = qx - sca[j*3+0];
        float dy = qy - sca[j*3+1];
        float dz = qz - sca[j*3+2];
        float d = dx*dx + dy*dy + dz*dz;
        if (j == n) d = 1e30f;
        if (d < bd[KK-1]) {                  // strict <: stable tie order
            bd[KK-1] = d; bi[KK-1] = j;
            #pragma unroll
            for (int q = KK-1; q > 0; q--) {
                if (bd[q] < bd[q-1]) {
                    float td = bd[q]; bd[q] = bd[q-1]; bd[q-1] = td;
                    int   ti = bi[q]; bi[q] = bi[q-1]; bi[q-1] = ti;
                }
            }
        }
    }
    #pragma unroll
    for (int k = 0; k < KK; k++) g_idx[(b*NN + n)*KK + k] = bi[k];
}

// ---------------- K3: edge FFNs + X_out + Hn + gate + logits, 2 nodes/block ----------------
// smem aliasing: sm4 and sbuf4 live inside xs4 (xs dead after GEMM1).
__global__ __launch_bounds__(128) void k_edge(
    const float* __restrict__ X, const int* __restrict__ S, const float* __restrict__ emb,
    const float* __restrict__ We1, const float* __restrict__ be1,
    const float* __restrict__ We2, const float* __restrict__ be2,
    const float* __restrict__ Wx1, const float* __restrict__ bx1,
    const float* __restrict__ Wx2, const float* __restrict__ bx2,
    const float* __restrict__ Wh1, const float* __restrict__ bh1,
    const float* __restrict__ Wh2, const float* __restrict__ bh2,
    const float* __restrict__ Wp1, const float* __restrict__ bp1,
    const float* __restrict__ Wr1, const float* __restrict__ br1,
    const float* __restrict__ Wr2, const float* __restrict__ br2,
    float* __restrict__ out)
{
    int node0 = 2*blockIdx.x;
    int tj = threadIdx.x;
    int b = node0 >> 10;

    __shared__ float4 xs4[2][729];     // per node: [silu(Hnb)(128)|silu(radial)(196)] = 324 floats
    __shared__ float4 sh14[2][288];    // silu(h1): 9x128 floats
    __shared__ float  relb[2][KK][42];
    __shared__ float4 shc4[2][32];
    __shared__ float  hcr[2][128];
    __shared__ float  xcen[2][42];
    __shared__ int    nbr[2][KK];
    __shared__ float4 smsum4[2][32];
    __shared__ float  wk[2][KK];
    __shared__ float  wx2s[128];
    __shared__ float4 tmpv4[2][32];
    __shared__ float4 snn4[2][32];
    __shared__ float4 sx04[2][32];

    // aliases into xs4 (valid only after GEMM1)
    #define SM4(n,k,i4)    xs4[n][(k)*32+(i4)]
    #define SM4F(n,k)      ((float*)&xs4[n][(k)*32])
    #define SBUF4(n,k,i4)  xs4[n][288+(k)*32+(i4)]
    #define SBUF4F(n,k)    ((float*)&xs4[n][288+(k)*32])

    {
        #pragma unroll
        for (int n = 0; n < 2; n++) {
            hcr[n][tj] = g_Hh[(node0+n)*128 + tj];
            ((float*)shc4[n])[tj] = g_sHh[(node0+n)*128 + tj];
        }
        wx2s[tj] = Wx2[tj];
        if (tj < 84) { int n = tj/42, i = tj%42; xcen[n][i] = X[(node0+n)*CC*3 + i]; }
        if (tj < 2*KK) { int n = tj/KK, k = tj%KK; nbr[n][k] = g_idx[(node0+n)*KK + k]; }
    }
    __syncthreads();

    // neighbor features (pre-silu'd) + rel vectors
    for (int u = tj; u < 2*KK*128; u += 128) {
        int nk = u >> 7, i = u & 127;
        int n = nk/KK, k = nk%KK;
        ((float*)xs4[n])[k*0 + 0] = 0.0f;  // dummy to keep compiler from reordering? (no-op removed below)
        ((float*)&xs4[n][k* (324/4)])[0] = ((float*)&xs4[n][k*(324/4)])[0]; // placeholder
        (void)i;
        break;
    }
    // (clean implementation below)
    for (int u = tj; u < 2*KK*128; u += 128) {
        int nk = u >> 7, i = u & 127;
        int n = nk/KK, k = nk%KK;
        ((float*)xs4[n])[k*324 + i] = g_sHh[(b*NN + nbr[n][k])*128 + i];
    }
    for (int u = tj; u < 2*KK*42; u += 128) {
        int idx = u/42, i = u - idx*42;
        int n = idx/KK, k = idx%KK;
        relb[n][k][i] = xcen[n][i] - X[(b*NN + nbr[n][k])*CC*3 + i];
    }
    __syncthreads();

    // radial = rel @ rel^T / C (14x14 Gram), silu'd
    for (int u = tj; u < 2*KK*196; u += 128) {
        int idx = u/196, i = u - idx*196;
        int n = idx/KK, k = idx%KK;
        int c = i/14, e = i - c*14;
        const float* r1 = &relb[n][k][c*3];
        const float* r2 = &relb[n][k][e*3];
        float rv = (r1[0]*r2[0] + r1[1]*r2[1] + r1[2]*r2[2]) * (1.0f/14.0f);
        ((float*)xs4[n])[k*324 + 128 + i] = silu_f(rv);
    }
    __syncthreads();

    u64 acc2[2][KK];

    // GEMM1: 452 -> 128 (center rows shared across 9 edges; weights shared across 2 nodes)
    {
        float base[2] = {be1[tj], be1[tj]};
        #pragma unroll 4
        for (int i4 = 0; i4 < 32; i4++) {
            int i = 4*i4;
            float w0 = We1[(i+0)*128+tj], w1 = We1[(i+1)*128+tj];
            float w2 = We1[(i+2)*128+tj], w3 = We1[(i+3)*128+tj];
            #pragma unroll
            for (int n = 0; n < 2; n++) {
                float4 a = shc4[n][i4];
                base[n] += a.x*w0 + a.y*w1 + a.z*w2 + a.w*w3;
            }
        }
        #pragma unroll
        for (int n = 0; n < 2; n++)
            #pragma unroll
            for (int k = 0; k < KK; k++) acc2[n][k] = pack2(base[n], 0.0f);
        #pragma unroll 3
        for (int i4 = 0; i4 < 81; i4++) {
            int ib = 128 + 4*i4;
            u64 wA = pack2(We1[(ib+0)*128+tj], We1[(ib+1)*128+tj]);
            u64 wB = pack2(We1[(ib+2)*128+tj], We1[(ib+3)*128+tj]);
            #pragma unroll
            for (int n = 0; n < 2; n++) {
                const ulonglong2* xr = reinterpret_cast<const ulonglong2*>(xs4[n]);
                #pragma unroll
                for (int k = 0; k < KK; k++) {
                    // xs float idx = k*324 + 4*i4 -> ulonglong2 idx = (k*324+4*i4)/4 = k*81+i4
                    ulonglong2 a = xr[k*81 + i4];
                    fma2(acc2[n][k], a.x, wA);
                    fma2(acc2[n][k], a.y, wB);
                }
            }
        }
        #pragma unroll
        for (int n = 0; n < 2; n++)
            #pragma unroll
            for (int k = 0; k < KK; k++)
                ((float*)&sh14[n][k*32])[tj] = silu_f(hsum2(acc2[n][k]));
    }
    __syncthreads();

    // GEMM2: m = silu(h1) @ We2 + be2 ; msum  (xs now dead -> sm4 aliases it)
    {
        float bv = be2[tj];
        #pragma unroll
        for (int n = 0; n < 2; n++)
            #pragma unroll
            for (int k = 0; k < KK; k++) acc2[n][k] = pack2(bv, 0.0f);
        #pragma unroll 2
        for (int i4 = 0; i4 < 32; i4++) {
            int i = 4*i4;
            u64 wA = pack2(We2[(i+0)*128+tj], We2[(i+1)*128+tj]);
            u64 wB = pack2(We2[(i+2)*128+tj], We2[(i+3)*128+tj]);
            #pragma unroll
            for (int n = 0; n < 2; n++) {
                #pragma unroll
                for (int k = 0; k < KK; k++) {
                    ulonglong2 a = *reinterpret_cast<const ulonglong2*>(&sh14[n][k*32 + i4]);
                    fma2(acc2[n][k], a.x, wA);
                    fma2(acc2[n][k], a.y, wB);
                }
            }
        }
        #pragma unroll
        for (int n = 0; n < 2; n++) {
            float msv = 0.0f;
            #pragma unroll
            for (int k = 0; k < KK; k++) {
                float mv = hsum2(acc2[n][k]);
                msv += mv;
                SM4F(n,k)[tj] = silu_f(mv);
            }
            ((float*)smsum4[n])[tj] = silu_f(msv);
        }
    }
    __syncthreads();

    // GEMM3: h2 = silu(m) @ Wx1 + bx1 ; stage silu(h2)*Wx2 (sbuf aliases xs upper half)
    {
        float bv = bx1[tj];
        #pragma unroll
        for (int n = 0; n < 2; n++)
            #pragma unroll
            for (int k = 0; k < KK; k++) acc2[n][k] = pack2(bv, 0.0f);
        #pragma unroll 2
        for (int i4 = 0; i4 < 32; i4++) {
            int i = 4*i4;
            u64 wA = pack2(Wx1[(i+0)*128+tj], Wx1[(i+1)*128+tj]);
            u64 wB = pack2(Wx1[(i+2)*128+tj], Wx1[(i+3)*128+tj]);
            #pragma unroll
            for (int n = 0; n < 2; n++) {
                #pragma unroll
                for (int k = 0; k < KK; k++) {
                    ulonglong2 a = *reinterpret_cast<const ulonglong2*>(&SM4(n,k,i4));
                    fma2(acc2[n][k], a.x, wA);
                    fma2(acc2[n][k], a.y, wB);
                }
            }
        }
        float wxv = wx2s[tj];
        #pragma unroll
        for (int n = 0; n < 2; n++)
            #pragma unroll
            for (int k = 0; k < KK; k++)
                SBUF4F(n,k)[tj] = silu_f(hsum2(acc2[n][k])) * wxv;
    }
    __syncthreads();

    if (tj < 2*KK) {
        int n = tj/KK, k = tj%KK;
        float4 s4 = make_float4(0.f,0.f,0.f,0.f);
        #pragma unroll 8
        for (int i4 = 0; i4 < 32; i4++) {
            float4 v = SBUF4(n,k,i4);
            s4.x += v.x; s4.y += v.y; s4.z += v.z; s4.w += v.w;
        }
        wk[n][k] = bx2[0] + s4.x + s4.y + s4.z + s4.w;
    }
    __syncthreads();

    // X_out = X + mean_k(rel * w)
    if (tj < 84) {
        int n = tj/42, i = tj%42;
        float s = 0.0f;
        #pragma unroll
        for (int k = 0; k < KK; k++) s += relb[n][k][i]*wk[n][k];
        out[XOFF + (node0+n)*42 + i] = xcen[n][i] + s*(1.0f/9.0f);
    }

    // Hn = Hh + FFN([Hh, msum])
    {
        float a[2] = {bh1[tj], bh1[tj]};
        #pragma unroll 4
        for (int i4 = 0; i4 < 32; i4++) {
            int i = 4*i4;
            float w0 = Wh1[(i+0)*128+tj], w1 = Wh1[(i+1)*128+tj];
            float w2 = Wh1[(i+2)*128+tj], w3 = Wh1[(i+3)*128+tj];
            #pragma unroll
            for (int n = 0; n < 2; n++) {
                float4 h = shc4[n][i4];
                a[n] += h.x*w0 + h.y*w1 + h.z*w2 + h.w*w3;
            }
        }
        #pragma unroll 4
        for (int i4 = 0; i4 < 32; i4++) {
            int i = 128 + 4*i4;
            float w0 = Wh1[(i+0)*128+tj], w1 = Wh1[(i+1)*128+tj];
            float w2 = Wh1[(i+2)*128+tj], w3 = Wh1[(i+3)*128+tj];
            #pragma unroll
            for (int n = 0; n < 2; n++) {
                float4 h = smsum4[n][i4];
                a[n] += h.x*w0 + h.y*w1 + h.z*w2 + h.w*w3;
            }
        }
        #pragma unroll
        for (int n = 0; n < 2; n++) ((float*)tmpv4[n])[tj] = silu_f(a[n]);
    }
    __syncthreads();
    {
        float hn[2];
        #pragma unroll
        for (int n = 0; n < 2; n++) hn[n] = hcr[n][tj] + bh2[tj];
        #pragma unroll 4
        for (int i4 = 0; i4 < 32; i4++) {
            int i = 4*i4;
            float w0 = Wh2[(i+0)*128+tj], w1 = Wh2[(i+1)*128+tj];
            float w2 = Wh2[(i+2)*128+tj], w3 = Wh2[(i+3)*128+tj];
            #pragma unroll
            for (int n = 0; n < 2; n++) {
                float4 h = tmpv4[n][i4];
                hn[n] += h.x*w0 + h.y*w1 + h.z*w2 + h.w*w3;
            }
        }
        #pragma unroll
        for (int n = 0; n < 2; n++) {
            float shn = silu_f(hn[n]);
            g_Hn[(node0+n)*128 + tj]  = hn[n];
            g_sHn[(node0+n)*128 + tj] = shn;
            ((float*)snn4[n])[tj] = shn;
        }
    }
    __syncthreads();

    // gate = sigmoid(silu(Hn)@Wp1 + bp1) ; x0 = H0*gate
    {
        float a[2] = {bp1[tj], bp1[tj]};
        #pragma unroll 4
        for (int i4 = 0; i4 < 32; i4++) {
            int i = 4*i4;
            float w0 = Wp1[(i+0)*128+tj], w1 = Wp1[(i+1)*128+tj];
            float w2 = Wp1[(i+2)*128+tj], w3 = Wp1[(i+3)*128+tj];
            #pragma unroll
            for (int n = 0; n < 2; n++) {
                float4 h = snn4[n][i4];
                a[n] += h.x*w0 + h.y*w1 + h.z*w2 + h.w*w3;
            }
        }
        #pragma unroll
        for (int n = 0; n < 2; n++) {
            float gate = sigm_f(a[n]);
            float h0 = emb[S[node0+n]*128 + tj];
            ((float*)sx04[n])[tj] = silu_f(h0*gate);
        }
    }
    __syncthreads();
    {
        float a[2] = {br1[tj], br1[tj]};
        #pragma unroll 4
        for (int i4 = 0; i4 < 32; i4++) {
            int i = 4*i4;
            float w0 = Wr1[(i+0)*128+tj], w1 = Wr1[(i+1)*128+tj];
            float w2 = Wr1[(i+2)*128+tj], w3 = Wr1[(i+3)*128+tj];
            #pragma unroll
            for (int n = 0; n < 2; n++) {
                float4 h = sx04[n][i4];
                a[n] += h.x*w0 + h.y*w1 + h.z*w2 + h.w*w3;
            }
        }
        #pragma unroll
        for (int n = 0; n < 2; n++) ((float*)tmpv4[n])[tj] = silu_f(a[n]);
    }
    __syncthreads();
    if (tj < NCC) {
        float a[2] = {br2[tj], br2[tj]};
        #pragma unroll 4
        for (int i4 = 0; i4 < 32; i4++) {
            int i = 4*i4;
            float w0 = Wr2[(i+0)*NCC+tj], w1 = Wr2[(i+1)*NCC+tj];
            float w2 = Wr2[(i+2)*NCC+tj], w3 = Wr2[(i+3)*NCC+tj];
            #pragma unroll
            for (int n = 0; n < 2; n++) {
                float4 h = tmpv4[n][i4];
                a[n] += h.x*w0 + h.y*w1 + h.z*w2 + h.w*w3;
            }
        }
        #pragma unroll
        for (int n = 0; n < 2; n++) out[(node0+n)*NCC + tj] = a[n];
    }
    #undef SM4
    #undef SM4F
    #undef SBUF4
    #undef SBUF4F
}

// ---------------- K4: pd (bidirectional pair FFN, hoisted center, 2 nodes/block) ----------------
__global__ __launch_bounds__(128) void k_pd(
    const float* __restrict__ Wd1, const float* __restrict__ bd1,
    const float* __restrict__ Wd2, const float* __restrict__ bd2,
    float* __restrict__ out)
{
    int node0 = 2*blockIdx.x;
    int tj = threadIdx.x;
    int b = node0 >> 10;

    __shared__ float4 shc4[2][32];
    __shared__ int    nbr[2][KK];
    __shared__ float4 xsd4[2][KK][32];
    __shared__ float4 sAB4[2][KK][32];   // silu(aA)+silu(aB), pre-scaled by Wd2

    #pragma unroll
    for (int n = 0; n < 2; n++) ((float*)shc4[n])[tj] = g_sHn[(node0+n)*128 + tj];
    if (tj < 2*KK) { int n = tj/KK, k = tj%KK; nbr[n][k] = g_idx[(node0+n)*KK + k]; }
    __syncthreads();
    for (int u = tj; u < 2*KK*128; u += 128) {
        int nk = u >> 7, i = u & 127;
        int n = nk/KK, k = nk%KK;
        ((float*)xsd4[n][k])[i] = g_sHn[(b*NN + nbr[n][k])*128 + i];
    }
    __syncthreads();

    u64 a2A[2][KK], a2B[2][KK];
    u64 c2A[2], c2B[2];
    float bdv = bd1[tj];
    #pragma unroll
    for (int n = 0; n < 2; n++) {
        c2A[n] = pack2(bdv, 0.0f); c2B[n] = c2A[n];
        #pragma unroll
        for (int k = 0; k < KK; k++){ a2A[n][k] = 0ULL; a2B[n][k] = 0ULL; }
    }
    #pragma unroll 2
    for (int i4 = 0; i4 < 32; i4++) {
        int i = 4*i4;
        u64 w1A = pack2(Wd1[(i+0)*128+tj],     Wd1[(i+1)*128+tj]);
        u64 w1B = pack2(Wd1[(i+2)*128+tj],     Wd1[(i+3)*128+tj]);
        u64 w2A = pack2(Wd1[(128+i+0)*128+tj], Wd1[(128+i+1)*128+tj]);
        u64 w2B = pack2(Wd1[(128+i+2)*128+tj], Wd1[(128+i+3)*128+tj]);
        #pragma unroll
        for (int n = 0; n < 2; n++) {
            ulonglong2 hc = *reinterpret_cast<const ulonglong2*>(&shc4[n][i4]);
            fma2(c2A[n], hc.x, w1A); fma2(c2A[n], hc.y, w1B);   // top · hc
            fma2(c2B[n], hc.x, w2A); fma2(c2B[n], hc.y, w2B);   // bottom · hc
            #pragma unroll
            for (int k = 0; k < KK; k++) {
                ulonglong2 hd = *reinterpret_cast<const ulonglong2*>(&xsd4[n][k][i4]);
                fma2(a2A[n][k], hd.x, w2A); fma2(a2A[n][k], hd.y, w2B);  // bottom · hd
                fma2(a2B[n][k], hd.x, w1A); fma2(a2B[n][k], hd.y, w1B);  // top · hd
            }
        }
    }
    float wd2 = Wd2[tj];
    #pragma unroll
    for (int n = 0; n < 2; n++) {
        float cA = hsum2(c2A[n]), cB = hsum2(c2B[n]);
        #pragma unroll
        for (int k = 0; k < KK; k++) {
            ((float*)sAB4[n][k])[tj] =
                (silu_f(cA + hsum2(a2A[n][k])) + silu_f(cB + hsum2(a2B[n][k]))) * wd2;
        }
    }
    __syncthreads();
    if (tj < 2*KK) {
        int n = tj/KK, k = tj%KK;
        float4 s4 = make_float4(0.f,0.f,0.f,0.f);
        #pragma unroll 8
        for (int i4 = 0; i4 < 32; i4++) {
            float4 v = sAB4[n][k][i4];
            s4.x += v.x; s4.y += v.y; s4.z += v.z; s4.w += v.w;
        }
        out[POFF + (node0+n)*KK + k] = 2.0f*bd2[0] + s4.x + s4.y + s4.z + s4.w;
    }
}

// ---------------- launcher ----------------
extern "C" void kernel_launch(void* const* d_in, const int* in_sizes, int n_in,
                              void* d_out, int out_size)
{
    const float* X   = (const float*)d_in[0];
    const int*   S   = (const int*)  d_in[1];
    const float* t   = (const float*)d_in[2];
    const float* emb = (const float*)d_in[3];
    const float* Wt1 = (const float*)d_in[4];
    const float* bt1 = (const float*)d_in[5];
    const float* Wt2 = (const float*)d_in[6];
    const float* bt2 = (const float*)d_in[7];
    const float* We1 = (const float*)d_in[8];
    const float* be1 = (const float*)d_in[9];
    const float* We2 = (const float*)d_in[10];
    const float* be2 = (const float*)d_in[11];
    const float* Wx1 = (const float*)d_in[12];
    const float* bx1 = (const float*)d_in[13];
    const float* Wx2 = (const float*)d_in[14];
    const float* bx2 = (const float*)d_in[15];
    const float* Wh1 = (const float*)d_in[16];
    const float* bh1 = (const float*)d_in[17];
    const float* Wh2 = (const float*)d_in[18];
    const float* bh2 = (const float*)d_in[19];
    const float* Wd1 = (const float*)d_in[20];
    const float* bd1 = (const float*)d_in[21];
    const float* Wd2 = (const float*)d_in[22];
    const float* bd2 = (const float*)d_in[23];
    const float* Wp1 = (const float*)d_in[24];
    const float* bp1 = (const float*)d_in[25];
    const float* Wr1 = (const float*)d_in[26];
    const float* br1 = (const float*)d_in[27];
    const float* Wr2 = (const float*)d_in[28];
    const float* br2 = (const float*)d_in[29];
    float* out = (float*)d_out;

    k_hh<<<NODES/2, 128>>>(t, S, emb, Wt1, bt1, Wt2, bt2);
    k_knn<<<BB*(NN/128), 128>>>(X);
    k_edge<<<NODES/2, 128>>>(X, S, emb,
                             We1, be1, We2, be2,
                             Wx1, bx1, Wx2, bx2,
                             Wh1, bh1, Wh2, bh2,
                             Wp1, bp1, Wr1, br1, Wr2, br2,
                             out);
    k_pd<<<NODES/2, 128>>>(Wd1, bd1, Wd2, bd2, out);
}

// round 11
// speedup vs baseline: 2.4209x; 1.2659x over previous
#include <cuda_runtime.h>
#include <math.h>

#define BB 32
#define NN 1024
#define CC 14
#define KK 9
#define EE 128
#define HH 128
#define NCC 25
#define NODES (BB*NN)

// output layout: logits (B,N,25) | X_out (B,N,14,3) | pd (B,N,9)
#define L_SZ (NODES*NCC)
#define X_SZ (NODES*CC*3)
#define XOFF L_SZ
#define POFF (L_SZ + X_SZ)

typedef unsigned long long u64;

// scratch (allowed: __device__ globals, no runtime alloc)
__device__ float g_Hh[NODES*EE];    // raw Hh
__device__ float g_sHh[NODES*EE];   // silu(Hh)
__device__ float g_y1[NODES*EE];    // We1[128:256]^T . silu(Hh[n])  (per-node neighbor term of GEMM1)
__device__ float g_sHn[NODES*EE];   // silu(Hn)  (kept for debug/symmetry)
__device__ float g_yT[NODES*EE];    // Wd1[0:128]^T   . silu(Hn[n])
__device__ float g_yB[NODES*EE];    // Wd1[128:256]^T . silu(Hn[n])
__device__ int   g_idx[NODES*KK];

// fast transcendentals: MUFU.EX2 + MUFU.RCP (~2^-21 rel err; budget is 1e-3)
__device__ __forceinline__ float silu_f(float x){ return __fdividef(x, 1.0f + __expf(-x)); }
__device__ __forceinline__ float sigm_f(float x){ return __fdividef(1.0f, 1.0f + __expf(-x)); }

// ---- packed fp32 (Blackwell FFMA2; PTX-only) ----
__device__ __forceinline__ u64 pack2(float lo, float hi){
    u64 r;
    asm("mov.b64 %0, {%1, %2};" : "=l"(r) : "r"(__float_as_uint(lo)), "r"(__float_as_uint(hi)));
    return r;
}
__device__ __forceinline__ void fma2(u64 &d, u64 a, u64 b){
    asm("fma.rn.f32x2 %0, %1, %2, %0;" : "+l"(d) : "l"(a), "l"(b));
}
__device__ __forceinline__ float hsum2(u64 v){
    unsigned lo, hi;
    asm("mov.b64 {%0, %1}, %2;" : "=r"(lo), "=r"(hi) : "l"(v));
    return __uint_as_float(lo) + __uint_as_float(hi);
}

// ---------------- K1: Hh = emb[S] + time_emb(t) ; y1 = We1_mid^T silu(Hh). 2 nodes/block ----
__global__ __launch_bounds__(128) void k_hh(
    const float* __restrict__ t, const int* __restrict__ S,
    const float* __restrict__ emb,
    const float* __restrict__ Wt1, const float* __restrict__ bt1,
    const float* __restrict__ Wt2, const float* __restrict__ bt2,
    const float* __restrict__ We1)
{
    int node0 = 2*blockIdx.x;
    int j = threadIdx.x;
    __shared__ float4 g4[2][32], h4[2][32], ssh[2][32];
    #pragma unroll
    for (int n = 0; n < 2; n++) {
        float tv = t[node0+n];
        float d = tv - (float)j*(1.0f/127.0f) + 1e-6f;
        ((float*)g4[n])[j] = expf(-8064.5f*d*d);   // precise exp (large args)
    }
    __syncthreads();
    float a[2] = {bt1[j], bt1[j]};
    #pragma unroll 4
    for (int i4 = 0; i4 < 32; i4++) {
        int i = 4*i4;
        float w0 = Wt1[(i+0)*128+j], w1 = Wt1[(i+1)*128+j];
        float w2 = Wt1[(i+2)*128+j], w3 = Wt1[(i+3)*128+j];
        #pragma unroll
        for (int n = 0; n < 2; n++) {
            float4 g = g4[n][i4];
            a[n] += g.x*w0 + g.y*w1 + g.z*w2 + g.w*w3;
        }
    }
    #pragma unroll
    for (int n = 0; n < 2; n++) ((float*)h4[n])[j] = fmaxf(a[n], 0.0f);
    __syncthreads();
    float a2[2] = {bt2[j], bt2[j]};
    #pragma unroll 4
    for (int i4 = 0; i4 < 32; i4++) {
        int i = 4*i4;
        float w0 = Wt2[(i+0)*128+j], w1 = Wt2[(i+1)*128+j];
        float w2 = Wt2[(i+2)*128+j], w3 = Wt2[(i+3)*128+j];
        #pragma unroll
        for (int n = 0; n < 2; n++) {
            float4 h = h4[n][i4];
            a2[n] += h.x*w0 + h.y*w1 + h.z*w2 + h.w*w3;
        }
    }
    #pragma unroll
    for (int n = 0; n < 2; n++) {
        float hv = emb[S[node0+n]*128+j] + a2[n];
        float sh = silu_f(hv);
        g_Hh[(node0+n)*128+j]  = hv;
        g_sHh[(node0+n)*128+j] = sh;
        ((float*)ssh[n])[j] = sh;
    }
    __syncthreads();
    // y1 = We1 rows [128,256) ^T . silu(Hh)
    float y[2] = {0.0f, 0.0f};
    #pragma unroll 4
    for (int i4 = 0; i4 < 32; i4++) {
        int i = 128 + 4*i4;
        float w0 = We1[(i+0)*128+j], w1 = We1[(i+1)*128+j];
        float w2 = We1[(i+2)*128+j], w3 = We1[(i+3)*128+j];
        #pragma unroll
        for (int n = 0; n < 2; n++) {
            float4 s = ssh[n][i4];
            y[n] += s.x*w0 + s.y*w1 + s.z*w2 + s.w*w3;
        }
    }
    #pragma unroll
    for (int n = 0; n < 2; n++) g_y1[(node0+n)*128+j] = y[n];
}

// ---------------- K2: top-9 nearest neighbors on ca = X[:,:,1,:] ----------------
__global__ __launch_bounds__(128) void k_knn(const float* __restrict__ X)
{
    __shared__ float sca[NN*3];
    int b = blockIdx.x >> 3;
    int tile = blockIdx.x & 7;
    int tj = threadIdx.x;
    for (int u = tj; u < NN*3; u += 128) {
        int n = u/3, d = u - n*3;
        sca[u] = X[((b*NN + n)*CC + 1)*3 + d];
    }
    __syncthreads();
    int n = tile*128 + tj;
    float qx = sca[n*3+0], qy = sca[n*3+1], qz = sca[n*3+2];
    float bd[KK]; int bi[KK];
    #pragma unroll
    for (int i = 0; i < KK; i++){ bd[i] = 1e30f; bi[i] = 0; }
    for (int j = 0; j < NN; j++) {
        float dx = qx - sca[j*3+0];
        float dy = qy - sca[j*3+1];
        float dz = qz - sca[j*3+2];
        float d = dx*dx + dy*dy + dz*dz;
        if (j == n) d = 1e30f;
        if (d < bd[KK-1]) {                  // strict <: stable tie order
            bd[KK-1] = d; bi[KK-1] = j;
            #pragma unroll
            for (int q = KK-1; q > 0; q--) {
                if (bd[q] < bd[q-1]) {
                    float td = bd[q]; bd[q] = bd[q-1]; bd[q-1] = td;
                    int   ti = bi[q]; bi[q] = bi[q-1]; bi[q-1] = ti;
                }
            }
        }
    }
    #pragma unroll
    for (int k = 0; k < KK; k++) g_idx[(b*NN + n)*KK + k] = bi[k];
}

// ---------------- K3: edge FFNs + X_out + Hn + gate + logits + yT/yB, 2 nodes/block ----------
// xs4 holds ONLY radial features (196 floats = 49 float4 per edge).
// Aliases: sm4 (silu(m)) lives in xs4 (dead after GEMM1); sbuf lives in sh14 (dead after GEMM2).
__global__ __launch_bounds__(128) void k_edge(
    const float* __restrict__ X, const int* __restrict__ S, const float* __restrict__ emb,
    const float* __restrict__ We1, const float* __restrict__ be1,
    const float* __restrict__ We2, const float* __restrict__ be2,
    const float* __restrict__ Wx1, const float* __restrict__ bx1,
    const float* __restrict__ Wx2, const float* __restrict__ bx2,
    const float* __restrict__ Wh1, const float* __restrict__ bh1,
    const float* __restrict__ Wh2, const float* __restrict__ bh2,
    const float* __restrict__ Wd1, const float* __restrict__ bd1,
    const float* __restrict__ Wp1, const float* __restrict__ bp1,
    const float* __restrict__ Wr1, const float* __restrict__ br1,
    const float* __restrict__ Wr2, const float* __restrict__ br2,
    float* __restrict__ out)
{
    int node0 = 2*blockIdx.x;
    int tj = threadIdx.x;
    int b = node0 >> 10;

    __shared__ float4 xs4[2][441];     // radial: 9 edges x 49 float4
    __shared__ float4 sh14[2][288];    // silu(h1): 9x128 floats (later aliased by sbuf)
    __shared__ float  relb[2][KK][42];
    __shared__ float4 shc4[2][32];
    __shared__ float  hcr[2][128];
    __shared__ float  xcen[2][42];
    __shared__ int    nbr[2][KK];
    __shared__ float4 smsum4[2][32];
    __shared__ float  wk[2][KK];
    __shared__ float  wx2s[128];
    __shared__ float4 tmpv4[2][32];
    __shared__ float4 snn4[2][32];
    __shared__ float4 sx04[2][32];

    #define SM4(n,k,i4)    xs4[n][(k)*32+(i4)]     // alias: valid after GEMM1
    #define SM4F(n,k)      ((float*)&xs4[n][(k)*32])
    #define SBUF4(n,k,i4)  sh14[n][(k)*32+(i4)]    // alias: valid after GEMM2
    #define SBUF4F(n,k)    ((float*)&sh14[n][(k)*32])

    {
        #pragma unroll
        for (int n = 0; n < 2; n++) {
            hcr[n][tj] = g_Hh[(node0+n)*128 + tj];
            ((float*)shc4[n])[tj] = g_sHh[(node0+n)*128 + tj];
        }
        wx2s[tj] = Wx2[tj];
        if (tj < 84) { int n = tj/42, i = tj%42; xcen[n][i] = X[(node0+n)*CC*3 + i]; }
        if (tj < 2*KK) { int n = tj/KK, k = tj%KK; nbr[n][k] = g_idx[(node0+n)*KK + k]; }
    }
    __syncthreads();

    // rel vectors
    for (int u = tj; u < 2*KK*42; u += 128) {
        int idx = u/42, i = u - idx*42;
        int n = idx/KK, k = idx%KK;
        relb[n][k][i] = xcen[n][i] - X[(b*NN + nbr[n][k])*CC*3 + i];
    }
    __syncthreads();

    // radial = rel @ rel^T / C (14x14 Gram), silu'd; compact layout k*196+i
    for (int u = tj; u < 2*KK*196; u += 128) {
        int idx = u/196, i = u - idx*196;
        int n = idx/KK, k = idx%KK;
        int c = i/14, e = i - c*14;
        const float* r1 = &relb[n][k][c*3];
        const float* r2 = &relb[n][k][e*3];
        float rv = (r1[0]*r2[0] + r1[1]*r2[1] + r1[2]*r2[2]) * (1.0f/14.0f);
        ((float*)xs4[n])[k*196 + i] = silu_f(rv);
    }
    __syncthreads();

    u64 acc2[2][KK];

    // GEMM1: acc = base(center) + y1[neighbor] + We1_radial^T . radial
    {
        float base[2] = {be1[tj], be1[tj]};
        #pragma unroll 4
        for (int i4 = 0; i4 < 32; i4++) {
            int i = 4*i4;
            float w0 = We1[(i+0)*128+tj], w1 = We1[(i+1)*128+tj];
            float w2 = We1[(i+2)*128+tj], w3 = We1[(i+3)*128+tj];
            #pragma unroll
            for (int n = 0; n < 2; n++) {
                float4 a = shc4[n][i4];
                base[n] += a.x*w0 + a.y*w1 + a.z*w2 + a.w*w3;
            }
        }
        #pragma unroll
        for (int n = 0; n < 2; n++)
            #pragma unroll
            for (int k = 0; k < KK; k++) {
                float y1v = g_y1[(b*NN + nbr[n][k])*128 + tj];
                acc2[n][k] = pack2(base[n] + y1v, 0.0f);
            }
        #pragma unroll 3
        for (int i4 = 0; i4 < 49; i4++) {
            int ib = 256 + 4*i4;
            u64 wA = pack2(We1[(ib+0)*128+tj], We1[(ib+1)*128+tj]);
            u64 wB = pack2(We1[(ib+2)*128+tj], We1[(ib+3)*128+tj]);
            #pragma unroll
            for (int n = 0; n < 2; n++) {
                const ulonglong2* xr = reinterpret_cast<const ulonglong2*>(xs4[n]);
                #pragma unroll
                for (int k = 0; k < KK; k++) {
                    ulonglong2 a = xr[k*49 + i4];   // float off k*196+4*i4
                    fma2(acc2[n][k], a.x, wA);
                    fma2(acc2[n][k], a.y, wB);
                }
            }
        }
        #pragma unroll
        for (int n = 0; n < 2; n++)
            #pragma unroll
            for (int k = 0; k < KK; k++)
                ((float*)&sh14[n][k*32])[tj] = silu_f(hsum2(acc2[n][k]));
    }
    __syncthreads();

    // GEMM2: m = silu(h1) @ We2 + be2 ; msum  (writes sm4 -> alias of xs4, now dead)
    {
        float bv = be2[tj];
        #pragma unroll
        for (int n = 0; n < 2; n++)
            #pragma unroll
            for (int k = 0; k < KK; k++) acc2[n][k] = pack2(bv, 0.0f);
        #pragma unroll 2
        for (int i4 = 0; i4 < 32; i4++) {
            int i = 4*i4;
            u64 wA = pack2(We2[(i+0)*128+tj], We2[(i+1)*128+tj]);
            u64 wB = pack2(We2[(i+2)*128+tj], We2[(i+3)*128+tj]);
            #pragma unroll
            for (int n = 0; n < 2; n++) {
                #pragma unroll
                for (int k = 0; k < KK; k++) {
                    ulonglong2 a = *reinterpret_cast<const ulonglong2*>(&sh14[n][k*32 + i4]);
                    fma2(acc2[n][k], a.x, wA);
                    fma2(acc2[n][k], a.y, wB);
                }
            }
        }
        #pragma unroll
        for (int n = 0; n < 2; n++) {
            float msv = 0.0f;
            #pragma unroll
            for (int k = 0; k < KK; k++) {
                float mv = hsum2(acc2[n][k]);
                msv += mv;
                SM4F(n,k)[tj] = silu_f(mv);
            }
            ((float*)smsum4[n])[tj] = silu_f(msv);
        }
    }
    __syncthreads();

    // GEMM3: h2 = silu(m) @ Wx1 + bx1 ; sbuf = silu(h2)*Wx2 (alias over sh14, now dead)
    {
        float bv = bx1[tj];
        #pragma unroll
        for (int n = 0; n < 2; n++)
            #pragma unroll
            for (int k = 0; k < KK; k++) acc2[n][k] = pack2(bv, 0.0f);
        #pragma unroll 2
        for (int i4 = 0; i4 < 32; i4++) {
            int i = 4*i4;
            u64 wA = pack2(Wx1[(i+0)*128+tj], Wx1[(i+1)*128+tj]);
            u64 wB = pack2(Wx1[(i+2)*128+tj], Wx1[(i+3)*128+tj]);
            #pragma unroll
            for (int n = 0; n < 2; n++) {
                #pragma unroll
                for (int k = 0; k < KK; k++) {
                    ulonglong2 a = *reinterpret_cast<const ulonglong2*>(&SM4(n,k,i4));
                    fma2(acc2[n][k], a.x, wA);
                    fma2(acc2[n][k], a.y, wB);
                }
            }
        }
        float wxv = wx2s[tj];
        __syncthreads();   // all sm4 reads done before sbuf overwrites sh14? (sbuf!=sm4; this guards sh14 readers: none. kept for safety vs GEMM2 stragglers)
        #pragma unroll
        for (int n = 0; n < 2; n++)
            #pragma unroll
            for (int k = 0; k < KK; k++)
                SBUF4F(n,k)[tj] = silu_f(hsum2(acc2[n][k])) * wxv;
    }
    __syncthreads();

    if (tj < 2*KK) {
        int n = tj/KK, k = tj%KK;
        float4 s4 = make_float4(0.f,0.f,0.f,0.f);
        #pragma unroll 8
        for (int i4 = 0; i4 < 32; i4++) {
            float4 v = SBUF4(n,k,i4);
            s4.x += v.x; s4.y += v.y; s4.z += v.z; s4.w += v.w;
        }
        wk[n][k] = bx2[0] + s4.x + s4.y + s4.z + s4.w;
    }
    __syncthreads();

    // X_out = X + mean_k(rel * w)
    if (tj < 84) {
        int n = tj/42, i = tj%42;
        float s = 0.0f;
        #pragma unroll
        for (int k = 0; k < KK; k++) s += relb[n][k][i]*wk[n][k];
        out[XOFF + (node0+n)*42 + i] = xcen[n][i] + s*(1.0f/9.0f);
    }

    // Hn = Hh + FFN([Hh, msum])
    {
        float a[2] = {bh1[tj], bh1[tj]};
        #pragma unroll 4
        for (int i4 = 0; i4 < 32; i4++) {
            int i = 4*i4;
            float w0 = Wh1[(i+0)*128+tj], w1 = Wh1[(i+1)*128+tj];
            float w2 = Wh1[(i+2)*128+tj], w3 = Wh1[(i+3)*128+tj];
            #pragma unroll
            for (int n = 0; n < 2; n++) {
                float4 h = shc4[n][i4];
                a[n] += h.x*w0 + h.y*w1 + h.z*w2 + h.w*w3;
            }
        }
        #pragma unroll 4
        for (int i4 = 0; i4 < 32; i4++) {
            int i = 128 + 4*i4;
            float w0 = Wh1[(i+0)*128+tj], w1 = Wh1[(i+1)*128+tj];
            float w2 = Wh1[(i+2)*128+tj], w3 = Wh1[(i+3)*128+tj];
            #pragma unroll
            for (int n = 0; n < 2; n++) {
                float4 h = smsum4[n][i4];
                a[n] += h.x*w0 + h.y*w1 + h.z*w2 + h.w*w3;
            }
        }
        #pragma unroll
        for (int n = 0; n < 2; n++) ((float*)tmpv4[n])[tj] = silu_f(a[n]);
    }
    __syncthreads();
    {
        float hn[2];
        #pragma unroll
        for (int n = 0; n < 2; n++) hn[n] = hcr[n][tj] + bh2[tj];
        #pragma unroll 4
        for (int i4 = 0; i4 < 32; i4++) {
            int i = 4*i4;
            float w0 = Wh2[(i+0)*128+tj], w1 = Wh2[(i+1)*128+tj];
            float w2 = Wh2[(i+2)*128+tj], w3 = Wh2[(i+3)*128+tj];
            #pragma unroll
            for (int n = 0; n < 2; n++) {
                float4 h = tmpv4[n][i4];
                hn[n] += h.x*w0 + h.y*w1 + h.z*w2 + h.w*w3;
            }
        }
        #pragma unroll
        for (int n = 0; n < 2; n++) {
            float shn = silu_f(hn[n]);
            g_sHn[(node0+n)*128 + tj] = shn;
            ((float*)snn4[n])[tj] = shn;
        }
    }
    __syncthreads();

    // gate = sigmoid(silu(Hn)@Wp1 + bp1) ; x0 = H0*gate
    {
        float a[2] = {bp1[tj], bp1[tj]};
        #pragma unroll 4
        for (int i4 = 0; i4 < 32; i4++) {
            int i = 4*i4;
            float w0 = Wp1[(i+0)*128+tj], w1 = Wp1[(i+1)*128+tj];
            float w2 = Wp1[(i+2)*128+tj], w3 = Wp1[(i+3)*128+tj];
            #pragma unroll
            for (int n = 0; n < 2; n++) {
                float4 h = snn4[n][i4];
                a[n] += h.x*w0 + h.y*w1 + h.z*w2 + h.w*w3;
            }
        }
        #pragma unroll
        for (int n = 0; n < 2; n++) {
            float gate = sigm_f(a[n]);
            float h0 = emb[S[node0+n]*128 + tj];
            ((float*)sx04[n])[tj] = silu_f(h0*gate);
        }
    }

    // yT/yB for the pd pair-FFN: Wd1_top^T.sHn, Wd1_bot^T.sHn (per node)
    {
        float yT[2] = {0.0f, 0.0f}, yB[2] = {0.0f, 0.0f};
        #pragma unroll 4
        for (int i4 = 0; i4 < 32; i4++) {
            int i = 4*i4;
            float t0 = Wd1[(i+0)*128+tj], t1 = Wd1[(i+1)*128+tj];
            float t2 = Wd1[(i+2)*128+tj], t3 = Wd1[(i+3)*128+tj];
            float b0 = Wd1[(128+i+0)*128+tj], b1v = Wd1[(128+i+1)*128+tj];
            float b2 = Wd1[(128+i+2)*128+tj], b3 = Wd1[(128+i+3)*128+tj];
            #pragma unroll
            for (int n = 0; n < 2; n++) {
                float4 h = snn4[n][i4];
                yT[n] += h.x*t0 + h.y*t1 + h.z*t2 + h.w*t3;
                yB[n] += h.x*b0 + h.y*b1v + h.z*b2 + h.w*b3;
            }
        }
        #pragma unroll
        for (int n = 0; n < 2; n++) {
            g_yT[(node0+n)*128+tj] = yT[n];
            g_yB[(node0+n)*128+tj] = yB[n];
        }
    }
    __syncthreads();
    {
        float a[2] = {br1[tj], br1[tj]};
        #pragma unroll 4
        for (int i4 = 0; i4 < 32; i4++) {
            int i = 4*i4;
            float w0 = Wr1[(i+0)*128+tj], w1 = Wr1[(i+1)*128+tj];
            float w2 = Wr1[(i+2)*128+tj], w3 = Wr1[(i+3)*128+tj];
            #pragma unroll
            for (int n = 0; n < 2; n++) {
                float4 h = sx04[n][i4];
                a[n] += h.x*w0 + h.y*w1 + h.z*w2 + h.w*w3;
            }
        }
        #pragma unroll
        for (int n = 0; n < 2; n++) ((float*)tmpv4[n])[tj] = silu_f(a[n]);
    }
    __syncthreads();
    if (tj < NCC) {
        float a[2] = {br2[tj], br2[tj]};
        #pragma unroll 4
        for (int i4 = 0; i4 < 32; i4++) {
            int i = 4*i4;
            float w0 = Wr2[(i+0)*NCC+tj], w1 = Wr2[(i+1)*NCC+tj];
            float w2 = Wr2[(i+2)*NCC+tj], w3 = Wr2[(i+3)*NCC+tj];
            #pragma unroll
            for (int n = 0; n < 2; n++) {
                float4 h = tmpv4[n][i4];
                a[n] += h.x*w0 + h.y*w1 + h.z*w2 + h.w*w3;
            }
        }
        #pragma unroll
        for (int n = 0; n < 2; n++) out[(node0+n)*NCC + tj] = a[n];
    }
    #undef SM4
    #undef SM4F
    #undef SBUF4
    #undef SBUF4F
}

// ---------------- K4: pd — now just gather + silu + Wd2 dot (yT/yB precomputed) ----------
__global__ __launch_bounds__(128) void k_pd(
    const float* __restrict__ bd1,
    const float* __restrict__ Wd2, const float* __restrict__ bd2,
    float* __restrict__ out)
{
    int node0 = 2*blockIdx.x;
    int tj = threadIdx.x;
    int b = node0 >> 10;

    __shared__ float yTc[2][128], yBc[2][128];
    __shared__ int   nbr[2][KK];
    __shared__ float4 sAB4[2][KK][32];

    #pragma unroll
    for (int n = 0; n < 2; n++) {
        yTc[n][tj] = g_yT[(node0+n)*128 + tj];
        yBc[n][tj] = g_yB[(node0+n)*128 + tj];
    }
    if (tj < 2*KK) { int n = tj/KK, k = tj%KK; nbr[n][k] = g_idx[(node0+n)*KK + k]; }
    __syncthreads();

    float bd1v = bd1[tj];
    float wd2v = Wd2[tj];
    #pragma unroll
    for (int n = 0; n < 2; n++) {
        float ytc = yTc[n][tj] + bd1v;
        float ybc = yBc[n][tj] + bd1v;
        #pragma unroll
        for (int k = 0; k < KK; k++) {
            int d = (b*NN + nbr[n][k])*128 + tj;
            float aA = ytc + g_yB[d];     // [Hs,Hd]: top.hc + bot.hd + bd1
            float aB = g_yT[d] + ybc;     // [Hd,Hs]: top.hd + bot.hc + bd1
            ((float*)sAB4[n][k])[tj] = (silu_f(aA) + silu_f(aB)) * wd2v;
        }
    }
    __syncthreads();
    if (tj < 2*KK) {
        int n = tj/KK, k = tj%KK;
        float4 s4 = make_float4(0.f,0.f,0.f,0.f);
        #pragma unroll 8
        for (int i4 = 0; i4 < 32; i4++) {
            float4 v = sAB4[n][k][i4];
            s4.x += v.x; s4.y += v.y; s4.z += v.z; s4.w += v.w;
        }
        out[POFF + (node0+n)*KK + k] = 2.0f*bd2[0] + s4.x + s4.y + s4.z + s4.w;
    }
}

// ---------------- launcher ----------------
extern "C" void kernel_launch(void* const* d_in, const int* in_sizes, int n_in,
                              void* d_out, int out_size)
{
    const float* X   = (const float*)d_in[0];
    const int*   S   = (const int*)  d_in[1];
    const float* t   = (const float*)d_in[2];
    const float* emb = (const float*)d_in[3];
    const float* Wt1 = (const float*)d_in[4];
    const float* bt1 = (const float*)d_in[5];
    const float* Wt2 = (const float*)d_in[6];
    const float* bt2 = (const float*)d_in[7];
    const float* We1 = (const float*)d_in[8];
    const float* be1 = (const float*)d_in[9];
    const float* We2 = (const float*)d_in[10];
    const float* be2 = (const float*)d_in[11];
    const float* Wx1 = (const float*)d_in[12];
    const float* bx1 = (const float*)d_in[13];
    const float* Wx2 = (const float*)d_in[14];
    const float* bx2 = (const float*)d_in[15];
    const float* Wh1 = (const float*)d_in[16];
    const float* bh1 = (const float*)d_in[17];
    const float* Wh2 = (const float*)d_in[18];
    const float* bh2 = (const float*)d_in[19];
    const float* Wd1 = (const float*)d_in[20];
    const float* bd1 = (const float*)d_in[21];
    const float* Wd2 = (const float*)d_in[22];
    const float* bd2 = (const float*)d_in[23];
    const float* Wp1 = (const float*)d_in[24];
    const float* bp1 = (const float*)d_in[25];
    const float* Wr1 = (const float*)d_in[26];
    const float* br1 = (const float*)d_in[27];
    const float* Wr2 = (const float*)d_in[28];
    const float* br2 = (const float*)d_in[29];
    float* out = (float*)d_out;

    k_hh<<<NODES/2, 128>>>(t, S, emb, Wt1, bt1, Wt2, bt2, We1);
    k_knn<<<BB*(NN/128), 128>>>(X);
    k_edge<<<NODES/2, 128>>>(X, S, emb,
                             We1, be1, We2, be2,
                             Wx1, bx1, Wx2, bx2,
                             Wh1, bh1, Wh2, bh2,
                             Wd1, bd1,
                             Wp1, bp1, Wr1, br1, Wr2, br2,
                             out);
    k_pd<<<NODES/2, 128>>>(bd1, Wd2, bd2, out);
}

// round 13
// speedup vs baseline: 2.6894x; 1.1109x over previous
#include <cuda_runtime.h>
#include <math.h>

#define BB 32
#define NN 1024
#define CC 14
#define KK 9
#define EE 128
#define HH 128
#define NCC 25
#define NODES (BB*NN)

// output layout: logits (B,N,25) | X_out (B,N,14,3) | pd (B,N,9)
#define L_SZ (NODES*NCC)
#define X_SZ (NODES*CC*3)
#define XOFF L_SZ
#define POFF (L_SZ + X_SZ)

#define NSYM 108   // 14 diag + 91 off-diag unique Gram entries, padded to 108 (27 float4)

typedef unsigned long long u64;

// scratch (allowed: __device__ globals, no runtime alloc)
__device__ float g_Hh[NODES*EE];    // raw Hh
__device__ float g_sHh[NODES*EE];   // silu(Hh)
__device__ float g_y1[NODES*EE];    // We1[128:256]^T . silu(Hh[n])
__device__ float g_sHn[NODES*EE];   // silu(Hn)
__device__ float g_yT[NODES*EE];    // Wd1[0:128]^T   . silu(Hn[n])
__device__ float g_yB[NODES*EE];    // Wd1[128:256]^T . silu(Hn[n])
__device__ float g_wsym[NSYM*EE];   // symmetric-folded We1 radial rows
__device__ int   g_idx[NODES*KK];

// off-diagonal pair enumeration (c<e), 91 pairs
__device__ __constant__ unsigned char d_pc[91] = {
    0,0,0,0,0,0,0,0,0,0,0,0,0,
    1,1,1,1,1,1,1,1,1,1,1,1,
    2,2,2,2,2,2,2,2,2,2,2,
    3,3,3,3,3,3,3,3,3,3,
    4,4,4,4,4,4,4,4,4,
    5,5,5,5,5,5,5,5,
    6,6,6,6,6,6,6,
    7,7,7,7,7,7,
    8,8,8,8,8,
    9,9,9,9,
    10,10,10,
    11,11,
    12};
__device__ __constant__ unsigned char d_pe[91] = {
    1,2,3,4,5,6,7,8,9,10,11,12,13,
    2,3,4,5,6,7,8,9,10,11,12,13,
    3,4,5,6,7,8,9,10,11,12,13,
    4,5,6,7,8,9,10,11,12,13,
    5,6,7,8,9,10,11,12,13,
    6,7,8,9,10,11,12,13,
    7,8,9,10,11,12,13,
    8,9,10,11,12,13,
    9,10,11,12,13,
    10,11,12,13,
    11,12,13,
    12,13,
    13};

// fast transcendentals: MUFU.EX2 + MUFU.RCP (~2^-21 rel err; budget is 1e-3)
__device__ __forceinline__ float silu_f(float x){ return __fdividef(x, 1.0f + __expf(-x)); }
__device__ __forceinline__ float sigm_f(float x){ return __fdividef(1.0f, 1.0f + __expf(-x)); }

// ---- packed fp32 (Blackwell FFMA2; PTX-only) ----
__device__ __forceinline__ u64 pack2(float lo, float hi){
    u64 r;
    asm("mov.b64 %0, {%1, %2};" : "=l"(r) : "r"(__float_as_uint(lo)), "r"(__float_as_uint(hi)));
    return r;
}
__device__ __forceinline__ void fma2(u64 &d, u64 a, u64 b){
    asm("fma.rn.f32x2 %0, %1, %2, %0;" : "+l"(d) : "l"(a), "l"(b));
}
__device__ __forceinline__ float hsum2(u64 v){
    unsigned lo, hi;
    asm("mov.b64 {%0, %1}, %2;" : "=r"(lo), "=r"(hi) : "l"(v));
    return __uint_as_float(lo) + __uint_as_float(hi);
}

// ---------------- K0: fold We1 radial rows by Gram symmetry ----------------
__global__ __launch_bounds__(128) void k_wsym(const float* __restrict__ We1)
{
    int u = blockIdx.x;        // feature row 0..NSYM-1
    int tj = threadIdx.x;
    float v;
    if (u < 14) {
        v = We1[(256 + u*14 + u)*128 + tj];
    } else if (u < 105) {
        int p = u - 14;
        int c = d_pc[p], e = d_pe[p];
        v = We1[(256 + c*14 + e)*128 + tj] + We1[(256 + e*14 + c)*128 + tj];
    } else {
        v = 0.0f;
    }
    g_wsym[u*128 + tj] = v;
}

// ---------------- K1: Hh = emb[S] + time_emb(t) ; y1 = We1_mid^T silu(Hh). 2 nodes/block ----
__global__ __launch_bounds__(128) void k_hh(
    const float* __restrict__ t, const int* __restrict__ S,
    const float* __restrict__ emb,
    const float* __restrict__ Wt1, const float* __restrict__ bt1,
    const float* __restrict__ Wt2, const float* __restrict__ bt2,
    const float* __restrict__ We1)
{
    int node0 = 2*blockIdx.x;
    int j = threadIdx.x;
    __shared__ float4 g4[2][32], h4[2][32], ssh[2][32];
    #pragma unroll
    for (int n = 0; n < 2; n++) {
        float tv = t[node0+n];
        float d = tv - (float)j*(1.0f/127.0f) + 1e-6f;
        ((float*)g4[n])[j] = expf(-8064.5f*d*d);   // precise exp (large args)
    }
    __syncthreads();
    float a[2] = {bt1[j], bt1[j]};
    #pragma unroll 4
    for (int i4 = 0; i4 < 32; i4++) {
        int i = 4*i4;
        float w0 = Wt1[(i+0)*128+j], w1 = Wt1[(i+1)*128+j];
        float w2 = Wt1[(i+2)*128+j], w3 = Wt1[(i+3)*128+j];
        #pragma unroll
        for (int n = 0; n < 2; n++) {
            float4 g = g4[n][i4];
            a[n] += g.x*w0 + g.y*w1 + g.z*w2 + g.w*w3;
        }
    }
    #pragma unroll
    for (int n = 0; n < 2; n++) ((float*)h4[n])[j] = fmaxf(a[n], 0.0f);
    __syncthreads();
    float a2[2] = {bt2[j], bt2[j]};
    #pragma unroll 4
    for (int i4 = 0; i4 < 32; i4++) {
        int i = 4*i4;
        float w0 = Wt2[(i+0)*128+j], w1 = Wt2[(i+1)*128+j];
        float w2 = Wt2[(i+2)*128+j], w3 = Wt2[(i+3)*128+j];
        #pragma unroll
        for (int n = 0; n < 2; n++) {
            float4 h = h4[n][i4];
            a2[n] += h.x*w0 + h.y*w1 + h.z*w2 + h.w*w3;
        }
    }
    #pragma unroll
    for (int n = 0; n < 2; n++) {
        float hv = emb[S[node0+n]*128+j] + a2[n];
        float sh = silu_f(hv);
        g_Hh[(node0+n)*128+j]  = hv;
        g_sHh[(node0+n)*128+j] = sh;
        ((float*)ssh[n])[j] = sh;
    }
    __syncthreads();
    // y1 = We1 rows [128,256) ^T . silu(Hh)
    float y[2] = {0.0f, 0.0f};
    #pragma unroll 4
    for (int i4 = 0; i4 < 32; i4++) {
        int i = 128 + 4*i4;
        float w0 = We1[(i+0)*128+j], w1 = We1[(i+1)*128+j];
        float w2 = We1[(i+2)*128+j], w3 = We1[(i+3)*128+j];
        #pragma unroll
        for (int n = 0; n < 2; n++) {
            float4 s = ssh[n][i4];
            y[n] += s.x*w0 + s.y*w1 + s.z*w2 + s.w*w3;
        }
    }
    #pragma unroll
    for (int n = 0; n < 2; n++) g_y1[(node0+n)*128+j] = y[n];
}

// ---------------- K2: top-9 nearest neighbors on ca = X[:,:,1,:] ----------------
__global__ __launch_bounds__(128) void k_knn(const float* __restrict__ X)
{
    __shared__ float sca[NN*3];
    int b = blockIdx.x >> 3;
    int tile = blockIdx.x & 7;
    int tj = threadIdx.x;
    for (int u = tj; u < NN*3; u += 128) {
        int n = u/3, d = u - n*3;
        sca[u] = X[((b*NN + n)*CC + 1)*3 + d];
    }
    __syncthreads();
    int n = tile*128 + tj;
    float qx = sca[n*3+0], qy = sca[n*3+1], qz = sca[n*3+2];
    float bd[KK]; int bi[KK];
    #pragma unroll
    for (int i = 0; i < KK; i++){ bd[i] = 1e30f; bi[i] = 0; }
    for (int j = 0; j < NN; j++) {
        float dx = qx - sca[j*3+0];
        float dy = qy - sca[j*3+1];
        float dz = qz - sca[j*3+2];
        float d = dx*dx + dy*dy + dz*dz;
        if (j == n) d = 1e30f;
        if (d < bd[KK-1]) {                  // strict <: stable tie order
            bd[KK-1] = d; bi[KK-1] = j;
            #pragma unroll
            for (int q = KK-1; q > 0; q--) {
                if (bd[q] < bd[q-1]) {
                    float td = bd[q]; bd[q] = bd[q-1]; bd[q-1] = td;
                    int   ti = bi[q]; bi[q] = bi[q-1]; bi[q-1] = ti;
                }
            }
        }
    }
    #pragma unroll
    for (int k = 0; k < KK; k++) g_idx[(b*NN + n)*KK + k] = bi[k];
}

// ---------------- K3: edge FFNs + X_out + Hn + gate + logits + yT/yB, 2 nodes/block ----------
// xs4 holds compact symmetric radial features (108 floats = 27 float4 per edge).
// Aliases: sm4 (silu(m)) lives in xs4 (dead after GEMM1); sbuf lives in sh14 (dead after GEMM2).
__global__ __launch_bounds__(128) void k_edge(
    const float* __restrict__ X, const int* __restrict__ S, const float* __restrict__ emb,
    const float* __restrict__ We1, const float* __restrict__ be1,
    const float* __restrict__ We2, const float* __restrict__ be2,
    const float* __restrict__ Wx1, const float* __restrict__ bx1,
    const float* __restrict__ Wx2, const float* __restrict__ bx2,
    const float* __restrict__ Wh1, const float* __restrict__ bh1,
    const float* __restrict__ Wh2, const float* __restrict__ bh2,
    const float* __restrict__ Wd1, const float* __restrict__ bd1,
    const float* __restrict__ Wp1, const float* __restrict__ bp1,
    const float* __restrict__ Wr1, const float* __restrict__ br1,
    const float* __restrict__ Wr2, const float* __restrict__ br2,
    float* __restrict__ out)
{
    int node0 = 2*blockIdx.x;
    int tj = threadIdx.x;
    int b = node0 >> 10;

    __shared__ float4 xs4[2][288];     // radial (9 x 27 = 243 used) ; aliased by sm4 after GEMM1
    __shared__ float4 sh14[2][288];    // silu(h1): 9x128 ; aliased by sbuf after GEMM2
    __shared__ float  relb[2][KK][42];
    __shared__ float4 shc4[2][32];
    __shared__ float  hcr[2][128];
    __shared__ float  xcen[2][42];
    __shared__ int    nbr[2][KK];
    __shared__ float4 smsum4[2][32];
    __shared__ float  wk[2][KK];
    __shared__ float  wx2s[128];
    __shared__ float4 tmpv4[2][32];
    __shared__ float4 snn4[2][32];
    __shared__ float4 sx04[2][32];

    #define SM4(n,k,i4)    xs4[n][(k)*32+(i4)]     // alias: valid after GEMM1
    #define SM4F(n,k)      ((float*)&xs4[n][(k)*32])
    #define SBUF4(n,k,i4)  sh14[n][(k)*32+(i4)]    // alias: valid after GEMM2
    #define SBUF4F(n,k)    ((float*)&sh14[n][(k)*32])

    {
        #pragma unroll
        for (int n = 0; n < 2; n++) {
            hcr[n][tj] = g_Hh[(node0+n)*128 + tj];
            ((float*)shc4[n])[tj] = g_sHh[(node0+n)*128 + tj];
        }
        wx2s[tj] = Wx2[tj];
        if (tj < 84) { int n = tj/42, i = tj%42; xcen[n][i] = X[(node0+n)*CC*3 + i]; }
        if (tj < 2*KK) { int n = tj/KK, k = tj%KK; nbr[n][k] = g_idx[(node0+n)*KK + k]; }
    }
    __syncthreads();

    // rel vectors
    for (int u = tj; u < 2*KK*42; u += 128) {
        int idx = u/42, i = u - idx*42;
        int n = idx/KK, k = idx%KK;
        relb[n][k][i] = xcen[n][i] - X[(b*NN + nbr[n][k])*CC*3 + i];
    }
    __syncthreads();

    // symmetric radial: 14 diag + 91 unique off-diag, silu'd; layout k*108+i
    for (int u = tj; u < 2*KK*NSYM; u += 128) {
        int idx = u/NSYM, i = u - idx*NSYM;
        int n = idx/KK, k = idx%KK;
        float sv = 0.0f;
        if (i < 105) {
            int c, e;
            if (i < 14) { c = i; e = i; }
            else { c = d_pc[i-14]; e = d_pe[i-14]; }
            const float* r1 = &relb[n][k][c*3];
            const float* r2 = &relb[n][k][e*3];
            float rv = (r1[0]*r2[0] + r1[1]*r2[1] + r1[2]*r2[2]) * (1.0f/14.0f);
            sv = silu_f(rv);
        }
        ((float*)xs4[n])[k*NSYM + i] = sv;
    }
    __syncthreads();

    u64 acc2[2][KK];

    // GEMM1: acc = base(center) + y1[neighbor] + Wsym^T . radial_sym
    {
        float base[2] = {be1[tj], be1[tj]};
        #pragma unroll 4
        for (int i4 = 0; i4 < 32; i4++) {
            int i = 4*i4;
            float w0 = We1[(i+0)*128+tj], w1 = We1[(i+1)*128+tj];
            float w2 = We1[(i+2)*128+tj], w3 = We1[(i+3)*128+tj];
            #pragma unroll
            for (int n = 0; n < 2; n++) {
                float4 a = shc4[n][i4];
                base[n] += a.x*w0 + a.y*w1 + a.z*w2 + a.w*w3;
            }
        }
        #pragma unroll
        for (int n = 0; n < 2; n++)
            #pragma unroll
            for (int k = 0; k < KK; k++) {
                float y1v = g_y1[(b*NN + nbr[n][k])*128 + tj];
                acc2[n][k] = pack2(base[n] + y1v, 0.0f);
            }
        #pragma unroll 3
        for (int i4 = 0; i4 < 27; i4++) {
            int ib = 4*i4;
            u64 wA = pack2(g_wsym[(ib+0)*128+tj], g_wsym[(ib+1)*128+tj]);
            u64 wB = pack2(g_wsym[(ib+2)*128+tj], g_wsym[(ib+3)*128+tj]);
            #pragma unroll
            for (int n = 0; n < 2; n++) {
                const ulonglong2* xr = reinterpret_cast<const ulonglong2*>(xs4[n]);
                #pragma unroll
                for (int k = 0; k < KK; k++) {
                    ulonglong2 a = xr[k*27 + i4];   // float off k*108+4*i4
                    fma2(acc2[n][k], a.x, wA);
                    fma2(acc2[n][k], a.y, wB);
                }
            }
        }
        #pragma unroll
        for (int n = 0; n < 2; n++)
            #pragma unroll
            for (int k = 0; k < KK; k++)
                ((float*)&sh14[n][k*32])[tj] = silu_f(hsum2(acc2[n][k]));
    }
    __syncthreads();

    // GEMM2: m = silu(h1) @ We2 + be2 ; msum  (writes sm4 -> alias of xs4, now dead)
    {
        float bv = be2[tj];
        #pragma unroll
        for (int n = 0; n < 2; n++)
            #pragma unroll
            for (int k = 0; k < KK; k++) acc2[n][k] = pack2(bv, 0.0f);
        #pragma unroll 2
        for (int i4 = 0; i4 < 32; i4++) {
            int i = 4*i4;
            u64 wA = pack2(We2[(i+0)*128+tj], We2[(i+1)*128+tj]);
            u64 wB = pack2(We2[(i+2)*128+tj], We2[(i+3)*128+tj]);
            #pragma unroll
            for (int n = 0; n < 2; n++) {
                #pragma unroll
                for (int k = 0; k < KK; k++) {
                    ulonglong2 a = *reinterpret_cast<const ulonglong2*>(&sh14[n][k*32 + i4]);
                    fma2(acc2[n][k], a.x, wA);
                    fma2(acc2[n][k], a.y, wB);
                }
            }
        }
        #pragma unroll
        for (int n = 0; n < 2; n++) {
            float msv = 0.0f;
            #pragma unroll
            for (int k = 0; k < KK; k++) {
                float mv = hsum2(acc2[n][k]);
                msv += mv;
                SM4F(n,k)[tj] = silu_f(mv);
            }
            ((float*)smsum4[n])[tj] = silu_f(msv);
        }
    }
    __syncthreads();

    // GEMM3: h2 = silu(m) @ Wx1 + bx1 ; sbuf = silu(h2)*Wx2 (alias over sh14, now dead)
    {
        float bv = bx1[tj];
        #pragma unroll
        for (int n = 0; n < 2; n++)
            #pragma unroll
            for (int k = 0; k < KK; k++) acc2[n][k] = pack2(bv, 0.0f);
        #pragma unroll 2
        for (int i4 = 0; i4 < 32; i4++) {
            int i = 4*i4;
            u64 wA = pack2(Wx1[(i+0)*128+tj], Wx1[(i+1)*128+tj]);
            u64 wB = pack2(Wx1[(i+2)*128+tj], Wx1[(i+3)*128+tj]);
            #pragma unroll
            for (int n = 0; n < 2; n++) {
                #pragma unroll
                for (int k = 0; k < KK; k++) {
                    ulonglong2 a = *reinterpret_cast<const ulonglong2*>(&SM4(n,k,i4));
                    fma2(acc2[n][k], a.x, wA);
                    fma2(acc2[n][k], a.y, wB);
                }
            }
        }
        float wxv = wx2s[tj];
        __syncthreads();   // ensure all sh14 (silu(h1)) reads from GEMM2 are done block-wide
        #pragma unroll
        for (int n = 0; n < 2; n++)
            #pragma unroll
            for (int k = 0; k < KK; k++)
                SBUF4F(n,k)[tj] = silu_f(hsum2(acc2[n][k])) * wxv;
    }
    __syncthreads();

    if (tj < 2*KK) {
        int n = tj/KK, k = tj%KK;
        float4 s4 = make_float4(0.f,0.f,0.f,0.f);
        #pragma unroll 8
        for (int i4 = 0; i4 < 32; i4++) {
            float4 v = SBUF4(n,k,i4);
            s4.x += v.x; s4.y += v.y; s4.z += v.z; s4.w += v.w;
        }
        wk[n][k] = bx2[0] + s4.x + s4.y + s4.z + s4.w;
    }
    __syncthreads();

    // X_out = X + mean_k(rel * w)
    if (tj < 84) {
        int n = tj/42, i = tj%42;
        float s = 0.0f;
        #pragma unroll
        for (int k = 0; k < KK; k++) s += relb[n][k][i]*wk[n][k];
        out[XOFF + (node0+n)*42 + i] = xcen[n][i] + s*(1.0f/9.0f);
    }

    // Hn = Hh + FFN([Hh, msum])
    {
        float a[2] = {bh1[tj], bh1[tj]};
        #pragma unroll 4
        for (int i4 = 0; i4 < 32; i4++) {
            int i = 4*i4;
            float w0 = Wh1[(i+0)*128+tj], w1 = Wh1[(i+1)*128+tj];
            float w2 = Wh1[(i+2)*128+tj], w3 = Wh1[(i+3)*128+tj];
            #pragma unroll
            for (int n = 0; n < 2; n++) {
                float4 h = shc4[n][i4];
                a[n] += h.x*w0 + h.y*w1 + h.z*w2 + h.w*w3;
            }
        }
        #pragma unroll 4
        for (int i4 = 0; i4 < 32; i4++) {
            int i = 128 + 4*i4;
            float w0 = Wh1[(i+0)*128+tj], w1 = Wh1[(i+1)*128+tj];
            float w2 = Wh1[(i+2)*128+tj], w3 = Wh1[(i+3)*128+tj];
            #pragma unroll
            for (int n = 0; n < 2; n++) {
                float4 h = smsum4[n][i4];
                a[n] += h.x*w0 + h.y*w1 + h.z*w2 + h.w*w3;
            }
        }
        #pragma unroll
        for (int n = 0; n < 2; n++) ((float*)tmpv4[n])[tj] = silu_f(a[n]);
    }
    __syncthreads();
    {
        float hn[2];
        #pragma unroll
        for (int n = 0; n < 2; n++) hn[n] = hcr[n][tj] + bh2[tj];
        #pragma unroll 4
        for (int i4 = 0; i4 < 32; i4++) {
            int i = 4*i4;
            float w0 = Wh2[(i+0)*128+tj], w1 = Wh2[(i+1)*128+tj];
            float w2 = Wh2[(i+2)*128+tj], w3 = Wh2[(i+3)*128+tj];
            #pragma unroll
            for (int n = 0; n < 2; n++) {
                float4 h = tmpv4[n][i4];
                hn[n] += h.x*w0 + h.y*w1 + h.z*w2 + h.w*w3;
            }
        }
        #pragma unroll
        for (int n = 0; n < 2; n++) {
            float shn = silu_f(hn[n]);
            g_sHn[(node0+n)*128 + tj] = shn;
            ((float*)snn4[n])[tj] = shn;
        }
    }
    __syncthreads();

    // gate = sigmoid(silu(Hn)@Wp1 + bp1) ; x0 = H0*gate
    {
        float a[2] = {bp1[tj], bp1[tj]};
        #pragma unroll 4
        for (int i4 = 0; i4 < 32; i4++) {
            int i = 4*i4;
            float w0 = Wp1[(i+0)*128+tj], w1 = Wp1[(i+1)*128+tj];
            float w2 = Wp1[(i+2)*128+tj], w3 = Wp1[(i+3)*128+tj];
            #pragma unroll
            for (int n = 0; n < 2; n++) {
                float4 h = snn4[n][i4];
                a[n] += h.x*w0 + h.y*w1 + h.z*w2 + h.w*w3;
            }
        }
        #pragma unroll
        for (int n = 0; n < 2; n++) {
            float gate = sigm_f(a[n]);
            float h0 = emb[S[node0+n]*128 + tj];
            ((float*)sx04[n])[tj] = silu_f(h0*gate);
        }
    }

    // yT/yB for the pd pair-FFN: Wd1_top^T.sHn, Wd1_bot^T.sHn (per node)
    {
        float yT[2] = {0.0f, 0.0f}, yB[2] = {0.0f, 0.0f};
        #pragma unroll 4
        for (int i4 = 0; i4 < 32; i4++) {
            int i = 4*i4;
            float t0 = Wd1[(i+0)*128+tj], t1 = Wd1[(i+1)*128+tj];
            float t2 = Wd1[(i+2)*128+tj], t3 = Wd1[(i+3)*128+tj];
            float b0 = Wd1[(128+i+0)*128+tj], b1v = Wd1[(128+i+1)*128+tj];
            float b2 = Wd1[(128+i+2)*128+tj], b3 = Wd1[(128+i+3)*128+tj];
            #pragma unroll
            for (int n = 0; n < 2; n++) {
                float4 h = snn4[n][i4];
                yT[n] += h.x*t0 + h.y*t1 + h.z*t2 + h.w*t3;
                yB[n] += h.x*b0 + h.y*b1v + h.z*b2 + h.w*b3;
            }
        }
        #pragma unroll
        for (int n = 0; n < 2; n++) {
            g_yT[(node0+n)*128+tj] = yT[n];
            g_yB[(node0+n)*128+tj] = yB[n];
        }
    }
    __syncthreads();
    {
        float a[2] = {br1[tj], br1[tj]};
        #pragma unroll 4
        for (int i4 = 0; i4 < 32; i4++) {
            int i = 4*i4;
            float w0 = Wr1[(i+0)*128+tj], w1 = Wr1[(i+1)*128+tj];
            float w2 = Wr1[(i+2)*128+tj], w3 = Wr1[(i+3)*128+tj];
            #pragma unroll
            for (int n = 0; n < 2; n++) {
                float4 h = sx04[n][i4];
                a[n] += h.x*w0 + h.y*w1 + h.z*w2 + h.w*w3;
            }
        }
        #pragma unroll
        for (int n = 0; n < 2; n++) ((float*)tmpv4[n])[tj] = silu_f(a[n]);
    }
    __syncthreads();
    if (tj < NCC) {
        float a[2] = {br2[tj], br2[tj]};
        #pragma unroll 4
        for (int i4 = 0; i4 < 32; i4++) {
            int i = 4*i4;
            float w0 = Wr2[(i+0)*NCC+tj], w1 = Wr2[(i+1)*NCC+tj];
            float w2 = Wr2[(i+2)*NCC+tj], w3 = Wr2[(i+3)*NCC+tj];
            #pragma unroll
            for (int n = 0; n < 2; n++) {
                float4 h = tmpv4[n][i4];
                a[n] += h.x*w0 + h.y*w1 + h.z*w2 + h.w*w3;
            }
        }
        #pragma unroll
        for (int n = 0; n < 2; n++) out[(node0+n)*NCC + tj] = a[n];
    }
    #undef SM4
    #undef SM4F
    #undef SBUF4
    #undef SBUF4F
}

// ---------------- K4: pd — gather + silu + Wd2 dot (yT/yB precomputed) ----------
__global__ __launch_bounds__(128) void k_pd(
    const float* __restrict__ bd1,
    const float* __restrict__ Wd2, const float* __restrict__ bd2,
    float* __restrict__ out)
{
    int node0 = 2*blockIdx.x;
    int tj = threadIdx.x;
    int b = node0 >> 10;

    __shared__ float yTc[2][128], yBc[2][128];
    __shared__ int   nbr[2][KK];
    __shared__ float4 sAB4[2][KK][32];

    #pragma unroll
    for (int n = 0; n < 2; n++) {
        yTc[n][tj] = g_yT[(node0+n)*128 + tj];
        yBc[n][tj] = g_yB[(node0+n)*128 + tj];
    }
    if (tj < 2*KK) { int n = tj/KK, k = tj%KK; nbr[n][k] = g_idx[(node0+n)*KK + k]; }
    __syncthreads();

    float bd1v = bd1[tj];
    float wd2v = Wd2[tj];
    #pragma unroll
    for (int n = 0; n < 2; n++) {
        float ytc = yTc[n][tj] + bd1v;
        float ybc = yBc[n][tj] + bd1v;
        #pragma unroll
        for (int k = 0; k < KK; k++) {
            int d = (b*NN + nbr[n][k])*128 + tj;
            float aA = ytc + g_yB[d];     // [Hs,Hd]: top.hc + bot.hd + bd1
            float aB = g_yT[d] + ybc;     // [Hd,Hs]: top.hd + bot.hc + bd1
            ((float*)sAB4[n][k])[tj] = (silu_f(aA) + silu_f(aB)) * wd2v;
        }
    }
    __syncthreads();
    if (tj < 2*KK) {
        int n = tj/KK, k = tj%KK;
        float4 s4 = make_float4(0.f,0.f,0.f,0.f);
        #pragma unroll 8
        for (int i4 = 0; i4 < 32; i4++) {
            float4 v = sAB4[n][k][i4];
            s4.x += v.x; s4.y += v.y; s4.z += v.z; s4.w += v.w;
        }
        out[POFF + (node0+n)*KK + k] = 2.0f*bd2[0] + s4.x + s4.y + s4.z + s4.w;
    }
}

// ---------------- launcher ----------------
extern "C" void kernel_launch(void* const* d_in, const int* in_sizes, int n_in,
                              void* d_out, int out_size)
{
    const float* X   = (const float*)d_in[0];
    const int*   S   = (const int*)  d_in[1];
    const float* t   = (const float*)d_in[2];
    const float* emb = (const float*)d_in[3];
    const float* Wt1 = (const float*)d_in[4];
    const float* bt1 = (const float*)d_in[5];
    const float* Wt2 = (const float*)d_in[6];
    const float* bt2 = (const float*)d_in[7];
    const float* We1 = (const float*)d_in[8];
    const float* be1 = (const float*)d_in[9];
    const float* We2 = (const float*)d_in[10];
    const float* be2 = (const float*)d_in[11];
    const float* Wx1 = (const float*)d_in[12];
    const float* bx1 = (const float*)d_in[13];
    const float* Wx2 = (const float*)d_in[14];
    const float* bx2 = (const float*)d_in[15];
    const float* Wh1 = (const float*)d_in[16];
    const float* bh1 = (const float*)d_in[17];
    const float* Wh2 = (const float*)d_in[18];
    const float* bh2 = (const float*)d_in[19];
    const float* Wd1 = (const float*)d_in[20];
    const float* bd1 = (const float*)d_in[21];
    const float* Wd2 = (const float*)d_in[22];
    const float* bd2 = (const float*)d_in[23];
    const float* Wp1 = (const float*)d_in[24];
    const float* bp1 = (const float*)d_in[25];
    const float* Wr1 = (const float*)d_in[26];
    const float* br1 = (const float*)d_in[27];
    const float* Wr2 = (const float*)d_in[28];
    const float* br2 = (const float*)d_in[29];
    float* out = (float*)d_out;

    k_wsym<<<NSYM, 128>>>(We1);
    k_hh<<<NODES/2, 128>>>(t, S, emb, Wt1, bt1, Wt2, bt2, We1);
    k_knn<<<BB*(NN/128), 128>>>(X);
    k_edge<<<NODES/2, 128>>>(X, S, emb,
                             We1, be1, We2, be2,
                             Wx1, bx1, Wx2, bx2,
                             Wh1, bh1, Wh2, bh2,
                             Wd1, bd1,
                             Wp1, bp1, Wr1, br1, Wr2, br2,
                             out);
    k_pd<<<NODES/2, 128>>>(bd1, Wd2, bd2, out);
}

// round 14
// speedup vs baseline: 2.7556x; 1.0246x over previous
#include <cuda_runtime.h>
#include <math.h>

#define BB 32
#define NN 1024
#define CC 14
#define KK 9
#define EE 128
#define HH 128
#define NCC 25
#define NODES (BB*NN)

// output layout: logits (B,N,25) | X_out (B,N,14,3) | pd (B,N,9)
#define L_SZ (NODES*NCC)
#define X_SZ (NODES*CC*3)
#define XOFF L_SZ
#define POFF (L_SZ + X_SZ)

#define NSYM 108   // 14 diag + 91 off-diag unique Gram entries, padded to 108 (27 float4)

typedef unsigned long long u64;

// scratch (allowed: __device__ globals, no runtime alloc)
__device__ float g_Hh[NODES*EE];     // raw Hh
__device__ float g_sHh[NODES*EE];    // silu(Hh)
__device__ float g_y1[NODES*EE];     // We1[128:256]^T . silu(Hh[n])
__device__ float g_smsum[NODES*EE];  // silu(sum_k m)
__device__ float g_sHn[NODES*EE];    // silu(Hn)
__device__ float g_yT[NODES*EE];     // Wd1[0:128]^T   . silu(Hn[n])
__device__ float g_yB[NODES*EE];     // Wd1[128:256]^T . silu(Hn[n])
__device__ float g_wsym[NSYM*EE];    // symmetric-folded We1 radial rows
__device__ int   g_idx[NODES*KK];

// off-diagonal pair enumeration (c<e), 91 pairs
__device__ __constant__ unsigned char d_pc[91] = {
    0,0,0,0,0,0,0,0,0,0,0,0,0,
    1,1,1,1,1,1,1,1,1,1,1,1,
    2,2,2,2,2,2,2,2,2,2,2,
    3,3,3,3,3,3,3,3,3,3,
    4,4,4,4,4,4,4,4,4,
    5,5,5,5,5,5,5,5,
    6,6,6,6,6,6,6,
    7,7,7,7,7,7,
    8,8,8,8,8,
    9,9,9,9,
    10,10,10,
    11,11,
    12};
__device__ __constant__ unsigned char d_pe[91] = {
    1,2,3,4,5,6,7,8,9,10,11,12,13,
    2,3,4,5,6,7,8,9,10,11,12,13,
    3,4,5,6,7,8,9,10,11,12,13,
    4,5,6,7,8,9,10,11,12,13,
    5,6,7,8,9,10,11,12,13,
    6,7,8,9,10,11,12,13,
    7,8,9,10,11,12,13,
    8,9,10,11,12,13,
    9,10,11,12,13,
    10,11,12,13,
    11,12,13,
    12,13,
    13};

// fast transcendentals: MUFU.EX2 + MUFU.RCP (~2^-21 rel err; budget is 1e-3)
__device__ __forceinline__ float silu_f(float x){ return __fdividef(x, 1.0f + __expf(-x)); }
__device__ __forceinline__ float sigm_f(float x){ return __fdividef(1.0f, 1.0f + __expf(-x)); }

// ---- packed fp32 (Blackwell FFMA2; PTX-only) ----
__device__ __forceinline__ u64 pack2(float lo, float hi){
    u64 r;
    asm("mov.b64 %0, {%1, %2};" : "=l"(r) : "r"(__float_as_uint(lo)), "r"(__float_as_uint(hi)));
    return r;
}
__device__ __forceinline__ void fma2(u64 &d, u64 a, u64 b){
    asm("fma.rn.f32x2 %0, %1, %2, %0;" : "+l"(d) : "l"(a), "l"(b));
}
__device__ __forceinline__ float hsum2(u64 v){
    unsigned lo, hi;
    asm("mov.b64 {%0, %1}, %2;" : "=r"(lo), "=r"(hi) : "l"(v));
    return __uint_as_float(lo) + __uint_as_float(hi);
}

// ---------------- K0: fold We1 radial rows by Gram symmetry ----------------
__global__ __launch_bounds__(128) void k_wsym(const float* __restrict__ We1)
{
    int u = blockIdx.x;        // feature row 0..NSYM-1
    int tj = threadIdx.x;
    float v;
    if (u < 14) {
        v = We1[(256 + u*14 + u)*128 + tj];
    } else if (u < 105) {
        int p = u - 14;
        int c = d_pc[p], e = d_pe[p];
        v = We1[(256 + c*14 + e)*128 + tj] + We1[(256 + e*14 + c)*128 + tj];
    } else {
        v = 0.0f;
    }
    g_wsym[u*128 + tj] = v;
}

// ---------------- K1: Hh = emb[S] + time_emb(t) ; y1 = We1_mid^T silu(Hh). 2 nodes/block ----
__global__ __launch_bounds__(128) void k_hh(
    const float* __restrict__ t, const int* __restrict__ S,
    const float* __restrict__ emb,
    const float* __restrict__ Wt1, const float* __restrict__ bt1,
    const float* __restrict__ Wt2, const float* __restrict__ bt2,
    const float* __restrict__ We1)
{
    int node0 = 2*blockIdx.x;
    int j = threadIdx.x;
    __shared__ float4 g4[2][32], h4[2][32], ssh[2][32];
    #pragma unroll
    for (int n = 0; n < 2; n++) {
        float tv = t[node0+n];
        float d = tv - (float)j*(1.0f/127.0f) + 1e-6f;
        ((float*)g4[n])[j] = expf(-8064.5f*d*d);   // precise exp (large args)
    }
    __syncthreads();
    float a[2] = {bt1[j], bt1[j]};
    #pragma unroll 4
    for (int i4 = 0; i4 < 32; i4++) {
        int i = 4*i4;
        float w0 = Wt1[(i+0)*128+j], w1 = Wt1[(i+1)*128+j];
        float w2 = Wt1[(i+2)*128+j], w3 = Wt1[(i+3)*128+j];
        #pragma unroll
        for (int n = 0; n < 2; n++) {
            float4 g = g4[n][i4];
            a[n] += g.x*w0 + g.y*w1 + g.z*w2 + g.w*w3;
        }
    }
    #pragma unroll
    for (int n = 0; n < 2; n++) ((float*)h4[n])[j] = fmaxf(a[n], 0.0f);
    __syncthreads();
    float a2[2] = {bt2[j], bt2[j]};
    #pragma unroll 4
    for (int i4 = 0; i4 < 32; i4++) {
        int i = 4*i4;
        float w0 = Wt2[(i+0)*128+j], w1 = Wt2[(i+1)*128+j];
        float w2 = Wt2[(i+2)*128+j], w3 = Wt2[(i+3)*128+j];
        #pragma unroll
        for (int n = 0; n < 2; n++) {
            float4 h = h4[n][i4];
            a2[n] += h.x*w0 + h.y*w1 + h.z*w2 + h.w*w3;
        }
    }
    #pragma unroll
    for (int n = 0; n < 2; n++) {
        float hv = emb[S[node0+n]*128+j] + a2[n];
        float sh = silu_f(hv);
        g_Hh[(node0+n)*128+j]  = hv;
        g_sHh[(node0+n)*128+j] = sh;
        ((float*)ssh[n])[j] = sh;
    }
    __syncthreads();
    // y1 = We1 rows [128,256) ^T . silu(Hh)
    float y[2] = {0.0f, 0.0f};
    #pragma unroll 4
    for (int i4 = 0; i4 < 32; i4++) {
        int i = 128 + 4*i4;
        float w0 = We1[(i+0)*128+j], w1 = We1[(i+1)*128+j];
        float w2 = We1[(i+2)*128+j], w3 = We1[(i+3)*128+j];
        #pragma unroll
        for (int n = 0; n < 2; n++) {
            float4 s = ssh[n][i4];
            y[n] += s.x*w0 + s.y*w1 + s.z*w2 + s.w*w3;
        }
    }
    #pragma unroll
    for (int n = 0; n < 2; n++) g_y1[(node0+n)*128+j] = y[n];
}

// ---------------- K2: top-9 nearest neighbors on ca = X[:,:,1,:] ----------------
__global__ __launch_bounds__(128) void k_knn(const float* __restrict__ X)
{
    __shared__ float sca[NN*3];
    int b = blockIdx.x >> 3;
    int tile = blockIdx.x & 7;
    int tj = threadIdx.x;
    for (int u = tj; u < NN*3; u += 128) {
        int n = u/3, d = u - n*3;
        sca[u] = X[((b*NN + n)*CC + 1)*3 + d];
    }
    __syncthreads();
    int n = tile*128 + tj;
    float qx = sca[n*3+0], qy = sca[n*3+1], qz = sca[n*3+2];
    float bd[KK]; int bi[KK];
    #pragma unroll
    for (int i = 0; i < KK; i++){ bd[i] = 1e30f; bi[i] = 0; }
    for (int j = 0; j < NN; j++) {
        float dx = qx - sca[j*3+0];
        float dy = qy - sca[j*3+1];
        float dz = qz - sca[j*3+2];
        float d = dx*dx + dy*dy + dz*dz;
        if (j == n) d = 1e30f;
        if (d < bd[KK-1]) {                  // strict <: stable tie order
            bd[KK-1] = d; bi[KK-1] = j;
            #pragma unroll
            for (int q = KK-1; q > 0; q--) {
                if (bd[q] < bd[q-1]) {
                    float td = bd[q]; bd[q] = bd[q-1]; bd[q-1] = td;
                    int   ti = bi[q]; bi[q] = bi[q-1]; bi[q-1] = ti;
                }
            }
        }
    }
    #pragma unroll
    for (int k = 0; k < KK; k++) g_idx[(b*NN + n)*KK + k] = bi[k];
}

// ---------------- K3: edge GEMMs + X_out + smsum, 2 nodes/block ----------
// xs4 holds compact symmetric radial features (108 floats = 27 float4 per edge).
// Aliases: sm4 (silu(m)) lives in xs4 (dead after GEMM1); sbuf lives in sh14 (dead after GEMM2).
__global__ __launch_bounds__(128) void k_edge(
    const float* __restrict__ X,
    const float* __restrict__ We1, const float* __restrict__ be1,
    const float* __restrict__ We2, const float* __restrict__ be2,
    const float* __restrict__ Wx1, const float* __restrict__ bx1,
    const float* __restrict__ Wx2, const float* __restrict__ bx2,
    float* __restrict__ out)
{
    int node0 = 2*blockIdx.x;
    int tj = threadIdx.x;
    int b = node0 >> 10;

    __shared__ float4 xs4[2][288];     // radial (9 x 27 = 243 used) ; aliased by sm4 after GEMM1
    __shared__ float4 sh14[2][288];    // silu(h1): 9x128 ; aliased by sbuf after GEMM2
    __shared__ float  relb[2][KK][42];
    __shared__ float4 shc4[2][32];
    __shared__ float  xcen[2][42];
    __shared__ int    nbr[2][KK];
    __shared__ float  wk[2][KK];
    __shared__ float  wx2s[128];

    #define SM4(n,k,i4)    xs4[n][(k)*32+(i4)]     // alias: valid after GEMM1
    #define SM4F(n,k)      ((float*)&xs4[n][(k)*32])
    #define SBUF4(n,k,i4)  sh14[n][(k)*32+(i4)]    // alias: valid after GEMM2
    #define SBUF4F(n,k)    ((float*)&sh14[n][(k)*32])

    {
        #pragma unroll
        for (int n = 0; n < 2; n++)
            ((float*)shc4[n])[tj] = g_sHh[(node0+n)*128 + tj];
        wx2s[tj] = Wx2[tj];
        if (tj < 84) { int n = tj/42, i = tj%42; xcen[n][i] = X[(node0+n)*CC*3 + i]; }
        if (tj < 2*KK) { int n = tj/KK, k = tj%KK; nbr[n][k] = g_idx[(node0+n)*KK + k]; }
    }
    __syncthreads();

    // rel vectors
    for (int u = tj; u < 2*KK*42; u += 128) {
        int idx = u/42, i = u - idx*42;
        int n = idx/KK, k = idx%KK;
        relb[n][k][i] = xcen[n][i] - X[(b*NN + nbr[n][k])*CC*3 + i];
    }
    __syncthreads();

    // symmetric radial: 14 diag + 91 unique off-diag, silu'd; layout k*108+i
    for (int u = tj; u < 2*KK*NSYM; u += 128) {
        int idx = u/NSYM, i = u - idx*NSYM;
        int n = idx/KK, k = idx%KK;
        float sv = 0.0f;
        if (i < 105) {
            int c, e;
            if (i < 14) { c = i; e = i; }
            else { c = d_pc[i-14]; e = d_pe[i-14]; }
            const float* r1 = &relb[n][k][c*3];
            const float* r2 = &relb[n][k][e*3];
            float rv = (r1[0]*r2[0] + r1[1]*r2[1] + r1[2]*r2[2]) * (1.0f/14.0f);
            sv = silu_f(rv);
        }
        ((float*)xs4[n])[k*NSYM + i] = sv;
    }
    __syncthreads();

    u64 acc2[2][KK];

    // GEMM1: acc = base(center) + y1[neighbor] + Wsym^T . radial_sym
    {
        float base[2] = {be1[tj], be1[tj]};
        #pragma unroll 4
        for (int i4 = 0; i4 < 32; i4++) {
            int i = 4*i4;
            float w0 = We1[(i+0)*128+tj], w1 = We1[(i+1)*128+tj];
            float w2 = We1[(i+2)*128+tj], w3 = We1[(i+3)*128+tj];
            #pragma unroll
            for (int n = 0; n < 2; n++) {
                float4 a = shc4[n][i4];
                base[n] += a.x*w0 + a.y*w1 + a.z*w2 + a.w*w3;
            }
        }
        #pragma unroll
        for (int n = 0; n < 2; n++)
            #pragma unroll
            for (int k = 0; k < KK; k++) {
                float y1v = g_y1[(b*NN + nbr[n][k])*128 + tj];
                acc2[n][k] = pack2(base[n] + y1v, 0.0f);
            }
        #pragma unroll 3
        for (int i4 = 0; i4 < 27; i4++) {
            int ib = 4*i4;
            u64 wA = pack2(g_wsym[(ib+0)*128+tj], g_wsym[(ib+1)*128+tj]);
            u64 wB = pack2(g_wsym[(ib+2)*128+tj], g_wsym[(ib+3)*128+tj]);
            #pragma unroll
            for (int n = 0; n < 2; n++) {
                const ulonglong2* xr = reinterpret_cast<const ulonglong2*>(xs4[n]);
                #pragma unroll
                for (int k = 0; k < KK; k++) {
                    ulonglong2 a = xr[k*27 + i4];   // float off k*108+4*i4
                    fma2(acc2[n][k], a.x, wA);
                    fma2(acc2[n][k], a.y, wB);
                }
            }
        }
        #pragma unroll
        for (int n = 0; n < 2; n++)
            #pragma unroll
            for (int k = 0; k < KK; k++)
                ((float*)&sh14[n][k*32])[tj] = silu_f(hsum2(acc2[n][k]));
    }
    __syncthreads();

    // GEMM2: m = silu(h1) @ We2 + be2 ; smsum -> global (sm4 aliases dead xs4)
    {
        float bv = be2[tj];
        #pragma unroll
        for (int n = 0; n < 2; n++)
            #pragma unroll
            for (int k = 0; k < KK; k++) acc2[n][k] = pack2(bv, 0.0f);
        #pragma unroll 2
        for (int i4 = 0; i4 < 32; i4++) {
            int i = 4*i4;
            u64 wA = pack2(We2[(i+0)*128+tj], We2[(i+1)*128+tj]);
            u64 wB = pack2(We2[(i+2)*128+tj], We2[(i+3)*128+tj]);
            #pragma unroll
            for (int n = 0; n < 2; n++) {
                #pragma unroll
                for (int k = 0; k < KK; k++) {
                    ulonglong2 a = *reinterpret_cast<const ulonglong2*>(&sh14[n][k*32 + i4]);
                    fma2(acc2[n][k], a.x, wA);
                    fma2(acc2[n][k], a.y, wB);
                }
            }
        }
        #pragma unroll
        for (int n = 0; n < 2; n++) {
            float msv = 0.0f;
            #pragma unroll
            for (int k = 0; k < KK; k++) {
                float mv = hsum2(acc2[n][k]);
                msv += mv;
                SM4F(n,k)[tj] = silu_f(mv);
            }
            g_smsum[(node0+n)*128 + tj] = silu_f(msv);
        }
    }
    __syncthreads();

    // GEMM3: h2 = silu(m) @ Wx1 + bx1 ; sbuf = silu(h2)*Wx2 (alias over sh14, now dead)
    {
        float bv = bx1[tj];
        #pragma unroll
        for (int n = 0; n < 2; n++)
            #pragma unroll
            for (int k = 0; k < KK; k++) acc2[n][k] = pack2(bv, 0.0f);
        #pragma unroll 2
        for (int i4 = 0; i4 < 32; i4++) {
            int i = 4*i4;
            u64 wA = pack2(Wx1[(i+0)*128+tj], Wx1[(i+1)*128+tj]);
            u64 wB = pack2(Wx1[(i+2)*128+tj], Wx1[(i+3)*128+tj]);
            #pragma unroll
            for (int n = 0; n < 2; n++) {
                #pragma unroll
                for (int k = 0; k < KK; k++) {
                    ulonglong2 a = *reinterpret_cast<const ulonglong2*>(&SM4(n,k,i4));
                    fma2(acc2[n][k], a.x, wA);
                    fma2(acc2[n][k], a.y, wB);
                }
            }
        }
        float wxv = wx2s[tj];
        __syncthreads();   // ensure all sh14 (silu(h1)) reads from GEMM2 are done block-wide
        #pragma unroll
        for (int n = 0; n < 2; n++)
            #pragma unroll
            for (int k = 0; k < KK; k++)
                SBUF4F(n,k)[tj] = silu_f(hsum2(acc2[n][k])) * wxv;
    }
    __syncthreads();

    if (tj < 2*KK) {
        int n = tj/KK, k = tj%KK;
        float4 s4 = make_float4(0.f,0.f,0.f,0.f);
        #pragma unroll 8
        for (int i4 = 0; i4 < 32; i4++) {
            float4 v = SBUF4(n,k,i4);
            s4.x += v.x; s4.y += v.y; s4.z += v.z; s4.w += v.w;
        }
        wk[n][k] = bx2[0] + s4.x + s4.y + s4.z + s4.w;
    }
    __syncthreads();

    // X_out = X + mean_k(rel * w)
    if (tj < 84) {
        int n = tj/42, i = tj%42;
        float s = 0.0f;
        #pragma unroll
        for (int k = 0; k < KK; k++) s += relb[n][k][i]*wk[n][k];
        out[XOFF + (node0+n)*42 + i] = xcen[n][i] + s*(1.0f/9.0f);
    }
    #undef SM4
    #undef SM4F
    #undef SBUF4
    #undef SBUF4F
}

// ---------------- K3b: node-level GEMVs, 8 nodes/block (4x weight reuse) ----------
// Hn = Hh + FFN([Hh, smsum]); gate; logits; yT/yB.
#define NB 8
__global__ __launch_bounds__(128) void k_node(
    const int* __restrict__ S, const float* __restrict__ emb,
    const float* __restrict__ Wh1, const float* __restrict__ bh1,
    const float* __restrict__ Wh2, const float* __restrict__ bh2,
    const float* __restrict__ Wd1,
    const float* __restrict__ Wp1, const float* __restrict__ bp1,
    const float* __restrict__ Wr1, const float* __restrict__ br1,
    const float* __restrict__ Wr2, const float* __restrict__ br2,
    float* __restrict__ out)
{
    int node0 = NB*blockIdx.x;
    int tj = threadIdx.x;

    __shared__ float4 shc4[NB][32];   // silu(Hh)
    __shared__ float  hcr[NB][128];   // raw Hh
    __shared__ float4 sms4[NB][32];   // silu(sum_k m)
    __shared__ float4 snn4[NB][32];   // silu(Hn)
    __shared__ float4 sx04[NB][32];   // silu(H0*gate)
    __shared__ float4 tmpv4[NB][32];

    #pragma unroll
    for (int n = 0; n < NB; n++) {
        ((float*)shc4[n])[tj] = g_sHh[(node0+n)*128 + tj];
        hcr[n][tj] = g_Hh[(node0+n)*128 + tj];
        ((float*)sms4[n])[tj] = g_smsum[(node0+n)*128 + tj];
    }
    __syncthreads();

    u64 acc2[NB];

    // h = silu(Wh1^T [shc; sms] + bh1)
    {
        float bv = bh1[tj];
        #pragma unroll
        for (int n = 0; n < NB; n++) acc2[n] = pack2(bv, 0.0f);
        #pragma unroll 2
        for (int i4 = 0; i4 < 32; i4++) {
            int i = 4*i4;
            u64 wA = pack2(Wh1[(i+0)*128+tj], Wh1[(i+1)*128+tj]);
            u64 wB = pack2(Wh1[(i+2)*128+tj], Wh1[(i+3)*128+tj]);
            #pragma unroll
            for (int n = 0; n < NB; n++) {
                ulonglong2 a = *reinterpret_cast<const ulonglong2*>(&shc4[n][i4]);
                fma2(acc2[n], a.x, wA);
                fma2(acc2[n], a.y, wB);
            }
        }
        #pragma unroll 2
        for (int i4 = 0; i4 < 32; i4++) {
            int i = 128 + 4*i4;
            u64 wA = pack2(Wh1[(i+0)*128+tj], Wh1[(i+1)*128+tj]);
            u64 wB = pack2(Wh1[(i+2)*128+tj], Wh1[(i+3)*128+tj]);
            #pragma unroll
            for (int n = 0; n < NB; n++) {
                ulonglong2 a = *reinterpret_cast<const ulonglong2*>(&sms4[n][i4]);
                fma2(acc2[n], a.x, wA);
                fma2(acc2[n], a.y, wB);
            }
        }
        #pragma unroll
        for (int n = 0; n < NB; n++) ((float*)tmpv4[n])[tj] = silu_f(hsum2(acc2[n]));
    }
    __syncthreads();

    // Hn = Hh + Wh2^T h + bh2 ; snn = silu(Hn)
    {
        float bv = bh2[tj];
        #pragma unroll
        for (int n = 0; n < NB; n++) acc2[n] = pack2(hcr[n][tj] + bv, 0.0f);
        #pragma unroll 2
        for (int i4 = 0; i4 < 32; i4++) {
            int i = 4*i4;
            u64 wA = pack2(Wh2[(i+0)*128+tj], Wh2[(i+1)*128+tj]);
            u64 wB = pack2(Wh2[(i+2)*128+tj], Wh2[(i+3)*128+tj]);
            #pragma unroll
            for (int n = 0; n < NB; n++) {
                ulonglong2 a = *reinterpret_cast<const ulonglong2*>(&tmpv4[n][i4]);
                fma2(acc2[n], a.x, wA);
                fma2(acc2[n], a.y, wB);
            }
        }
        #pragma unroll
        for (int n = 0; n < NB; n++) {
            float shn = silu_f(hsum2(acc2[n]));
            g_sHn[(node0+n)*128 + tj] = shn;
            ((float*)snn4[n])[tj] = shn;
        }
    }
    __syncthreads();

    // gate = sigmoid(Wp1^T snn + bp1) ; sx0 = silu(H0*gate)
    {
        float bv = bp1[tj];
        #pragma unroll
        for (int n = 0; n < NB; n++) acc2[n] = pack2(bv, 0.0f);
        #pragma unroll 2
        for (int i4 = 0; i4 < 32; i4++) {
            int i = 4*i4;
            u64 wA = pack2(Wp1[(i+0)*128+tj], Wp1[(i+1)*128+tj]);
            u64 wB = pack2(Wp1[(i+2)*128+tj], Wp1[(i+3)*128+tj]);
            #pragma unroll
            for (int n = 0; n < NB; n++) {
                ulonglong2 a = *reinterpret_cast<const ulonglong2*>(&snn4[n][i4]);
                fma2(acc2[n], a.x, wA);
                fma2(acc2[n], a.y, wB);
            }
        }
        #pragma unroll
        for (int n = 0; n < NB; n++) {
            float gate = sigm_f(hsum2(acc2[n]));
            float h0 = emb[S[node0+n]*128 + tj];
            ((float*)sx04[n])[tj] = silu_f(h0*gate);
        }
    }

    // yT/yB = Wd1_top^T snn, Wd1_bot^T snn (snn already synced)
    {
        u64 aT[NB], aB[NB];
        #pragma unroll
        for (int n = 0; n < NB; n++){ aT[n] = 0ULL; aB[n] = 0ULL; }
        #pragma unroll 2
        for (int i4 = 0; i4 < 32; i4++) {
            int i = 4*i4;
            u64 t1 = pack2(Wd1[(i+0)*128+tj],     Wd1[(i+1)*128+tj]);
            u64 t2 = pack2(Wd1[(i+2)*128+tj],     Wd1[(i+3)*128+tj]);
            u64 b1 = pack2(Wd1[(128+i+0)*128+tj], Wd1[(128+i+1)*128+tj]);
            u64 b2 = pack2(Wd1[(128+i+2)*128+tj], Wd1[(128+i+3)*128+tj]);
            #pragma unroll
            for (int n = 0; n < NB; n++) {
                ulonglong2 a = *reinterpret_cast<const ulonglong2*>(&snn4[n][i4]);
                fma2(aT[n], a.x, t1); fma2(aT[n], a.y, t2);
                fma2(aB[n], a.x, b1); fma2(aB[n], a.y, b2);
            }
        }
        #pragma unroll
        for (int n = 0; n < NB; n++) {
            g_yT[(node0+n)*128+tj] = hsum2(aT[n]);
            g_yB[(node0+n)*128+tj] = hsum2(aB[n]);
        }
    }
    __syncthreads();

    // r1 = silu(Wr1^T sx0 + br1)
    {
        float bv = br1[tj];
        #pragma unroll
        for (int n = 0; n < NB; n++) acc2[n] = pack2(bv, 0.0f);
        #pragma unroll 2
        for (int i4 = 0; i4 < 32; i4++) {
            int i = 4*i4;
            u64 wA = pack2(Wr1[(i+0)*128+tj], Wr1[(i+1)*128+tj]);
            u64 wB = pack2(Wr1[(i+2)*128+tj], Wr1[(i+3)*128+tj]);
            #pragma unroll
            for (int n = 0; n < NB; n++) {
                ulonglong2 a = *reinterpret_cast<const ulonglong2*>(&sx04[n][i4]);
                fma2(acc2[n], a.x, wA);
                fma2(acc2[n], a.y, wB);
            }
        }
        #pragma unroll
        for (int n = 0; n < NB; n++) ((float*)tmpv4[n])[tj] = silu_f(hsum2(acc2[n]));
    }
    __syncthreads();

    // logits = Wr2^T r1 + br2
    if (tj < NCC) {
        float a[NB];
        float bv = br2[tj];
        #pragma unroll
        for (int n = 0; n < NB; n++) a[n] = bv;
        #pragma unroll 4
        for (int i4 = 0; i4 < 32; i4++) {
            int i = 4*i4;
            float w0 = Wr2[(i+0)*NCC+tj], w1 = Wr2[(i+1)*NCC+tj];
            float w2 = Wr2[(i+2)*NCC+tj], w3 = Wr2[(i+3)*NCC+tj];
            #pragma unroll
            for (int n = 0; n < NB; n++) {
                float4 h = tmpv4[n][i4];
                a[n] += h.x*w0 + h.y*w1 + h.z*w2 + h.w*w3;
            }
        }
        #pragma unroll
        for (int n = 0; n < NB; n++) out[(node0+n)*NCC + tj] = a[n];
    }
}

// ---------------- K4: pd — gather + silu + Wd2 dot (yT/yB precomputed) ----------
__global__ __launch_bounds__(128) void k_pd(
    const float* __restrict__ bd1,
    const float* __restrict__ Wd2, const float* __restrict__ bd2,
    float* __restrict__ out)
{
    int node0 = 2*blockIdx.x;
    int tj = threadIdx.x;
    int b = node0 >> 10;

    __shared__ float yTc[2][128], yBc[2][128];
    __shared__ int   nbr[2][KK];
    __shared__ float4 sAB4[2][KK][32];

    #pragma unroll
    for (int n = 0; n < 2; n++) {
        yTc[n][tj] = g_yT[(node0+n)*128 + tj];
        yBc[n][tj] = g_yB[(node0+n)*128 + tj];
    }
    if (tj < 2*KK) { int n = tj/KK, k = tj%KK; nbr[n][k] = g_idx[(node0+n)*KK + k]; }
    __syncthreads();

    float bd1v = bd1[tj];
    float wd2v = Wd2[tj];
    #pragma unroll
    for (int n = 0; n < 2; n++) {
        float ytc = yTc[n][tj] + bd1v;
        float ybc = yBc[n][tj] + bd1v;
        #pragma unroll
        for (int k = 0; k < KK; k++) {
            int d = (b*NN + nbr[n][k])*128 + tj;
            float aA = ytc + g_yB[d];     // [Hs,Hd]: top.hc + bot.hd + bd1
            float aB = g_yT[d] + ybc;     // [Hd,Hs]: top.hd + bot.hc + bd1
            ((float*)sAB4[n][k])[tj] = (silu_f(aA) + silu_f(aB)) * wd2v;
        }
    }
    __syncthreads();
    if (tj < 2*KK) {
        int n = tj/KK, k = tj%KK;
        float4 s4 = make_float4(0.f,0.f,0.f,0.f);
        #pragma unroll 8
        for (int i4 = 0; i4 < 32; i4++) {
            float4 v = sAB4[n][k][i4];
            s4.x += v.x; s4.y += v.y; s4.z += v.z; s4.w += v.w;
        }
        out[POFF + (node0+n)*KK + k] = 2.0f*bd2[0] + s4.x + s4.y + s4.z + s4.w;
    }
}

// ---------------- launcher ----------------
extern "C" void kernel_launch(void* const* d_in, const int* in_sizes, int n_in,
                              void* d_out, int out_size)
{
    const float* X   = (const float*)d_in[0];
    const int*   S   = (const int*)  d_in[1];
    const float* t   = (const float*)d_in[2];
    const float* emb = (const float*)d_in[3];
    const float* Wt1 = (const float*)d_in[4];
    const float* bt1 = (const float*)d_in[5];
    const float* Wt2 = (const float*)d_in[6];
    const float* bt2 = (const float*)d_in[7];
    const float* We1 = (const float*)d_in[8];
    const float* be1 = (const float*)d_in[9];
    const float* We2 = (const float*)d_in[10];
    const float* be2 = (const float*)d_in[11];
    const float* Wx1 = (const float*)d_in[12];
    const float* bx1 = (const float*)d_in[13];
    const float* Wx2 = (const float*)d_in[14];
    const float* bx2 = (const float*)d_in[15];
    const float* Wh1 = (const float*)d_in[16];
    const float* bh1 = (const float*)d_in[17];
    const float* Wh2 = (const float*)d_in[18];
    const float* bh2 = (const float*)d_in[19];
    const float* Wd1 = (const float*)d_in[20];
    const float* bd1 = (const float*)d_in[21];
    const float* Wd2 = (const float*)d_in[22];
    const float* bd2 = (const float*)d_in[23];
    const float* Wp1 = (const float*)d_in[24];
    const float* bp1 = (const float*)d_in[25];
    const float* Wr1 = (const float*)d_in[26];
    const float* br1 = (const float*)d_in[27];
    const float* Wr2 = (const float*)d_in[28];
    const float* br2 = (const float*)d_in[29];
    float* out = (float*)d_out;

    k_wsym<<<NSYM, 128>>>(We1);
    k_hh<<<NODES/2, 128>>>(t, S, emb, Wt1, bt1, Wt2, bt2, We1);
    k_knn<<<BB*(NN/128), 128>>>(X);
    k_edge<<<NODES/2, 128>>>(X,
                             We1, be1, We2, be2,
                             Wx1, bx1, Wx2, bx2,
                             out);
    k_node<<<NODES/NB, 128>>>(S, emb,
                              Wh1, bh1, Wh2, bh2,
                              Wd1,
                              Wp1, bp1, Wr1, br1, Wr2, br2,
                              out);
    k_pd<<<NODES/2, 128>>>(bd1, Wd2, bd2, out);
}

// round 15
// speedup vs baseline: 2.9721x; 1.0786x over previous
#include <cuda_runtime.h>
#include <math.h>

#define BB 32
#define NN 1024
#define CC 14
#define KK 9
#define EE 128
#define HH 128
#define NCC 25
#define NODES (BB*NN)

// output layout: logits (B,N,25) | X_out (B,N,14,3) | pd (B,N,9)
#define L_SZ (NODES*NCC)
#define X_SZ (NODES*CC*3)
#define XOFF L_SZ
#define POFF (L_SZ + X_SZ)

#define NSYM 108   // 14 diag + 91 off-diag unique Gram entries, padded to 108 (27 float4)

typedef unsigned long long u64;

// scratch (allowed: __device__ globals, no runtime alloc)
__device__ float g_Hh[NODES*EE];     // raw Hh
__device__ float g_sHh[NODES*EE];    // silu(Hh)
__device__ float g_y1[NODES*EE];     // We1[128:256]^T . silu(Hh[n])
__device__ float g_smsum[NODES*EE];  // silu(sum_k m)
__device__ float g_sHn[NODES*EE];    // silu(Hn)
__device__ float g_yT[NODES*EE];     // Wd1[0:128]^T   . silu(Hn[n])
__device__ float g_yB[NODES*EE];     // Wd1[128:256]^T . silu(Hn[n])
__device__ float g_wsym[NSYM*EE];    // symmetric-folded We1 radial rows
__device__ int   g_idx[NODES*KK];

// off-diagonal pair enumeration (c<e), 91 pairs
__device__ __constant__ unsigned char d_pc[91] = {
    0,0,0,0,0,0,0,0,0,0,0,0,0,
    1,1,1,1,1,1,1,1,1,1,1,1,
    2,2,2,2,2,2,2,2,2,2,2,
    3,3,3,3,3,3,3,3,3,3,
    4,4,4,4,4,4,4,4,4,
    5,5,5,5,5,5,5,5,
    6,6,6,6,6,6,6,
    7,7,7,7,7,7,
    8,8,8,8,8,
    9,9,9,9,
    10,10,10,
    11,11,
    12};
__device__ __constant__ unsigned char d_pe[91] = {
    1,2,3,4,5,6,7,8,9,10,11,12,13,
    2,3,4,5,6,7,8,9,10,11,12,13,
    3,4,5,6,7,8,9,10,11,12,13,
    4,5,6,7,8,9,10,11,12,13,
    5,6,7,8,9,10,11,12,13,
    6,7,8,9,10,11,12,13,
    7,8,9,10,11,12,13,
    8,9,10,11,12,13,
    9,10,11,12,13,
    10,11,12,13,
    11,12,13,
    12,13,
    13};

// fast transcendentals: MUFU.EX2 + MUFU.RCP (~2^-21 rel err; budget is 1e-3)
__device__ __forceinline__ float silu_f(float x){ return __fdividef(x, 1.0f + __expf(-x)); }
__device__ __forceinline__ float sigm_f(float x){ return __fdividef(1.0f, 1.0f + __expf(-x)); }

// ---- packed fp32 (Blackwell FFMA2; PTX-only) ----
__device__ __forceinline__ u64 pack2(float lo, float hi){
    u64 r;
    asm("mov.b64 %0, {%1, %2};" : "=l"(r) : "r"(__float_as_uint(lo)), "r"(__float_as_uint(hi)));
    return r;
}
__device__ __forceinline__ void fma2(u64 &d, u64 a, u64 b){
    asm("fma.rn.f32x2 %0, %1, %2, %0;" : "+l"(d) : "l"(a), "l"(b));
}
__device__ __forceinline__ float hsum2(u64 v){
    unsigned lo, hi;
    asm("mov.b64 {%0, %1}, %2;" : "=r"(lo), "=r"(hi) : "l"(v));
    return __uint_as_float(lo) + __uint_as_float(hi);
}

// ---------------- K0: fold We1 radial rows by Gram symmetry ----------------
__global__ __launch_bounds__(128) void k_wsym(const float* __restrict__ We1)
{
    int u = blockIdx.x;        // feature row 0..NSYM-1 (uniform per block: no divergent LDC)
    int tj = threadIdx.x;
    float v;
    if (u < 14) {
        v = We1[(256 + u*14 + u)*128 + tj];
    } else if (u < 105) {
        int p = u - 14;
        int c = d_pc[p], e = d_pe[p];
        v = We1[(256 + c*14 + e)*128 + tj] + We1[(256 + e*14 + c)*128 + tj];
    } else {
        v = 0.0f;
    }
    g_wsym[u*128 + tj] = v;
}

// ---------------- K1: Hh = emb[S] + time_emb(t) ; y1 = We1_mid^T silu(Hh). 2 nodes/block ----
__global__ __launch_bounds__(128) void k_hh(
    const float* __restrict__ t, const int* __restrict__ S,
    const float* __restrict__ emb,
    const float* __restrict__ Wt1, const float* __restrict__ bt1,
    const float* __restrict__ Wt2, const float* __restrict__ bt2,
    const float* __restrict__ We1)
{
    int node0 = 2*blockIdx.x;
    int j = threadIdx.x;
    __shared__ float4 g4[2][32], h4[2][32], ssh[2][32];
    #pragma unroll
    for (int n = 0; n < 2; n++) {
        float tv = t[node0+n];
        float d = tv - (float)j*(1.0f/127.0f) + 1e-6f;
        ((float*)g4[n])[j] = expf(-8064.5f*d*d);   // precise exp (large args)
    }
    __syncthreads();
    float a[2] = {bt1[j], bt1[j]};
    #pragma unroll 4
    for (int i4 = 0; i4 < 32; i4++) {
        int i = 4*i4;
        float w0 = Wt1[(i+0)*128+j], w1 = Wt1[(i+1)*128+j];
        float w2 = Wt1[(i+2)*128+j], w3 = Wt1[(i+3)*128+j];
        #pragma unroll
        for (int n = 0; n < 2; n++) {
            float4 g = g4[n][i4];
            a[n] += g.x*w0 + g.y*w1 + g.z*w2 + g.w*w3;
        }
    }
    #pragma unroll
    for (int n = 0; n < 2; n++) ((float*)h4[n])[j] = fmaxf(a[n], 0.0f);
    __syncthreads();
    float a2[2] = {bt2[j], bt2[j]};
    #pragma unroll 4
    for (int i4 = 0; i4 < 32; i4++) {
        int i = 4*i4;
        float w0 = Wt2[(i+0)*128+j], w1 = Wt2[(i+1)*128+j];
        float w2 = Wt2[(i+2)*128+j], w3 = Wt2[(i+3)*128+j];
        #pragma unroll
        for (int n = 0; n < 2; n++) {
            float4 h = h4[n][i4];
            a2[n] += h.x*w0 + h.y*w1 + h.z*w2 + h.w*w3;
        }
    }
    #pragma unroll
    for (int n = 0; n < 2; n++) {
        float hv = emb[S[node0+n]*128+j] + a2[n];
        float sh = silu_f(hv);
        g_Hh[(node0+n)*128+j]  = hv;
        g_sHh[(node0+n)*128+j] = sh;
        ((float*)ssh[n])[j] = sh;
    }
    __syncthreads();
    // y1 = We1 rows [128,256) ^T . silu(Hh)
    float y[2] = {0.0f, 0.0f};
    #pragma unroll 4
    for (int i4 = 0; i4 < 32; i4++) {
        int i = 128 + 4*i4;
        float w0 = We1[(i+0)*128+j], w1 = We1[(i+1)*128+j];
        float w2 = We1[(i+2)*128+j], w3 = We1[(i+3)*128+j];
        #pragma unroll
        for (int n = 0; n < 2; n++) {
            float4 s = ssh[n][i4];
            y[n] += s.x*w0 + s.y*w1 + s.z*w2 + s.w*w3;
        }
    }
    #pragma unroll
    for (int n = 0; n < 2; n++) g_y1[(node0+n)*128+j] = y[n];
}

// ---------------- K2: top-9 nearest neighbors on ca = X[:,:,1,:] ----------------
__global__ __launch_bounds__(128) void k_knn(const float* __restrict__ X)
{
    __shared__ float sca[NN*3];
    int b = blockIdx.x >> 3;
    int tile = blockIdx.x & 7;
    int tj = threadIdx.x;
    for (int u = tj; u < NN*3; u += 128) {
        int n = u/3, d = u - n*3;
        sca[u] = X[((b*NN + n)*CC + 1)*3 + d];
    }
    __syncthreads();
    int n = tile*128 + tj;
    float qx = sca[n*3+0], qy = sca[n*3+1], qz = sca[n*3+2];
    float bd[KK]; int bi[KK];
    #pragma unroll
    for (int i = 0; i < KK; i++){ bd[i] = 1e30f; bi[i] = 0; }
    for (int j = 0; j < NN; j++) {
        float dx = qx - sca[j*3+0];
        float dy = qy - sca[j*3+1];
        float dz = qz - sca[j*3+2];
        float d = dx*dx + dy*dy + dz*dz;
        if (j == n) d = 1e30f;
        if (d < bd[KK-1]) {                  // strict <: stable tie order
            bd[KK-1] = d; bi[KK-1] = j;
            #pragma unroll
            for (int q = KK-1; q > 0; q--) {
                if (bd[q] < bd[q-1]) {
                    float td = bd[q]; bd[q] = bd[q-1]; bd[q-1] = td;
                    int   ti = bi[q]; bi[q] = bi[q-1]; bi[q-1] = ti;
                }
            }
        }
    }
    #pragma unroll
    for (int k = 0; k < KK; k++) g_idx[(b*NN + n)*KK + k] = bi[k];
}

// ---------------- K3: edge GEMMs + X_out + smsum, 2 nodes/block ----------
// xs4 holds compact symmetric radial features (108 floats = 27 float4 per edge).
// Aliases: sm4 (silu(m)) lives in xs4 (dead after GEMM1); sbuf lives in sh14 (dead after GEMM2).
// Gram pair table lives in SMEM (per-lane divergent __constant__ access serializes; smem doesn't).
__global__ __launch_bounds__(128) void k_edge(
    const float* __restrict__ X,
    const float* __restrict__ We1, const float* __restrict__ be1,
    const float* __restrict__ We2, const float* __restrict__ be2,
    const float* __restrict__ Wx1, const float* __restrict__ bx1,
    const float* __restrict__ Wx2, const float* __restrict__ bx2,
    float* __restrict__ out)
{
    int node0 = 2*blockIdx.x;
    int tj = threadIdx.x;
    int b = node0 >> 10;

    __shared__ float4 xs4[2][288];     // radial (9 x 27 = 243 used) ; aliased by sm4 after GEMM1
    __shared__ float4 sh14[2][288];    // silu(h1): 9x128 ; aliased by sbuf after GEMM2
    __shared__ float  relb[2][KK][42];
    __shared__ float4 shc4[2][32];
    __shared__ float  xcen[2][42];
    __shared__ int    nbr[2][KK];
    __shared__ float  wk[2][KK];
    __shared__ float  wx2s[128];
    __shared__ uchar2 spair[91];       // (c*3, e*3) Gram pair table in smem

    #define SM4(n,k,i4)    xs4[n][(k)*32+(i4)]     // alias: valid after GEMM1
    #define SM4F(n,k)      ((float*)&xs4[n][(k)*32])
    #define SBUF4(n,k,i4)  sh14[n][(k)*32+(i4)]    // alias: valid after GEMM2
    #define SBUF4F(n,k)    ((float*)&sh14[n][(k)*32])

    {
        #pragma unroll
        for (int n = 0; n < 2; n++)
            ((float*)shc4[n])[tj] = g_sHh[(node0+n)*128 + tj];
        wx2s[tj] = Wx2[tj];
        if (tj < 84) { int n = tj/42, i = tj%42; xcen[n][i] = X[(node0+n)*CC*3 + i]; }
        if (tj < 2*KK) { int n = tj/KK, k = tj%KK; nbr[n][k] = g_idx[(node0+n)*KK + k]; }
        if (tj < 91) spair[tj] = make_uchar2((unsigned char)(d_pc[tj]*3),
                                             (unsigned char)(d_pe[tj]*3));
    }
    __syncthreads();

    // rel vectors
    for (int u = tj; u < 2*KK*42; u += 128) {
        int idx = u/42, i = u - idx*42;
        int n = idx/KK, k = idx%KK;
        relb[n][k][i] = xcen[n][i] - X[(b*NN + nbr[n][k])*CC*3 + i];
    }
    __syncthreads();

    // symmetric radial: 14 diag + 91 unique off-diag, silu'd; layout k*108+i
    for (int u = tj; u < 2*KK*NSYM; u += 128) {
        int idx = u/NSYM, i = u - idx*NSYM;
        int n = idx/KK, k = idx%KK;
        float sv = 0.0f;
        if (i < 105) {
            int c3, e3;
            if (i < 14) { c3 = i*3; e3 = c3; }
            else { uchar2 pr = spair[i-14]; c3 = pr.x; e3 = pr.y; }
            const float* r1 = &relb[n][k][c3];
            const float* r2 = &relb[n][k][e3];
            float rv = (r1[0]*r2[0] + r1[1]*r2[1] + r1[2]*r2[2]) * (1.0f/14.0f);
            sv = silu_f(rv);
        }
        ((float*)xs4[n])[k*NSYM + i] = sv;
    }
    __syncthreads();

    u64 acc2[2][KK];

    // GEMM1: acc = base(center) + y1[neighbor] + Wsym^T . radial_sym
    {
        float base[2] = {be1[tj], be1[tj]};
        #pragma unroll 4
        for (int i4 = 0; i4 < 32; i4++) {
            int i = 4*i4;
            float w0 = We1[(i+0)*128+tj], w1 = We1[(i+1)*128+tj];
            float w2 = We1[(i+2)*128+tj], w3 = We1[(i+3)*128+tj];
            #pragma unroll
            for (int n = 0; n < 2; n++) {
                float4 a = shc4[n][i4];
                base[n] += a.x*w0 + a.y*w1 + a.z*w2 + a.w*w3;
            }
        }
        #pragma unroll
        for (int n = 0; n < 2; n++)
            #pragma unroll
            for (int k = 0; k < KK; k++) {
                float y1v = g_y1[(b*NN + nbr[n][k])*128 + tj];
                acc2[n][k] = pack2(base[n] + y1v, 0.0f);
            }
        #pragma unroll 3
        for (int i4 = 0; i4 < 27; i4++) {
            int ib = 4*i4;
            u64 wA = pack2(g_wsym[(ib+0)*128+tj], g_wsym[(ib+1)*128+tj]);
            u64 wB = pack2(g_wsym[(ib+2)*128+tj], g_wsym[(ib+3)*128+tj]);
            #pragma unroll
            for (int n = 0; n < 2; n++) {
                const ulonglong2* xr = reinterpret_cast<const ulonglong2*>(xs4[n]);
                #pragma unroll
                for (int k = 0; k < KK; k++) {
                    ulonglong2 a = xr[k*27 + i4];   // float off k*108+4*i4
                    fma2(acc2[n][k], a.x, wA);
                    fma2(acc2[n][k], a.y, wB);
                }
            }
        }
        #pragma unroll
        for (int n = 0; n < 2; n++)
            #pragma unroll
            for (int k = 0; k < KK; k++)
                ((float*)&sh14[n][k*32])[tj] = silu_f(hsum2(acc2[n][k]));
    }
    __syncthreads();

    // GEMM2: m = silu(h1) @ We2 + be2 ; smsum -> global (sm4 aliases dead xs4)
    {
        float bv = be2[tj];
        #pragma unroll
        for (int n = 0; n < 2; n++)
            #pragma unroll
            for (int k = 0; k < KK; k++) acc2[n][k] = pack2(bv, 0.0f);
        #pragma unroll 4
        for (int i4 = 0; i4 < 32; i4++) {
            int i = 4*i4;
            u64 wA = pack2(We2[(i+0)*128+tj], We2[(i+1)*128+tj]);
            u64 wB = pack2(We2[(i+2)*128+tj], We2[(i+3)*128+tj]);
            #pragma unroll
            for (int n = 0; n < 2; n++) {
                #pragma unroll
                for (int k = 0; k < KK; k++) {
                    ulonglong2 a = *reinterpret_cast<const ulonglong2*>(&sh14[n][k*32 + i4]);
                    fma2(acc2[n][k], a.x, wA);
                    fma2(acc2[n][k], a.y, wB);
                }
            }
        }
        #pragma unroll
        for (int n = 0; n < 2; n++) {
            float msv = 0.0f;
            #pragma unroll
            for (int k = 0; k < KK; k++) {
                float mv = hsum2(acc2[n][k]);
                msv += mv;
                SM4F(n,k)[tj] = silu_f(mv);
            }
            g_smsum[(node0+n)*128 + tj] = silu_f(msv);
        }
    }
    __syncthreads();

    // GEMM3: h2 = silu(m) @ Wx1 + bx1 ; sbuf = silu(h2)*Wx2 (alias over sh14, now dead)
    {
        float bv = bx1[tj];
        #pragma unroll
        for (int n = 0; n < 2; n++)
            #pragma unroll
            for (int k = 0; k < KK; k++) acc2[n][k] = pack2(bv, 0.0f);
        #pragma unroll 4
        for (int i4 = 0; i4 < 32; i4++) {
            int i = 4*i4;
            u64 wA = pack2(Wx1[(i+0)*128+tj], Wx1[(i+1)*128+tj]);
            u64 wB = pack2(Wx1[(i+2)*128+tj], Wx1[(i+3)*128+tj]);
            #pragma unroll
            for (int n = 0; n < 2; n++) {
                #pragma unroll
                for (int k = 0; k < KK; k++) {
                    ulonglong2 a = *reinterpret_cast<const ulonglong2*>(&SM4(n,k,i4));
                    fma2(acc2[n][k], a.x, wA);
                    fma2(acc2[n][k], a.y, wB);
                }
            }
        }
        float wxv = wx2s[tj];
        __syncthreads();   // ensure all sh14 (silu(h1)) reads from GEMM2 are done block-wide
        #pragma unroll
        for (int n = 0; n < 2; n++)
            #pragma unroll
            for (int k = 0; k < KK; k++)
                SBUF4F(n,k)[tj] = silu_f(hsum2(acc2[n][k])) * wxv;
    }
    __syncthreads();

    if (tj < 2*KK) {
        int n = tj/KK, k = tj%KK;
        float4 s4 = make_float4(0.f,0.f,0.f,0.f);
        #pragma unroll 8
        for (int i4 = 0; i4 < 32; i4++) {
            float4 v = SBUF4(n,k,i4);
            s4.x += v.x; s4.y += v.y; s4.z += v.z; s4.w += v.w;
        }
        wk[n][k] = bx2[0] + s4.x + s4.y + s4.z + s4.w;
    }
    __syncthreads();

    // X_out = X + mean_k(rel * w)
    if (tj < 84) {
        int n = tj/42, i = tj%42;
        float s = 0.0f;
        #pragma unroll
        for (int k = 0; k < KK; k++) s += relb[n][k][i]*wk[n][k];
        out[XOFF + (node0+n)*42 + i] = xcen[n][i] + s*(1.0f/9.0f);
    }
    #undef SM4
    #undef SM4F
    #undef SBUF4
    #undef SBUF4F
}

// ---------------- K3b: node-level GEMVs, 8 nodes/block (4x weight reuse) ----------
// Hn = Hh + FFN([Hh, smsum]); gate; logits; yT/yB.
#define NB 8
__global__ __launch_bounds__(128) void k_node(
    const int* __restrict__ S, const float* __restrict__ emb,
    const float* __restrict__ Wh1, const float* __restrict__ bh1,
    const float* __restrict__ Wh2, const float* __restrict__ bh2,
    const float* __restrict__ Wd1,
    const float* __restrict__ Wp1, const float* __restrict__ bp1,
    const float* __restrict__ Wr1, const float* __restrict__ br1,
    const float* __restrict__ Wr2, const float* __restrict__ br2,
    float* __restrict__ out)
{
    int node0 = NB*blockIdx.x;
    int tj = threadIdx.x;

    __shared__ float4 shc4[NB][32];   // silu(Hh)
    __shared__ float  hcr[NB][128];   // raw Hh
    __shared__ float4 sms4[NB][32];   // silu(sum_k m)
    __shared__ float4 snn4[NB][32];   // silu(Hn)
    __shared__ float4 sx04[NB][32];   // silu(H0*gate)
    __shared__ float4 tmpv4[NB][32];

    #pragma unroll
    for (int n = 0; n < NB; n++) {
        ((float*)shc4[n])[tj] = g_sHh[(node0+n)*128 + tj];
        hcr[n][tj] = g_Hh[(node0+n)*128 + tj];
        ((float*)sms4[n])[tj] = g_smsum[(node0+n)*128 + tj];
    }
    __syncthreads();

    u64 acc2[NB];

    // h = silu(Wh1^T [shc; sms] + bh1)
    {
        float bv = bh1[tj];
        #pragma unroll
        for (int n = 0; n < NB; n++) acc2[n] = pack2(bv, 0.0f);
        #pragma unroll 2
        for (int i4 = 0; i4 < 32; i4++) {
            int i = 4*i4;
            u64 wA = pack2(Wh1[(i+0)*128+tj], Wh1[(i+1)*128+tj]);
            u64 wB = pack2(Wh1[(i+2)*128+tj], Wh1[(i+3)*128+tj]);
            #pragma unroll
            for (int n = 0; n < NB; n++) {
                ulonglong2 a = *reinterpret_cast<const ulonglong2*>(&shc4[n][i4]);
                fma2(acc2[n], a.x, wA);
                fma2(acc2[n], a.y, wB);
            }
        }
        #pragma unroll 2
        for (int i4 = 0; i4 < 32; i4++) {
            int i = 128 + 4*i4;
            u64 wA = pack2(Wh1[(i+0)*128+tj], Wh1[(i+1)*128+tj]);
            u64 wB = pack2(Wh1[(i+2)*128+tj], Wh1[(i+3)*128+tj]);
            #pragma unroll
            for (int n = 0; n < NB; n++) {
                ulonglong2 a = *reinterpret_cast<const ulonglong2*>(&sms4[n][i4]);
                fma2(acc2[n], a.x, wA);
                fma2(acc2[n], a.y, wB);
            }
        }
        #pragma unroll
        for (int n = 0; n < NB; n++) ((float*)tmpv4[n])[tj] = silu_f(hsum2(acc2[n]));
    }
    __syncthreads();

    // Hn = Hh + Wh2^T h + bh2 ; snn = silu(Hn)
    {
        float bv = bh2[tj];
        #pragma unroll
        for (int n = 0; n < NB; n++) acc2[n] = pack2(hcr[n][tj] + bv, 0.0f);
        #pragma unroll 2
        for (int i4 = 0; i4 < 32; i4++) {
            int i = 4*i4;
            u64 wA = pack2(Wh2[(i+0)*128+tj], Wh2[(i+1)*128+tj]);
            u64 wB = pack2(Wh2[(i+2)*128+tj], Wh2[(i+3)*128+tj]);
            #pragma unroll
            for (int n = 0; n < NB; n++) {
                ulonglong2 a = *reinterpret_cast<const ulonglong2*>(&tmpv4[n][i4]);
                fma2(acc2[n], a.x, wA);
                fma2(acc2[n], a.y, wB);
            }
        }
        #pragma unroll
        for (int n = 0; n < NB; n++) {
            float shn = silu_f(hsum2(acc2[n]));
            g_sHn[(node0+n)*128 + tj] = shn;
            ((float*)snn4[n])[tj] = shn;
        }
    }
    __syncthreads();

    // gate = sigmoid(Wp1^T snn + bp1) ; sx0 = silu(H0*gate)
    {
        float bv = bp1[tj];
        #pragma unroll
        for (int n = 0; n < NB; n++) acc2[n] = pack2(bv, 0.0f);
        #pragma unroll 2
        for (int i4 = 0; i4 < 32; i4++) {
            int i = 4*i4;
            u64 wA = pack2(Wp1[(i+0)*128+tj], Wp1[(i+1)*128+tj]);
            u64 wB = pack2(Wp1[(i+2)*128+tj], Wp1[(i+3)*128+tj]);
            #pragma unroll
            for (int n = 0; n < NB; n++) {
                ulonglong2 a = *reinterpret_cast<const ulonglong2*>(&snn4[n][i4]);
                fma2(acc2[n], a.x, wA);
                fma2(acc2[n], a.y, wB);
            }
        }
        #pragma unroll
        for (int n = 0; n < NB; n++) {
            float gate = sigm_f(hsum2(acc2[n]));
            float h0 = emb[S[node0+n]*128 + tj];
            ((float*)sx04[n])[tj] = silu_f(h0*gate);
        }
    }

    // yT/yB = Wd1_top^T snn, Wd1_bot^T snn (snn already synced)
    {
        u64 aT[NB], aB[NB];
        #pragma unroll
        for (int n = 0; n < NB; n++){ aT[n] = 0ULL; aB[n] = 0ULL; }
        #pragma unroll 2
        for (int i4 = 0; i4 < 32; i4++) {
            int i = 4*i4;
            u64 t1 = pack2(Wd1[(i+0)*128+tj],     Wd1[(i+1)*128+tj]);
            u64 t2 = pack2(Wd1[(i+2)*128+tj],     Wd1[(i+3)*128+tj]);
            u64 b1 = pack2(Wd1[(128+i+0)*128+tj], Wd1[(128+i+1)*128+tj]);
            u64 b2 = pack2(Wd1[(128+i+2)*128+tj], Wd1[(128+i+3)*128+tj]);
            #pragma unroll
            for (int n = 0; n < NB; n++) {
                ulonglong2 a = *reinterpret_cast<const ulonglong2*>(&snn4[n][i4]);
                fma2(aT[n], a.x, t1); fma2(aT[n], a.y, t2);
                fma2(aB[n], a.x, b1); fma2(aB[n], a.y, b2);
            }
        }
        #pragma unroll
        for (int n = 0; n < NB; n++) {
            g_yT[(node0+n)*128+tj] = hsum2(aT[n]);
            g_yB[(node0+n)*128+tj] = hsum2(aB[n]);
        }
    }
    __syncthreads();

    // r1 = silu(Wr1^T sx0 + br1)
    {
        float bv = br1[tj];
        #pragma unroll
        for (int n = 0; n < NB; n++) acc2[n] = pack2(bv, 0.0f);
        #pragma unroll 2
        for (int i4 = 0; i4 < 32; i4++) {
            int i = 4*i4;
            u64 wA = pack2(Wr1[(i+0)*128+tj], Wr1[(i+1)*128+tj]);
            u64 wB = pack2(Wr1[(i+2)*128+tj], Wr1[(i+3)*128+tj]);
            #pragma unroll
            for (int n = 0; n < NB; n++) {
                ulonglong2 a = *reinterpret_cast<const ulonglong2*>(&sx04[n][i4]);
                fma2(acc2[n], a.x, wA);
                fma2(acc2[n], a.y, wB);
            }
        }
        #pragma unroll
        for (int n = 0; n < NB; n++) ((float*)tmpv4[n])[tj] = silu_f(hsum2(acc2[n]));
    }
    __syncthreads();

    // logits = Wr2^T r1 + br2
    if (tj < NCC) {
        float a[NB];
        float bv = br2[tj];
        #pragma unroll
        for (int n = 0; n < NB; n++) a[n] = bv;
        #pragma unroll 4
        for (int i4 = 0; i4 < 32; i4++) {
            int i = 4*i4;
            float w0 = Wr2[(i+0)*NCC+tj], w1 = Wr2[(i+1)*NCC+tj];
            float w2 = Wr2[(i+2)*NCC+tj], w3 = Wr2[(i+3)*NCC+tj];
            #pragma unroll
            for (int n = 0; n < NB; n++) {
                float4 h = tmpv4[n][i4];
                a[n] += h.x*w0 + h.y*w1 + h.z*w2 + h.w*w3;
            }
        }
        #pragma unroll
        for (int n = 0; n < NB; n++) out[(node0+n)*NCC + tj] = a[n];
    }
}

// ---------------- K4: pd — gather + silu + Wd2 dot (yT/yB precomputed) ----------
__global__ __launch_bounds__(128) void k_pd(
    const float* __restrict__ bd1,
    const float* __restrict__ Wd2, const float* __restrict__ bd2,
    float* __restrict__ out)
{
    int node0 = 2*blockIdx.x;
    int tj = threadIdx.x;
    int b = node0 >> 10;

    __shared__ float yTc[2][128], yBc[2][128];
    __shared__ int   nbr[2][KK];
    __shared__ float4 sAB4[2][KK][32];

    #pragma unroll
    for (int n = 0; n < 2; n++) {
        yTc[n][tj] = g_yT[(node0+n)*128 + tj];
        yBc[n][tj] = g_yB[(node0+n)*128 + tj];
    }
    if (tj < 2*KK) { int n = tj/KK, k = tj%KK; nbr[n][k] = g_idx[(node0+n)*KK + k]; }
    __syncthreads();

    float bd1v = bd1[tj];
    float wd2v = Wd2[tj];
    #pragma unroll
    for (int n = 0; n < 2; n++) {
        float ytc = yTc[n][tj] + bd1v;
        float ybc = yBc[n][tj] + bd1v;
        #pragma unroll
        for (int k = 0; k < KK; k++) {
            int d = (b*NN + nbr[n][k])*128 + tj;
            float aA = ytc + g_yB[d];     // [Hs,Hd]: top.hc + bot.hd + bd1
            float aB = g_yT[d] + ybc;     // [Hd,Hs]: top.hd + bot.hc + bd1
            ((float*)sAB4[n][k])[tj] = (silu_f(aA) + silu_f(aB)) * wd2v;
        }
    }
    __syncthreads();
    if (tj < 2*KK) {
        int n = tj/KK, k = tj%KK;
        float4 s4 = make_float4(0.f,0.f,0.f,0.f);
        #pragma unroll 8
        for (int i4 = 0; i4 < 32; i4++) {
            float4 v = sAB4[n][k][i4];
            s4.x += v.x; s4.y += v.y; s4.z += v.z; s4.w += v.w;
        }
        out[POFF + (node0+n)*KK + k] = 2.0f*bd2[0] + s4.x + s4.y + s4.z + s4.w;
    }
}

// ---------------- launcher ----------------
extern "C" void kernel_launch(void* const* d_in, const int* in_sizes, int n_in,
                              void* d_out, int out_size)
{
    const float* X   = (const float*)d_in[0];
    const int*   S   = (const int*)  d_in[1];
    const float* t   = (const float*)d_in[2];
    const float* emb = (const float*)d_in[3];
    const float* Wt1 = (const float*)d_in[4];
    const float* bt1 = (const float*)d_in[5];
    const float* Wt2 = (const float*)d_in[6];
    const float* bt2 = (const float*)d_in[7];
    const float* We1 = (const float*)d_in[8];
    const float* be1 = (const float*)d_in[9];
    const float* We2 = (const float*)d_in[10];
    const float* be2 = (const float*)d_in[11];
    const float* Wx1 = (const float*)d_in[12];
    const float* bx1 = (const float*)d_in[13];
    const float* Wx2 = (const float*)d_in[14];
    const float* bx2 = (const float*)d_in[15];
    const float* Wh1 = (const float*)d_in[16];
    const float* bh1 = (const float*)d_in[17];
    const float* Wh2 = (const float*)d_in[18];
    const float* bh2 = (const float*)d_in[19];
    const float* Wd1 = (const float*)d_in[20];
    const float* bd1 = (const float*)d_in[21];
    const float* Wd2 = (const float*)d_in[22];
    const float* bd2 = (const float*)d_in[23];
    const float* Wp1 = (const float*)d_in[24];
    const float* bp1 = (const float*)d_in[25];
    const float* Wr1 = (const float*)d_in[26];
    const float* br1 = (const float*)d_in[27];
    const float* Wr2 = (const float*)d_in[28];
    const float* br2 = (const float*)d_in[29];
    float* out = (float*)d_out;

    k_wsym<<<NSYM, 128>>>(We1);
    k_hh<<<NODES/2, 128>>>(t, S, emb, Wt1, bt1, Wt2, bt2, We1);
    k_knn<<<BB*(NN/128), 128>>>(X);
    k_edge<<<NODES/2, 128>>>(X,
                             We1, be1, We2, be2,
                             Wx1, bx1, Wx2, bx2,
                             out);
    k_node<<<NODES/NB, 128>>>(S, emb,
                              Wh1, bh1, Wh2, bh2,
                              Wd1,
                              Wp1, bp1, Wr1, br1, Wr2, br2,
                              out);
    k_pd<<<NODES/2, 128>>>(bd1, Wd2, bd2, out);
}

// round 16
// speedup vs baseline: 3.4266x; 1.1529x over previous
#include <cuda_runtime.h>
#include <math.h>

#define BB 32
#define NN 1024
#define CC 14
#define KK 9
#define EE 128
#define HH 128
#define NCC 25
#define NODES (BB*NN)

// output layout: logits (B,N,25) | X_out (B,N,14,3) | pd (B,N,9)
#define L_SZ (NODES*NCC)
#define X_SZ (NODES*CC*3)
#define XOFF L_SZ
#define POFF (L_SZ + X_SZ)

#define NSYM 108   // 14 diag + 91 off-diag unique Gram entries, padded to 108 (27 float4)

typedef unsigned long long u64;

// scratch (allowed: __device__ globals, no runtime alloc)
__device__ float g_Hh[NODES*EE];     // raw Hh
__device__ float g_sHh[NODES*EE];    // silu(Hh)
__device__ float g_y1[NODES*EE];     // We1[128:256]^T . silu(Hh[n])
__device__ float g_smsum[NODES*EE];  // silu(sum_k m)
__device__ float g_sHn[NODES*EE];    // silu(Hn)
__device__ float g_yT[NODES*EE];     // Wd1[0:128]^T   . silu(Hn[n])
__device__ float g_yB[NODES*EE];     // Wd1[128:256]^T . silu(Hn[n])
__device__ float g_wsym[NSYM*EE];    // symmetric-folded We1 radial rows
__device__ int   g_idx[NODES*KK];

// off-diagonal pair enumeration (c<e), 91 pairs
__device__ __constant__ unsigned char d_pc[91] = {
    0,0,0,0,0,0,0,0,0,0,0,0,0,
    1,1,1,1,1,1,1,1,1,1,1,1,
    2,2,2,2,2,2,2,2,2,2,2,
    3,3,3,3,3,3,3,3,3,3,
    4,4,4,4,4,4,4,4,4,
    5,5,5,5,5,5,5,5,
    6,6,6,6,6,6,6,
    7,7,7,7,7,7,
    8,8,8,8,8,
    9,9,9,9,
    10,10,10,
    11,11,
    12};
__device__ __constant__ unsigned char d_pe[91] = {
    1,2,3,4,5,6,7,8,9,10,11,12,13,
    2,3,4,5,6,7,8,9,10,11,12,13,
    3,4,5,6,7,8,9,10,11,12,13,
    4,5,6,7,8,9,10,11,12,13,
    5,6,7,8,9,10,11,12,13,
    6,7,8,9,10,11,12,13,
    7,8,9,10,11,12,13,
    8,9,10,11,12,13,
    9,10,11,12,13,
    10,11,12,13,
    11,12,13,
    12,13,
    13};

// fast transcendentals: MUFU.EX2 + MUFU.RCP (~2^-21 rel err; budget is 1e-3)
__device__ __forceinline__ float silu_f(float x){ return __fdividef(x, 1.0f + __expf(-x)); }
__device__ __forceinline__ float sigm_f(float x){ return __fdividef(1.0f, 1.0f + __expf(-x)); }

// ---- packed fp32 (Blackwell FFMA2; PTX-only) ----
__device__ __forceinline__ u64 pack2(float lo, float hi){
    u64 r;
    asm("mov.b64 %0, {%1, %2};" : "=l"(r) : "r"(__float_as_uint(lo)), "r"(__float_as_uint(hi)));
    return r;
}
__device__ __forceinline__ void fma2(u64 &d, u64 a, u64 b){
    asm("fma.rn.f32x2 %0, %1, %2, %0;" : "+l"(d) : "l"(a), "l"(b));
}
__device__ __forceinline__ float hsum2(u64 v){
    unsigned lo, hi;
    asm("mov.b64 {%0, %1}, %2;" : "=r"(lo), "=r"(hi) : "l"(v));
    return __uint_as_float(lo) + __uint_as_float(hi);
}

// ---------------- K0: fold We1 radial rows by Gram symmetry ----------------
__global__ __launch_bounds__(128) void k_wsym(const float* __restrict__ We1)
{
    int u = blockIdx.x;        // feature row 0..NSYM-1 (uniform per block: no divergent LDC)
    int tj = threadIdx.x;
    float v;
    if (u < 14) {
        v = We1[(256 + u*14 + u)*128 + tj];
    } else if (u < 105) {
        int p = u - 14;
        int c = d_pc[p], e = d_pe[p];
        v = We1[(256 + c*14 + e)*128 + tj] + We1[(256 + e*14 + c)*128 + tj];
    } else {
        v = 0.0f;
    }
    g_wsym[u*128 + tj] = v;
}

// ---------------- K1: Hh = emb[S] + time_emb(t) ; y1 = We1_mid^T silu(Hh). 2 nodes/block ----
__global__ __launch_bounds__(128) void k_hh(
    const float* __restrict__ t, const int* __restrict__ S,
    const float* __restrict__ emb,
    const float* __restrict__ Wt1, const float* __restrict__ bt1,
    const float* __restrict__ Wt2, const float* __restrict__ bt2,
    const float* __restrict__ We1)
{
    int node0 = 2*blockIdx.x;
    int j = threadIdx.x;
    __shared__ float4 g4[2][32], h4[2][32], ssh[2][32];
    #pragma unroll
    for (int n = 0; n < 2; n++) {
        float tv = t[node0+n];
        float d = tv - (float)j*(1.0f/127.0f) + 1e-6f;
        ((float*)g4[n])[j] = expf(-8064.5f*d*d);   // precise exp (large args)
    }
    __syncthreads();
    float a[2] = {bt1[j], bt1[j]};
    #pragma unroll 4
    for (int i4 = 0; i4 < 32; i4++) {
        int i = 4*i4;
        float w0 = Wt1[(i+0)*128+j], w1 = Wt1[(i+1)*128+j];
        float w2 = Wt1[(i+2)*128+j], w3 = Wt1[(i+3)*128+j];
        #pragma unroll
        for (int n = 0; n < 2; n++) {
            float4 g = g4[n][i4];
            a[n] += g.x*w0 + g.y*w1 + g.z*w2 + g.w*w3;
        }
    }
    #pragma unroll
    for (int n = 0; n < 2; n++) ((float*)h4[n])[j] = fmaxf(a[n], 0.0f);
    __syncthreads();
    float a2[2] = {bt2[j], bt2[j]};
    #pragma unroll 4
    for (int i4 = 0; i4 < 32; i4++) {
        int i = 4*i4;
        float w0 = Wt2[(i+0)*128+j], w1 = Wt2[(i+1)*128+j];
        float w2 = Wt2[(i+2)*128+j], w3 = Wt2[(i+3)*128+j];
        #pragma unroll
        for (int n = 0; n < 2; n++) {
            float4 h = h4[n][i4];
            a2[n] += h.x*w0 + h.y*w1 + h.z*w2 + h.w*w3;
        }
    }
    #pragma unroll
    for (int n = 0; n < 2; n++) {
        float hv = emb[S[node0+n]*128+j] + a2[n];
        float sh = silu_f(hv);
        g_Hh[(node0+n)*128+j]  = hv;
        g_sHh[(node0+n)*128+j] = sh;
        ((float*)ssh[n])[j] = sh;
    }
    __syncthreads();
    // y1 = We1 rows [128,256) ^T . silu(Hh)
    float y[2] = {0.0f, 0.0f};
    #pragma unroll 4
    for (int i4 = 0; i4 < 32; i4++) {
        int i = 128 + 4*i4;
        float w0 = We1[(i+0)*128+j], w1 = We1[(i+1)*128+j];
        float w2 = We1[(i+2)*128+j], w3 = We1[(i+3)*128+j];
        #pragma unroll
        for (int n = 0; n < 2; n++) {
            float4 s = ssh[n][i4];
            y[n] += s.x*w0 + s.y*w1 + s.z*w2 + s.w*w3;
        }
    }
    #pragma unroll
    for (int n = 0; n < 2; n++) g_y1[(node0+n)*128+j] = y[n];
}

// ---------------- K2: top-9 nearest neighbors on ca = X[:,:,1,:] ----------------
__global__ __launch_bounds__(128) void k_knn(const float* __restrict__ X)
{
    __shared__ float sca[NN*3];
    int b = blockIdx.x >> 3;
    int tile = blockIdx.x & 7;
    int tj = threadIdx.x;
    for (int u = tj; u < NN*3; u += 128) {
        int n = u/3, d = u - n*3;
        sca[u] = X[((b*NN + n)*CC + 1)*3 + d];
    }
    __syncthreads();
    int n = tile*128 + tj;
    float qx = sca[n*3+0], qy = sca[n*3+1], qz = sca[n*3+2];
    float bd[KK]; int bi[KK];
    #pragma unroll
    for (int i = 0; i < KK; i++){ bd[i] = 1e30f; bi[i] = 0; }
    for (int j = 0; j < NN; j++) {
        float dx = qx - sca[j*3+0];
        float dy = qy - sca[j*3+1];
        float dz = qz - sca[j*3+2];
        float d = dx*dx + dy*dy + dz*dz;
        if (j == n) d = 1e30f;
        if (d < bd[KK-1]) {                  // strict <: stable tie order
            bd[KK-1] = d; bi[KK-1] = j;
            #pragma unroll
            for (int q = KK-1; q > 0; q--) {
                if (bd[q] < bd[q-1]) {
                    float td = bd[q]; bd[q] = bd[q-1]; bd[q-1] = td;
                    int   ti = bi[q]; bi[q] = bi[q-1]; bi[q-1] = ti;
                }
            }
        }
    }
    #pragma unroll
    for (int k = 0; k < KK; k++) g_idx[(b*NN + n)*KK + k] = bi[k];
}

// ---------------- K3: edge GEMMs + X_out + smsum, 2 nodes/block ----------
// GEMM loops: warp-per-node, 2 output channels per thread (ch, ch+64).
// Warps {0,1} -> node 0, {2,3} -> node 1: halves redundant activation LDS.
// xs4 compact symmetric radial (27 float4/edge); sm4 aliases xs4 after GEMM1;
// sbuf aliases sh14 after GEMM2. Gram pair table in SMEM.
__global__ __launch_bounds__(128) void k_edge(
    const float* __restrict__ X,
    const float* __restrict__ We1, const float* __restrict__ be1,
    const float* __restrict__ We2, const float* __restrict__ be2,
    const float* __restrict__ Wx1, const float* __restrict__ bx1,
    const float* __restrict__ Wx2, const float* __restrict__ bx2,
    float* __restrict__ out)
{
    int node0 = 2*blockIdx.x;
    int tj = threadIdx.x;
    int b = node0 >> 10;
    int wid  = tj >> 5, lane = tj & 31;
    int my_n = wid >> 1;                       // 0 or 1
    int ch   = ((wid & 1) << 5) | lane;        // 0..63; 2nd channel = ch+64

    __shared__ float4 xs4[2][288];     // radial (9 x 27 = 243 used) ; aliased by sm4 after GEMM1
    __shared__ float4 sh14[2][288];    // silu(h1): 9x128 ; aliased by sbuf after GEMM2
    __shared__ float  relb[2][KK][42];
    __shared__ float4 shc4[2][32];
    __shared__ float  xcen[2][42];
    __shared__ int    nbr[2][KK];
    __shared__ float  wk[2][KK];
    __shared__ float  wx2s[128];
    __shared__ uchar2 spair[91];       // (c*3, e*3) Gram pair table in smem

    #define SM4(n,k,i4)    xs4[n][(k)*32+(i4)]     // alias: valid after GEMM1
    #define SM4F(n,k)      ((float*)&xs4[n][(k)*32])
    #define SBUF4(n,k,i4)  sh14[n][(k)*32+(i4)]    // alias: valid after GEMM2
    #define SBUF4F(n,k)    ((float*)&sh14[n][(k)*32])

    {
        #pragma unroll
        for (int n = 0; n < 2; n++)
            ((float*)shc4[n])[tj] = g_sHh[(node0+n)*128 + tj];
        wx2s[tj] = Wx2[tj];
        if (tj < 84) { int n = tj/42, i = tj%42; xcen[n][i] = X[(node0+n)*CC*3 + i]; }
        if (tj < 2*KK) { int n = tj/KK, k = tj%KK; nbr[n][k] = g_idx[(node0+n)*KK + k]; }
        if (tj < 91) spair[tj] = make_uchar2((unsigned char)(d_pc[tj]*3),
                                             (unsigned char)(d_pe[tj]*3));
    }
    __syncthreads();

    // rel vectors
    for (int u = tj; u < 2*KK*42; u += 128) {
        int idx = u/42, i = u - idx*42;
        int n = idx/KK, k = idx%KK;
        relb[n][k][i] = xcen[n][i] - X[(b*NN + nbr[n][k])*CC*3 + i];
    }
    __syncthreads();

    // symmetric radial: 14 diag + 91 unique off-diag, silu'd; layout k*108+i
    for (int u = tj; u < 2*KK*NSYM; u += 128) {
        int idx = u/NSYM, i = u - idx*NSYM;
        int n = idx/KK, k = idx%KK;
        float sv = 0.0f;
        if (i < 105) {
            int c3, e3;
            if (i < 14) { c3 = i*3; e3 = c3; }
            else { uchar2 pr = spair[i-14]; c3 = pr.x; e3 = pr.y; }
            const float* r1 = &relb[n][k][c3];
            const float* r2 = &relb[n][k][e3];
            float rv = (r1[0]*r2[0] + r1[1]*r2[1] + r1[2]*r2[2]) * (1.0f/14.0f);
            sv = silu_f(rv);
        }
        ((float*)xs4[n])[k*NSYM + i] = sv;
    }
    __syncthreads();

    u64 acc0[KK], acc1[KK];

    // GEMM1: acc = base(center) + y1[neighbor] + Wsym^T . radial_sym
    // warp handles node my_n, channels ch and ch+64
    {
        float base0 = be1[ch], base1 = be1[ch+64];
        #pragma unroll 4
        for (int i4 = 0; i4 < 32; i4++) {
            int i = 4*i4;
            float4 a = shc4[my_n][i4];
            base0 += a.x*We1[(i+0)*128+ch]    + a.y*We1[(i+1)*128+ch]
                   + a.z*We1[(i+2)*128+ch]    + a.w*We1[(i+3)*128+ch];
            base1 += a.x*We1[(i+0)*128+ch+64] + a.y*We1[(i+1)*128+ch+64]
                   + a.z*We1[(i+2)*128+ch+64] + a.w*We1[(i+3)*128+ch+64];
        }
        #pragma unroll
        for (int k = 0; k < KK; k++) {
            int nb = (b*NN + nbr[my_n][k])*128;
            acc0[k] = pack2(base0 + g_y1[nb + ch], 0.0f);
            acc1[k] = pack2(base1 + g_y1[nb + ch + 64], 0.0f);
        }
        #pragma unroll 3
        for (int i4 = 0; i4 < 27; i4++) {
            int ib = 4*i4;
            u64 wA0 = pack2(g_wsym[(ib+0)*128+ch],    g_wsym[(ib+1)*128+ch]);
            u64 wB0 = pack2(g_wsym[(ib+2)*128+ch],    g_wsym[(ib+3)*128+ch]);
            u64 wA1 = pack2(g_wsym[(ib+0)*128+ch+64], g_wsym[(ib+1)*128+ch+64]);
            u64 wB1 = pack2(g_wsym[(ib+2)*128+ch+64], g_wsym[(ib+3)*128+ch+64]);
            const ulonglong2* xr = reinterpret_cast<const ulonglong2*>(xs4[my_n]);
            #pragma unroll
            for (int k = 0; k < KK; k++) {
                ulonglong2 a = xr[k*27 + i4];   // float off k*108+4*i4
                fma2(acc0[k], a.x, wA0); fma2(acc0[k], a.y, wB0);
                fma2(acc1[k], a.x, wA1); fma2(acc1[k], a.y, wB1);
            }
        }
        #pragma unroll
        for (int k = 0; k < KK; k++) {
            ((float*)&sh14[my_n][k*32])[ch]      = silu_f(hsum2(acc0[k]));
            ((float*)&sh14[my_n][k*32])[ch + 64] = silu_f(hsum2(acc1[k]));
        }
    }
    __syncthreads();

    // GEMM2: m = silu(h1) @ We2 + be2 ; smsum -> global (sm4 aliases dead xs4)
    {
        float bv0 = be2[ch], bv1 = be2[ch+64];
        #pragma unroll
        for (int k = 0; k < KK; k++) { acc0[k] = pack2(bv0, 0.0f); acc1[k] = pack2(bv1, 0.0f); }
        #pragma unroll 4
        for (int i4 = 0; i4 < 32; i4++) {
            int i = 4*i4;
            u64 wA0 = pack2(We2[(i+0)*128+ch],    We2[(i+1)*128+ch]);
            u64 wB0 = pack2(We2[(i+2)*128+ch],    We2[(i+3)*128+ch]);
            u64 wA1 = pack2(We2[(i+0)*128+ch+64], We2[(i+1)*128+ch+64]);
            u64 wB1 = pack2(We2[(i+2)*128+ch+64], We2[(i+3)*128+ch+64]);
            #pragma unroll
            for (int k = 0; k < KK; k++) {
                ulonglong2 a = *reinterpret_cast<const ulonglong2*>(&sh14[my_n][k*32 + i4]);
                fma2(acc0[k], a.x, wA0); fma2(acc0[k], a.y, wB0);
                fma2(acc1[k], a.x, wA1); fma2(acc1[k], a.y, wB1);
            }
        }
        float ms0 = 0.0f, ms1 = 0.0f;
        #pragma unroll
        for (int k = 0; k < KK; k++) {
            float m0 = hsum2(acc0[k]);
            float m1 = hsum2(acc1[k]);
            ms0 += m0; ms1 += m1;
            SM4F(my_n,k)[ch]      = silu_f(m0);
            SM4F(my_n,k)[ch + 64] = silu_f(m1);
        }
        g_smsum[(node0+my_n)*128 + ch]      = silu_f(ms0);
        g_smsum[(node0+my_n)*128 + ch + 64] = silu_f(ms1);
    }
    __syncthreads();

    // GEMM3: h2 = silu(m) @ Wx1 + bx1 ; sbuf = silu(h2)*Wx2 (alias over sh14, now dead)
    {
        float bv0 = bx1[ch], bv1 = bx1[ch+64];
        #pragma unroll
        for (int k = 0; k < KK; k++) { acc0[k] = pack2(bv0, 0.0f); acc1[k] = pack2(bv1, 0.0f); }
        #pragma unroll 4
        for (int i4 = 0; i4 < 32; i4++) {
            int i = 4*i4;
            u64 wA0 = pack2(Wx1[(i+0)*128+ch],    Wx1[(i+1)*128+ch]);
            u64 wB0 = pack2(Wx1[(i+2)*128+ch],    Wx1[(i+3)*128+ch]);
            u64 wA1 = pack2(Wx1[(i+0)*128+ch+64], Wx1[(i+1)*128+ch+64]);
            u64 wB1 = pack2(Wx1[(i+2)*128+ch+64], Wx1[(i+3)*128+ch+64]);
            #pragma unroll
            for (int k = 0; k < KK; k++) {
                ulonglong2 a = *reinterpret_cast<const ulonglong2*>(&SM4(my_n,k,i4));
                fma2(acc0[k], a.x, wA0); fma2(acc0[k], a.y, wB0);
                fma2(acc1[k], a.x, wA1); fma2(acc1[k], a.y, wB1);
            }
        }
        float wxv0 = wx2s[ch], wxv1 = wx2s[ch+64];
        __syncthreads();   // ensure all sh14 (silu(h1)) reads from GEMM2 are done block-wide
        #pragma unroll
        for (int k = 0; k < KK; k++) {
            SBUF4F(my_n,k)[ch]      = silu_f(hsum2(acc0[k])) * wxv0;
            SBUF4F(my_n,k)[ch + 64] = silu_f(hsum2(acc1[k])) * wxv1;
        }
    }
    __syncthreads();

    if (tj < 2*KK) {
        int n = tj/KK, k = tj%KK;
        float4 s4 = make_float4(0.f,0.f,0.f,0.f);
        #pragma unroll 8
        for (int i4 = 0; i4 < 32; i4++) {
            float4 v = SBUF4(n,k,i4);
            s4.x += v.x; s4.y += v.y; s4.z += v.z; s4.w += v.w;
        }
        wk[n][k] = bx2[0] + s4.x + s4.y + s4.z + s4.w;
    }
    __syncthreads();

    // X_out = X + mean_k(rel * w)
    if (tj < 84) {
        int n = tj/42, i = tj%42;
        float s = 0.0f;
        #pragma unroll
        for (int k = 0; k < KK; k++) s += relb[n][k][i]*wk[n][k];
        out[XOFF + (node0+n)*42 + i] = xcen[n][i] + s*(1.0f/9.0f);
    }
    #undef SM4
    #undef SM4F
    #undef SBUF4
    #undef SBUF4F
}

// ---------------- K3b: node-level GEMVs, 8 nodes/block (4x weight reuse) ----------
// Hn = Hh + FFN([Hh, smsum]); gate; logits; yT/yB.
#define NB 8
__global__ __launch_bounds__(128) void k_node(
    const int* __restrict__ S, const float* __restrict__ emb,
    const float* __restrict__ Wh1, const float* __restrict__ bh1,
    const float* __restrict__ Wh2, const float* __restrict__ bh2,
    const float* __restrict__ Wd1,
    const float* __restrict__ Wp1, const float* __restrict__ bp1,
    const float* __restrict__ Wr1, const float* __restrict__ br1,
    const float* __restrict__ Wr2, const float* __restrict__ br2,
    float* __restrict__ out)
{
    int node0 = NB*blockIdx.x;
    int tj = threadIdx.x;

    __shared__ float4 shc4[NB][32];   // silu(Hh)
    __shared__ float  hcr[NB][128];   // raw Hh
    __shared__ float4 sms4[NB][32];   // silu(sum_k m)
    __shared__ float4 snn4[NB][32];   // silu(Hn)
    __shared__ float4 sx04[NB][32];   // silu(H0*gate)
    __shared__ float4 tmpv4[NB][32];

    #pragma unroll
    for (int n = 0; n < NB; n++) {
        ((float*)shc4[n])[tj] = g_sHh[(node0+n)*128 + tj];
        hcr[n][tj] = g_Hh[(node0+n)*128 + tj];
        ((float*)sms4[n])[tj] = g_smsum[(node0+n)*128 + tj];
    }
    __syncthreads();

    u64 acc2[NB];

    // h = silu(Wh1^T [shc; sms] + bh1)
    {
        float bv = bh1[tj];
        #pragma unroll
        for (int n = 0; n < NB; n++) acc2[n] = pack2(bv, 0.0f);
        #pragma unroll 2
        for (int i4 = 0; i4 < 32; i4++) {
            int i = 4*i4;
            u64 wA = pack2(Wh1[(i+0)*128+tj], Wh1[(i+1)*128+tj]);
            u64 wB = pack2(Wh1[(i+2)*128+tj], Wh1[(i+3)*128+tj]);
            #pragma unroll
            for (int n = 0; n < NB; n++) {
                ulonglong2 a = *reinterpret_cast<const ulonglong2*>(&shc4[n][i4]);
                fma2(acc2[n], a.x, wA);
                fma2(acc2[n], a.y, wB);
            }
        }
        #pragma unroll 2
        for (int i4 = 0; i4 < 32; i4++) {
            int i = 128 + 4*i4;
            u64 wA = pack2(Wh1[(i+0)*128+tj], Wh1[(i+1)*128+tj]);
            u64 wB = pack2(Wh1[(i+2)*128+tj], Wh1[(i+3)*128+tj]);
            #pragma unroll
            for (int n = 0; n < NB; n++) {
                ulonglong2 a = *reinterpret_cast<const ulonglong2*>(&sms4[n][i4]);
                fma2(acc2[n], a.x, wA);
                fma2(acc2[n], a.y, wB);
            }
        }
        #pragma unroll
        for (int n = 0; n < NB; n++) ((float*)tmpv4[n])[tj] = silu_f(hsum2(acc2[n]));
    }
    __syncthreads();

    // Hn = Hh + Wh2^T h + bh2 ; snn = silu(Hn)
    {
        float bv = bh2[tj];
        #pragma unroll
        for (int n = 0; n < NB; n++) acc2[n] = pack2(hcr[n][tj] + bv, 0.0f);
        #pragma unroll 2
        for (int i4 = 0; i4 < 32; i4++) {
            int i = 4*i4;
            u64 wA = pack2(Wh2[(i+0)*128+tj], Wh2[(i+1)*128+tj]);
            u64 wB = pack2(Wh2[(i+2)*128+tj], Wh2[(i+3)*128+tj]);
            #pragma unroll
            for (int n = 0; n < NB; n++) {
                ulonglong2 a = *reinterpret_cast<const ulonglong2*>(&tmpv4[n][i4]);
                fma2(acc2[n], a.x, wA);
                fma2(acc2[n], a.y, wB);
            }
        }
        #pragma unroll
        for (int n = 0; n < NB; n++) {
            float shn = silu_f(hsum2(acc2[n]));
            g_sHn[(node0+n)*128 + tj] = shn;
            ((float*)snn4[n])[tj] = shn;
        }
    }
    __syncthreads();

    // gate = sigmoid(Wp1^T snn + bp1) ; sx0 = silu(H0*gate)
    {
        float bv = bp1[tj];
        #pragma unroll
        for (int n = 0; n < NB; n++) acc2[n] = pack2(bv, 0.0f);
        #pragma unroll 2
        for (int i4 = 0; i4 < 32; i4++) {
            int i = 4*i4;
            u64 wA = pack2(Wp1[(i+0)*128+tj], Wp1[(i+1)*128+tj]);
            u64 wB = pack2(Wp1[(i+2)*128+tj], Wp1[(i+3)*128+tj]);
            #pragma unroll
            for (int n = 0; n < NB; n++) {
                ulonglong2 a = *reinterpret_cast<const ulonglong2*>(&snn4[n][i4]);
                fma2(acc2[n], a.x, wA);
                fma2(acc2[n], a.y, wB);
            }
        }
        #pragma unroll
        for (int n = 0; n < NB; n++) {
            float gate = sigm_f(hsum2(acc2[n]));
            float h0 = emb[S[node0+n]*128 + tj];
            ((float*)sx04[n])[tj] = silu_f(h0*gate);
        }
    }

    // yT/yB = Wd1_top^T snn, Wd1_bot^T snn (snn already synced)
    {
        u64 aT[NB], aB[NB];
        #pragma unroll
        for (int n = 0; n < NB; n++){ aT[n] = 0ULL; aB[n] = 0ULL; }
        #pragma unroll 2
        for (int i4 = 0; i4 < 32; i4++) {
            int i = 4*i4;
            u64 t1 = pack2(Wd1[(i+0)*128+tj],     Wd1[(i+1)*128+tj]);
            u64 t2 = pack2(Wd1[(i+2)*128+tj],     Wd1[(i+3)*128+tj]);
            u64 b1 = pack2(Wd1[(128+i+0)*128+tj], Wd1[(128+i+1)*128+tj]);
            u64 b2 = pack2(Wd1[(128+i+2)*128+tj], Wd1[(128+i+3)*128+tj]);
            #pragma unroll
            for (int n = 0; n < NB; n++) {
                ulonglong2 a = *reinterpret_cast<const ulonglong2*>(&snn4[n][i4]);
                fma2(aT[n], a.x, t1); fma2(aT[n], a.y, t2);
                fma2(aB[n], a.x, b1); fma2(aB[n], a.y, b2);
            }
        }
        #pragma unroll
        for (int n = 0; n < NB; n++) {
            g_yT[(node0+n)*128+tj] = hsum2(aT[n]);
            g_yB[(node0+n)*128+tj] = hsum2(aB[n]);
        }
    }
    __syncthreads();

    // r1 = silu(Wr1^T sx0 + br1)
    {
        float bv = br1[tj];
        #pragma unroll
        for (int n = 0; n < NB; n++) acc2[n] = pack2(bv, 0.0f);
        #pragma unroll 2
        for (int i4 = 0; i4 < 32; i4++) {
            int i = 4*i4;
            u64 wA = pack2(Wr1[(i+0)*128+tj], Wr1[(i+1)*128+tj]);
            u64 wB = pack2(Wr1[(i+2)*128+tj], Wr1[(i+3)*128+tj]);
            #pragma unroll
            for (int n = 0; n < NB; n++) {
                ulonglong2 a = *reinterpret_cast<const ulonglong2*>(&sx04[n][i4]);
                fma2(acc2[n], a.x, wA);
                fma2(acc2[n], a.y, wB);
            }
        }
        #pragma unroll
        for (int n = 0; n < NB; n++) ((float*)tmpv4[n])[tj] = silu_f(hsum2(acc2[n]));
    }
    __syncthreads();

    // logits = Wr2^T r1 + br2
    if (tj < NCC) {
        float a[NB];
        float bv = br2[tj];
        #pragma unroll
        for (int n = 0; n < NB; n++) a[n] = bv;
        #pragma unroll 4
        for (int i4 = 0; i4 < 32; i4++) {
            int i = 4*i4;
            float w0 = Wr2[(i+0)*NCC+tj], w1 = Wr2[(i+1)*NCC+tj];
            float w2 = Wr2[(i+2)*NCC+tj], w3 = Wr2[(i+3)*NCC+tj];
            #pragma unroll
            for (int n = 0; n < NB; n++) {
                float4 h = tmpv4[n][i4];
                a[n] += h.x*w0 + h.y*w1 + h.z*w2 + h.w*w3;
            }
        }
        #pragma unroll
        for (int n = 0; n < NB; n++) out[(node0+n)*NCC + tj] = a[n];
    }
}

// ---------------- K4: pd — gather + silu + Wd2 dot (yT/yB precomputed) ----------
__global__ __launch_bounds__(128) void k_pd(
    const float* __restrict__ bd1,
    const float* __restrict__ Wd2, const float* __restrict__ bd2,
    float* __restrict__ out)
{
    int node0 = 2*blockIdx.x;
    int tj = threadIdx.x;
    int b = node0 >> 10;

    __shared__ float yTc[2][128], yBc[2][128];
    __shared__ int   nbr[2][KK];
    __shared__ float4 sAB4[2][KK][32];

    #pragma unroll
    for (int n = 0; n < 2; n++) {
        yTc[n][tj] = g_yT[(node0+n)*128 + tj];
        yBc[n][tj] = g_yB[(node0+n)*128 + tj];
    }
    if (tj < 2*KK) { int n = tj/KK, k = tj%KK; nbr[n][k] = g_idx[(node0+n)*KK + k]; }
    __syncthreads();

    float bd1v = bd1[tj];
    float wd2v = Wd2[tj];
    #pragma unroll
    for (int n = 0; n < 2; n++) {
        float ytc = yTc[n][tj] + bd1v;
        float ybc = yBc[n][tj] + bd1v;
        #pragma unroll
        for (int k = 0; k < KK; k++) {
            int d = (b*NN + nbr[n][k])*128 + tj;
            float aA = ytc + g_yB[d];     // [Hs,Hd]: top.hc + bot.hd + bd1
            float aB = g_yT[d] + ybc;     // [Hd,Hs]: top.hd + bot.hc + bd1
            ((float*)sAB4[n][k])[tj] = (silu_f(aA) + silu_f(aB)) * wd2v;
        }
    }
    __syncthreads();
    if (tj < 2*KK) {
        int n = tj/KK, k = tj%KK;
        float4 s4 = make_float4(0.f,0.f,0.f,0.f);
        #pragma unroll 8
        for (int i4 = 0; i4 < 32; i4++) {
            float4 v = sAB4[n][k][i4];
            s4.x += v.x; s4.y += v.y; s4.z += v.z; s4.w += v.w;
        }
        out[POFF + (node0+n)*KK + k] = 2.0f*bd2[0] + s4.x + s4.y + s4.z + s4.w;
    }
}

// ---------------- launcher ----------------
extern "C" void kernel_launch(void* const* d_in, const int* in_sizes, int n_in,
                              void* d_out, int out_size)
{
    const float* X   = (const float*)d_in[0];
    const int*   S   = (const int*)  d_in[1];
    const float* t   = (const float*)d_in[2];
    const float* emb = (const float*)d_in[3];
    const float* Wt1 = (const float*)d_in[4];
    const float* bt1 = (const float*)d_in[5];
    const float* Wt2 = (const float*)d_in[6];
    const float* bt2 = (const float*)d_in[7];
    const float* We1 = (const float*)d_in[8];
    const float* be1 = (const float*)d_in[9];
    const float* We2 = (const float*)d_in[10];
    const float* be2 = (const float*)d_in[11];
    const float* Wx1 = (const float*)d_in[12];
    const float* bx1 = (const float*)d_in[13];
    const float* Wx2 = (const float*)d_in[14];
    const float* bx2 = (const float*)d_in[15];
    const float* Wh1 = (const float*)d_in[16];
    const float* bh1 = (const float*)d_in[17];
    const float* Wh2 = (const float*)d_in[18];
    const float* bh2 = (const float*)d_in[19];
    const float* Wd1 = (const float*)d_in[20];
    const float* bd1 = (const float*)d_in[21];
    const float* Wd2 = (const float*)d_in[22];
    const float* bd2 = (const float*)d_in[23];
    const float* Wp1 = (const float*)d_in[24];
    const float* bp1 = (const float*)d_in[25];
    const float* Wr1 = (const float*)d_in[26];
    const float* br1 = (const float*)d_in[27];
    const float* Wr2 = (const float*)d_in[28];
    const float* br2 = (const float*)d_in[29];
    float* out = (float*)d_out;

    k_wsym<<<NSYM, 128>>>(We1);
    k_hh<<<NODES/2, 128>>>(t, S, emb, Wt1, bt1, Wt2, bt2, We1);
    k_knn<<<BB*(NN/128), 128>>>(X);
    k_edge<<<NODES/2, 128>>>(X,
                             We1, be1, We2, be2,
                             Wx1, bx1, Wx2, bx2,
                             out);
    k_node<<<NODES/NB, 128>>>(S, emb,
                              Wh1, bh1, Wh2, bh2,
                              Wd1,
                              Wp1, bp1, Wr1, br1, Wr2, br2,
                              out);
    k_pd<<<NODES/2, 128>>>(bd1, Wd2, bd2, out);
}

// round 17
// speedup vs baseline: 3.4776x; 1.0149x over previous
#include <cuda_runtime.h>
#include <math.h>

#define BB 32
#define NN 1024
#define CC 14
#define KK 9
#define EE 128
#define HH 128
#define NCC 25
#define NODES (BB*NN)

// output layout: logits (B,N,25) | X_out (B,N,14,3) | pd (B,N,9)
#define L_SZ (NODES*NCC)
#define X_SZ (NODES*CC*3)
#define XOFF L_SZ
#define POFF (L_SZ + X_SZ)

#define NSYM 108   // 14 diag + 91 off-diag unique Gram entries, padded to 108 (27 float4)

typedef unsigned long long u64;

// scratch (allowed: __device__ globals, no runtime alloc)
__device__ float g_Hh[NODES*EE];     // raw Hh
__device__ float g_sHh[NODES*EE];    // silu(Hh)
__device__ float g_y1[NODES*EE];     // We1[128:256]^T . silu(Hh[n])
__device__ float g_smsum[NODES*EE];  // silu(sum_k m)
__device__ float g_sHn[NODES*EE];    // silu(Hn)
__device__ float g_yT[NODES*EE];     // Wd1[0:128]^T   . silu(Hn[n])
__device__ float g_yB[NODES*EE];     // Wd1[128:256]^T . silu(Hn[n])
__device__ int   g_idx[NODES*KK];

// transposed pack-ready weights: T[i4][ch][j] = W[(4*i4+j)*128 + ch]
__device__ float g_tWt1 [32*EE*4];
__device__ float g_tWt2 [32*EE*4];
__device__ float g_tWe1c[32*EE*4];   // We1 rows 0..127 (center)
__device__ float g_tWe1m[32*EE*4];   // We1 rows 128..255 (neighbor)
__device__ float g_twsym[27*EE*4];   // symmetric-folded radial rows (written by k_wsym)
__device__ float g_tWe2 [32*EE*4];
__device__ float g_tWx1 [32*EE*4];
__device__ float g_tWh1 [64*EE*4];
__device__ float g_tWh2 [32*EE*4];
__device__ float g_tWp1 [32*EE*4];
__device__ float g_tWd1 [64*EE*4];   // i4 0..31 = top rows, 32..63 = bottom rows
__device__ float g_tWr1 [32*EE*4];

// off-diagonal pair enumeration (c<e), 91 pairs
__device__ __constant__ unsigned char d_pc[91] = {
    0,0,0,0,0,0,0,0,0,0,0,0,0,
    1,1,1,1,1,1,1,1,1,1,1,1,
    2,2,2,2,2,2,2,2,2,2,2,
    3,3,3,3,3,3,3,3,3,3,
    4,4,4,4,4,4,4,4,4,
    5,5,5,5,5,5,5,5,
    6,6,6,6,6,6,6,
    7,7,7,7,7,7,
    8,8,8,8,8,
    9,9,9,9,
    10,10,10,
    11,11,
    12};
__device__ __constant__ unsigned char d_pe[91] = {
    1,2,3,4,5,6,7,8,9,10,11,12,13,
    2,3,4,5,6,7,8,9,10,11,12,13,
    3,4,5,6,7,8,9,10,11,12,13,
    4,5,6,7,8,9,10,11,12,13,
    5,6,7,8,9,10,11,12,13,
    6,7,8,9,10,11,12,13,
    7,8,9,10,11,12,13,
    8,9,10,11,12,13,
    9,10,11,12,13,
    10,11,12,13,
    11,12,13,
    12,13,
    13};

// fast transcendentals: MUFU.EX2 + MUFU.RCP (~2^-21 rel err; budget is 1e-3)
__device__ __forceinline__ float silu_f(float x){ return __fdividef(x, 1.0f + __expf(-x)); }
__device__ __forceinline__ float sigm_f(float x){ return __fdividef(1.0f, 1.0f + __expf(-x)); }

// ---- packed fp32 (Blackwell FFMA2; PTX-only) ----
__device__ __forceinline__ u64 pack2(float lo, float hi){
    u64 r;
    asm("mov.b64 %0, {%1, %2};" : "=l"(r) : "r"(__float_as_uint(lo)), "r"(__float_as_uint(hi)));
    return r;
}
__device__ __forceinline__ void fma2(u64 &d, u64 a, u64 b){
    asm("fma.rn.f32x2 %0, %1, %2, %0;" : "+l"(d) : "l"(a), "l"(b));
}
__device__ __forceinline__ float hsum2(u64 v){
    unsigned lo, hi;
    asm("mov.b64 {%0, %1}, %2;" : "=r"(lo), "=r"(hi) : "l"(v));
    return __uint_as_float(lo) + __uint_as_float(hi);
}

// ---------------- K-1: generic transpose to pack-ready layout ----------------
__global__ __launch_bounds__(128) void k_tr(const float* __restrict__ src,
                                            float* __restrict__ dst, int row0)
{
    int i4 = blockIdx.x, tj = threadIdx.x;
    float4 v;
    v.x = src[(row0 + 4*i4 + 0)*128 + tj];
    v.y = src[(row0 + 4*i4 + 1)*128 + tj];
    v.z = src[(row0 + 4*i4 + 2)*128 + tj];
    v.w = src[(row0 + 4*i4 + 3)*128 + tj];
    *reinterpret_cast<float4*>(&dst[(i4*128 + tj)*4]) = v;
}

// ---------------- K0: fold We1 radial rows by Gram symmetry (writes transposed) ----------------
__global__ __launch_bounds__(128) void k_wsym(const float* __restrict__ We1)
{
    int u = blockIdx.x;        // feature row 0..NSYM-1 (uniform per block: no divergent LDC)
    int tj = threadIdx.x;
    float v;
    if (u < 14) {
        v = We1[(256 + u*14 + u)*128 + tj];
    } else if (u < 105) {
        int p = u - 14;
        int c = d_pc[p], e = d_pe[p];
        v = We1[(256 + c*14 + e)*128 + tj] + We1[(256 + e*14 + c)*128 + tj];
    } else {
        v = 0.0f;
    }
    g_twsym[(u >> 2)*512 + tj*4 + (u & 3)] = v;
}

// ---------------- K1: Hh = emb[S] + time_emb(t) ; y1 = We1_mid^T silu(Hh). 2 nodes/block ----
__global__ __launch_bounds__(128) void k_hh(
    const float* __restrict__ t, const int* __restrict__ S,
    const float* __restrict__ emb,
    const float* __restrict__ bt1, const float* __restrict__ bt2)
{
    int node0 = 2*blockIdx.x;
    int j = threadIdx.x;
    __shared__ float4 g4[2][32], h4[2][32], ssh[2][32];
    #pragma unroll
    for (int n = 0; n < 2; n++) {
        float tv = t[node0+n];
        float d = tv - (float)j*(1.0f/127.0f) + 1e-6f;
        ((float*)g4[n])[j] = expf(-8064.5f*d*d);   // precise exp (large args)
    }
    __syncthreads();
    float a[2] = {bt1[j], bt1[j]};
    #pragma unroll 4
    for (int i4 = 0; i4 < 32; i4++) {
        float4 w = *reinterpret_cast<const float4*>(&g_tWt1[(i4*128 + j)*4]);
        #pragma unroll
        for (int n = 0; n < 2; n++) {
            float4 g = g4[n][i4];
            a[n] += g.x*w.x + g.y*w.y + g.z*w.z + g.w*w.w;
        }
    }
    #pragma unroll
    for (int n = 0; n < 2; n++) ((float*)h4[n])[j] = fmaxf(a[n], 0.0f);
    __syncthreads();
    float a2[2] = {bt2[j], bt2[j]};
    #pragma unroll 4
    for (int i4 = 0; i4 < 32; i4++) {
        float4 w = *reinterpret_cast<const float4*>(&g_tWt2[(i4*128 + j)*4]);
        #pragma unroll
        for (int n = 0; n < 2; n++) {
            float4 h = h4[n][i4];
            a2[n] += h.x*w.x + h.y*w.y + h.z*w.z + h.w*w.w;
        }
    }
    #pragma unroll
    for (int n = 0; n < 2; n++) {
        float hv = emb[S[node0+n]*128+j] + a2[n];
        float sh = silu_f(hv);
        g_Hh[(node0+n)*128+j]  = hv;
        g_sHh[(node0+n)*128+j] = sh;
        ((float*)ssh[n])[j] = sh;
    }
    __syncthreads();
    // y1 = We1 rows [128,256) ^T . silu(Hh)
    float y[2] = {0.0f, 0.0f};
    #pragma unroll 4
    for (int i4 = 0; i4 < 32; i4++) {
        float4 w = *reinterpret_cast<const float4*>(&g_tWe1m[(i4*128 + j)*4]);
        #pragma unroll
        for (int n = 0; n < 2; n++) {
            float4 s = ssh[n][i4];
            y[n] += s.x*w.x + s.y*w.y + s.z*w.z + s.w*w.w;
        }
    }
    #pragma unroll
    for (int n = 0; n < 2; n++) g_y1[(node0+n)*128+j] = y[n];
}

// ---------------- K2: top-9 nearest neighbors on ca = X[:,:,1,:] ----------------
__global__ __launch_bounds__(128) void k_knn(const float* __restrict__ X)
{
    __shared__ float sca[NN*3];
    int b = blockIdx.x >> 3;
    int tile = blockIdx.x & 7;
    int tj = threadIdx.x;
    for (int u = tj; u < NN*3; u += 128) {
        int n = u/3, d = u - n*3;
        sca[u] = X[((b*NN + n)*CC + 1)*3 + d];
    }
    __syncthreads();
    int n = tile*128 + tj;
    float qx = sca[n*3+0], qy = sca[n*3+1], qz = sca[n*3+2];
    float bd[KK]; int bi[KK];
    #pragma unroll
    for (int i = 0; i < KK; i++){ bd[i] = 1e30f; bi[i] = 0; }
    for (int j = 0; j < NN; j++) {
        float dx = qx - sca[j*3+0];
        float dy = qy - sca[j*3+1];
        float dz = qz - sca[j*3+2];
        float d = dx*dx + dy*dy + dz*dz;
        if (j == n) d = 1e30f;
        if (d < bd[KK-1]) {                  // strict <: stable tie order
            bd[KK-1] = d; bi[KK-1] = j;
            #pragma unroll
            for (int q = KK-1; q > 0; q--) {
                if (bd[q] < bd[q-1]) {
                    float td = bd[q]; bd[q] = bd[q-1]; bd[q-1] = td;
                    int   ti = bi[q]; bi[q] = bi[q-1]; bi[q-1] = ti;
                }
            }
        }
    }
    #pragma unroll
    for (int k = 0; k < KK; k++) g_idx[(b*NN + n)*KK + k] = bi[k];
}

// ---------------- K3: edge GEMMs + X_out + smsum, 2 nodes/block ----------
// GEMM loops: warp-per-node, 2 output channels per thread (ch, ch+64);
// weights come from transposed pack-ready layout (1 LDG.128 = 2 f32x2 operands).
__global__ __launch_bounds__(128) void k_edge(
    const float* __restrict__ X,
    const float* __restrict__ be1, const float* __restrict__ be2,
    const float* __restrict__ bx1,
    const float* __restrict__ Wx2, const float* __restrict__ bx2,
    float* __restrict__ out)
{
    int node0 = 2*blockIdx.x;
    int tj = threadIdx.x;
    int b = node0 >> 10;
    int wid  = tj >> 5, lane = tj & 31;
    int my_n = wid >> 1;                       // 0 or 1
    int ch   = ((wid & 1) << 5) | lane;        // 0..63; 2nd channel = ch+64

    __shared__ float4 xs4[2][288];     // radial (9 x 27 = 243 used) ; aliased by sm4 after GEMM1
    __shared__ float4 sh14[2][288];    // silu(h1): 9x128 ; aliased by sbuf after GEMM2
    __shared__ float  relb[2][KK][42];
    __shared__ float4 shc4[2][32];
    __shared__ float  xcen[2][42];
    __shared__ int    nbr[2][KK];
    __shared__ float  wk[2][KK];
    __shared__ float  wx2s[128];
    __shared__ uchar2 spair[91];       // (c*3, e*3) Gram pair table in smem

    #define SM4(n,k,i4)    xs4[n][(k)*32+(i4)]     // alias: valid after GEMM1
    #define SM4F(n,k)      ((float*)&xs4[n][(k)*32])
    #define SBUF4(n,k,i4)  sh14[n][(k)*32+(i4)]    // alias: valid after GEMM2
    #define SBUF4F(n,k)    ((float*)&sh14[n][(k)*32])

    {
        #pragma unroll
        for (int n = 0; n < 2; n++)
            ((float*)shc4[n])[tj] = g_sHh[(node0+n)*128 + tj];
        wx2s[tj] = Wx2[tj];
        if (tj < 84) { int n = tj/42, i = tj%42; xcen[n][i] = X[(node0+n)*CC*3 + i]; }
        if (tj < 2*KK) { int n = tj/KK, k = tj%KK; nbr[n][k] = g_idx[(node0+n)*KK + k]; }
        if (tj < 91) spair[tj] = make_uchar2((unsigned char)(d_pc[tj]*3),
                                             (unsigned char)(d_pe[tj]*3));
    }
    __syncthreads();

    // rel vectors
    for (int u = tj; u < 2*KK*42; u += 128) {
        int idx = u/42, i = u - idx*42;
        int n = idx/KK, k = idx%KK;
        relb[n][k][i] = xcen[n][i] - X[(b*NN + nbr[n][k])*CC*3 + i];
    }
    __syncthreads();

    // symmetric radial: 14 diag + 91 unique off-diag, silu'd; layout k*108+i
    for (int u = tj; u < 2*KK*NSYM; u += 128) {
        int idx = u/NSYM, i = u - idx*NSYM;
        int n = idx/KK, k = idx%KK;
        float sv = 0.0f;
        if (i < 105) {
            int c3, e3;
            if (i < 14) { c3 = i*3; e3 = c3; }
            else { uchar2 pr = spair[i-14]; c3 = pr.x; e3 = pr.y; }
            const float* r1 = &relb[n][k][c3];
            const float* r2 = &relb[n][k][e3];
            float rv = (r1[0]*r2[0] + r1[1]*r2[1] + r1[2]*r2[2]) * (1.0f/14.0f);
            sv = silu_f(rv);
        }
        ((float*)xs4[n])[k*NSYM + i] = sv;
    }
    __syncthreads();

    u64 acc0[KK], acc1[KK];

    // GEMM1: acc = base(center) + y1[neighbor] + Wsym^T . radial_sym
    {
        float base0 = be1[ch], base1 = be1[ch+64];
        #pragma unroll 4
        for (int i4 = 0; i4 < 32; i4++) {
            float4 a = shc4[my_n][i4];
            float4 w0 = *reinterpret_cast<const float4*>(&g_tWe1c[(i4*128 + ch)*4]);
            float4 w1 = *reinterpret_cast<const float4*>(&g_tWe1c[(i4*128 + ch + 64)*4]);
            base0 += a.x*w0.x + a.y*w0.y + a.z*w0.z + a.w*w0.w;
            base1 += a.x*w1.x + a.y*w1.y + a.z*w1.z + a.w*w1.w;
        }
        #pragma unroll
        for (int k = 0; k < KK; k++) {
            int nb = (b*NN + nbr[my_n][k])*128;
            acc0[k] = pack2(base0 + g_y1[nb + ch], 0.0f);
            acc1[k] = pack2(base1 + g_y1[nb + ch + 64], 0.0f);
        }
        #pragma unroll 3
        for (int i4 = 0; i4 < 27; i4++) {
            ulonglong2 W0 = *reinterpret_cast<const ulonglong2*>(&g_twsym[(i4*128 + ch)*4]);
            ulonglong2 W1 = *reinterpret_cast<const ulonglong2*>(&g_twsym[(i4*128 + ch + 64)*4]);
            const ulonglong2* xr = reinterpret_cast<const ulonglong2*>(xs4[my_n]);
            #pragma unroll
            for (int k = 0; k < KK; k++) {
                ulonglong2 a = xr[k*27 + i4];   // float off k*108+4*i4
                fma2(acc0[k], a.x, W0.x); fma2(acc0[k], a.y, W0.y);
                fma2(acc1[k], a.x, W1.x); fma2(acc1[k], a.y, W1.y);
            }
        }
        #pragma unroll
        for (int k = 0; k < KK; k++) {
            ((float*)&sh14[my_n][k*32])[ch]      = silu_f(hsum2(acc0[k]));
            ((float*)&sh14[my_n][k*32])[ch + 64] = silu_f(hsum2(acc1[k]));
        }
    }
    __syncthreads();

    // GEMM2: m = silu(h1) @ We2 + be2 ; smsum -> global (sm4 aliases dead xs4)
    {
        float bv0 = be2[ch], bv1 = be2[ch+64];
        #pragma unroll
        for (int k = 0; k < KK; k++) { acc0[k] = pack2(bv0, 0.0f); acc1[k] = pack2(bv1, 0.0f); }
        #pragma unroll 4
        for (int i4 = 0; i4 < 32; i4++) {
            ulonglong2 W0 = *reinterpret_cast<const ulonglong2*>(&g_tWe2[(i4*128 + ch)*4]);
            ulonglong2 W1 = *reinterpret_cast<const ulonglong2*>(&g_tWe2[(i4*128 + ch + 64)*4]);
            #pragma unroll
            for (int k = 0; k < KK; k++) {
                ulonglong2 a = *reinterpret_cast<const ulonglong2*>(&sh14[my_n][k*32 + i4]);
                fma2(acc0[k], a.x, W0.x); fma2(acc0[k], a.y, W0.y);
                fma2(acc1[k], a.x, W1.x); fma2(acc1[k], a.y, W1.y);
            }
        }
        float ms0 = 0.0f, ms1 = 0.0f;
        #pragma unroll
        for (int k = 0; k < KK; k++) {
            float m0 = hsum2(acc0[k]);
            float m1 = hsum2(acc1[k]);
            ms0 += m0; ms1 += m1;
            SM4F(my_n,k)[ch]      = silu_f(m0);
            SM4F(my_n,k)[ch + 64] = silu_f(m1);
        }
        g_smsum[(node0+my_n)*128 + ch]      = silu_f(ms0);
        g_smsum[(node0+my_n)*128 + ch + 64] = silu_f(ms1);
    }
    __syncthreads();

    // GEMM3: h2 = silu(m) @ Wx1 + bx1 ; sbuf = silu(h2)*Wx2 (alias over sh14, now dead)
    {
        float bv0 = bx1[ch], bv1 = bx1[ch+64];
        #pragma unroll
        for (int k = 0; k < KK; k++) { acc0[k] = pack2(bv0, 0.0f); acc1[k] = pack2(bv1, 0.0f); }
        #pragma unroll 4
        for (int i4 = 0; i4 < 32; i4++) {
            ulonglong2 W0 = *reinterpret_cast<const ulonglong2*>(&g_tWx1[(i4*128 + ch)*4]);
            ulonglong2 W1 = *reinterpret_cast<const ulonglong2*>(&g_tWx1[(i4*128 + ch + 64)*4]);
            #pragma unroll
            for (int k = 0; k < KK; k++) {
                ulonglong2 a = *reinterpret_cast<const ulonglong2*>(&SM4(my_n,k,i4));
                fma2(acc0[k], a.x, W0.x); fma2(acc0[k], a.y, W0.y);
                fma2(acc1[k], a.x, W1.x); fma2(acc1[k], a.y, W1.y);
            }
        }
        float wxv0 = wx2s[ch], wxv1 = wx2s[ch+64];
        __syncthreads();   // ensure all sh14 (silu(h1)) reads from GEMM2 are done block-wide
        #pragma unroll
        for (int k = 0; k < KK; k++) {
            SBUF4F(my_n,k)[ch]      = silu_f(hsum2(acc0[k])) * wxv0;
            SBUF4F(my_n,k)[ch + 64] = silu_f(hsum2(acc1[k])) * wxv1;
        }
    }
    __syncthreads();

    if (tj < 2*KK) {
        int n = tj/KK, k = tj%KK;
        float4 s4 = make_float4(0.f,0.f,0.f,0.f);
        #pragma unroll 8
        for (int i4 = 0; i4 < 32; i4++) {
            float4 v = SBUF4(n,k,i4);
            s4.x += v.x; s4.y += v.y; s4.z += v.z; s4.w += v.w;
        }
        wk[n][k] = bx2[0] + s4.x + s4.y + s4.z + s4.w;
    }
    __syncthreads();

    // X_out = X + mean_k(rel * w)
    if (tj < 84) {
        int n = tj/42, i = tj%42;
        float s = 0.0f;
        #pragma unroll
        for (int k = 0; k < KK; k++) s += relb[n][k][i]*wk[n][k];
        out[XOFF + (node0+n)*42 + i] = xcen[n][i] + s*(1.0f/9.0f);
    }
    #undef SM4
    #undef SM4F
    #undef SBUF4
    #undef SBUF4F
}

// ---------------- K3b: node-level GEMVs, 8 nodes/block (4x weight reuse) ----------
// Hn = Hh + FFN([Hh, smsum]); gate; logits; yT/yB. Transposed weights: 1 LDG.128/i4.
#define NB 8
__global__ __launch_bounds__(128) void k_node(
    const int* __restrict__ S, const float* __restrict__ emb,
    const float* __restrict__ bh1, const float* __restrict__ bh2,
    const float* __restrict__ bp1,
    const float* __restrict__ br1,
    const float* __restrict__ Wr2, const float* __restrict__ br2,
    float* __restrict__ out)
{
    int node0 = NB*blockIdx.x;
    int tj = threadIdx.x;

    __shared__ float4 shc4[NB][32];   // silu(Hh)
    __shared__ float  hcr[NB][128];   // raw Hh
    __shared__ float4 sms4[NB][32];   // silu(sum_k m)
    __shared__ float4 snn4[NB][32];   // silu(Hn)
    __shared__ float4 sx04[NB][32];   // silu(H0*gate)
    __shared__ float4 tmpv4[NB][32];

    #pragma unroll
    for (int n = 0; n < NB; n++) {
        ((float*)shc4[n])[tj] = g_sHh[(node0+n)*128 + tj];
        hcr[n][tj] = g_Hh[(node0+n)*128 + tj];
        ((float*)sms4[n])[tj] = g_smsum[(node0+n)*128 + tj];
    }
    __syncthreads();

    u64 acc2[NB];

    // h = silu(Wh1^T [shc; sms] + bh1)
    {
        float bv = bh1[tj];
        #pragma unroll
        for (int n = 0; n < NB; n++) acc2[n] = pack2(bv, 0.0f);
        #pragma unroll 2
        for (int i4 = 0; i4 < 32; i4++) {
            ulonglong2 W = *reinterpret_cast<const ulonglong2*>(&g_tWh1[(i4*128 + tj)*4]);
            #pragma unroll
            for (int n = 0; n < NB; n++) {
                ulonglong2 a = *reinterpret_cast<const ulonglong2*>(&shc4[n][i4]);
                fma2(acc2[n], a.x, W.x);
                fma2(acc2[n], a.y, W.y);
            }
        }
        #pragma unroll 2
        for (int i4 = 0; i4 < 32; i4++) {
            ulonglong2 W = *reinterpret_cast<const ulonglong2*>(&g_tWh1[((32+i4)*128 + tj)*4]);
            #pragma unroll
            for (int n = 0; n < NB; n++) {
                ulonglong2 a = *reinterpret_cast<const ulonglong2*>(&sms4[n][i4]);
                fma2(acc2[n], a.x, W.x);
                fma2(acc2[n], a.y, W.y);
            }
        }
        #pragma unroll
        for (int n = 0; n < NB; n++) ((float*)tmpv4[n])[tj] = silu_f(hsum2(acc2[n]));
    }
    __syncthreads();

    // Hn = Hh + Wh2^T h + bh2 ; snn = silu(Hn)
    {
        float bv = bh2[tj];
        #pragma unroll
        for (int n = 0; n < NB; n++) acc2[n] = pack2(hcr[n][tj] + bv, 0.0f);
        #pragma unroll 2
        for (int i4 = 0; i4 < 32; i4++) {
            ulonglong2 W = *reinterpret_cast<const ulonglong2*>(&g_tWh2[(i4*128 + tj)*4]);
            #pragma unroll
            for (int n = 0; n < NB; n++) {
                ulonglong2 a = *reinterpret_cast<const ulonglong2*>(&tmpv4[n][i4]);
                fma2(acc2[n], a.x, W.x);
                fma2(acc2[n], a.y, W.y);
            }
        }
        #pragma unroll
        for (int n = 0; n < NB; n++) {
            float shn = silu_f(hsum2(acc2[n]));
            g_sHn[(node0+n)*128 + tj] = shn;
            ((float*)snn4[n])[tj] = shn;
        }
    }
    __syncthreads();

    // gate = sigmoid(Wp1^T snn + bp1) ; sx0 = silu(H0*gate)
    {
        float bv = bp1[tj];
        #pragma unroll
        for (int n = 0; n < NB; n++) acc2[n] = pack2(bv, 0.0f);
        #pragma unroll 2
        for (int i4 = 0; i4 < 32; i4++) {
            ulonglong2 W = *reinterpret_cast<const ulonglong2*>(&g_tWp1[(i4*128 + tj)*4]);
            #pragma unroll
            for (int n = 0; n < NB; n++) {
                ulonglong2 a = *reinterpret_cast<const ulonglong2*>(&snn4[n][i4]);
                fma2(acc2[n], a.x, W.x);
                fma2(acc2[n], a.y, W.y);
            }
        }
        #pragma unroll
        for (int n = 0; n < NB; n++) {
            float gate = sigm_f(hsum2(acc2[n]));
            float h0 = emb[S[node0+n]*128 + tj];
            ((float*)sx04[n])[tj] = silu_f(h0*gate);
        }
    }

    // yT/yB = Wd1_top^T snn, Wd1_bot^T snn (snn already synced)
    {
        u64 aT[NB], aB[NB];
        #pragma unroll
        for (int n = 0; n < NB; n++){ aT[n] = 0ULL; aB[n] = 0ULL; }
        #pragma unroll 2
        for (int i4 = 0; i4 < 32; i4++) {
            ulonglong2 Wt = *reinterpret_cast<const ulonglong2*>(&g_tWd1[(i4*128 + tj)*4]);
            ulonglong2 Wb = *reinterpret_cast<const ulonglong2*>(&g_tWd1[((32+i4)*128 + tj)*4]);
            #pragma unroll
            for (int n = 0; n < NB; n++) {
                ulonglong2 a = *reinterpret_cast<const ulonglong2*>(&snn4[n][i4]);
                fma2(aT[n], a.x, Wt.x); fma2(aT[n], a.y, Wt.y);
                fma2(aB[n], a.x, Wb.x); fma2(aB[n], a.y, Wb.y);
            }
        }
        #pragma unroll
        for (int n = 0; n < NB; n++) {
            g_yT[(node0+n)*128+tj] = hsum2(aT[n]);
            g_yB[(node0+n)*128+tj] = hsum2(aB[n]);
        }
    }
    __syncthreads();

    // r1 = silu(Wr1^T sx0 + br1)
    {
        float bv = br1[tj];
        #pragma unroll
        for (int n = 0; n < NB; n++) acc2[n] = pack2(bv, 0.0f);
        #pragma unroll 2
        for (int i4 = 0; i4 < 32; i4++) {
            ulonglong2 W = *reinterpret_cast<const ulonglong2*>(&g_tWr1[(i4*128 + tj)*4]);
            #pragma unroll
            for (int n = 0; n < NB; n++) {
                ulonglong2 a = *reinterpret_cast<const ulonglong2*>(&sx04[n][i4]);
                fma2(acc2[n], a.x, W.x);
                fma2(acc2[n], a.y, W.y);
            }
        }
        #pragma unroll
        for (int n = 0; n < NB; n++) ((float*)tmpv4[n])[tj] = silu_f(hsum2(acc2[n]));
    }
    __syncthreads();

    // logits = Wr2^T r1 + br2
    if (tj < NCC) {
        float a[NB];
        float bv = br2[tj];
        #pragma unroll
        for (int n = 0; n < NB; n++) a[n] = bv;
        #pragma unroll 4
        for (int i4 = 0; i4 < 32; i4++) {
            int i = 4*i4;
            float w0 = Wr2[(i+0)*NCC+tj], w1 = Wr2[(i+1)*NCC+tj];
            float w2 = Wr2[(i+2)*NCC+tj], w3 = Wr2[(i+3)*NCC+tj];
            #pragma unroll
            for (int n = 0; n < NB; n++) {
                float4 h = tmpv4[n][i4];
                a[n] += h.x*w0 + h.y*w1 + h.z*w2 + h.w*w3;
            }
        }
        #pragma unroll
        for (int n = 0; n < NB; n++) out[(node0+n)*NCC + tj] = a[n];
    }
}

// ---------------- K4: pd — gather + silu + Wd2 dot (yT/yB precomputed) ----------
__global__ __launch_bounds__(128) void k_pd(
    const float* __restrict__ bd1,
    const float* __restrict__ Wd2, const float* __restrict__ bd2,
    float* __restrict__ out)
{
    int node0 = 2*blockIdx.x;
    int tj = threadIdx.x;
    int b = node0 >> 10;

    __shared__ float yTc[2][128], yBc[2][128];
    __shared__ int   nbr[2][KK];
    __shared__ float4 sAB4[2][KK][32];

    #pragma unroll
    for (int n = 0; n < 2; n++) {
        yTc[n][tj] = g_yT[(node0+n)*128 + tj];
        yBc[n][tj] = g_yB[(node0+n)*128 + tj];
    }
    if (tj < 2*KK) { int n = tj/KK, k = tj%KK; nbr[n][k] = g_idx[(node0+n)*KK + k]; }
    __syncthreads();

    float bd1v = bd1[tj];
    float wd2v = Wd2[tj];
    #pragma unroll
    for (int n = 0; n < 2; n++) {
        float ytc = yTc[n][tj] + bd1v;
        float ybc = yBc[n][tj] + bd1v;
        #pragma unroll
        for (int k = 0; k < KK; k++) {
            int d = (b*NN + nbr[n][k])*128 + tj;
            float aA = ytc + g_yB[d];     // [Hs,Hd]: top.hc + bot.hd + bd1
            float aB = g_yT[d] + ybc;     // [Hd,Hs]: top.hd + bot.hc + bd1
            ((float*)sAB4[n][k])[tj] = (silu_f(aA) + silu_f(aB)) * wd2v;
        }
    }
    __syncthreads();
    if (tj < 2*KK) {
        int n = tj/KK, k = tj%KK;
        float4 s4 = make_float4(0.f,0.f,0.f,0.f);
        #pragma unroll 8
        for (int i4 = 0; i4 < 32; i4++) {
            float4 v = sAB4[n][k][i4];
            s4.x += v.x; s4.y += v.y; s4.z += v.z; s4.w += v.w;
        }
        out[POFF + (node0+n)*KK + k] = 2.0f*bd2[0] + s4.x + s4.y + s4.z + s4.w;
    }
}

// ---------------- launcher ----------------
extern "C" void kernel_launch(void* const* d_in, const int* in_sizes, int n_in,
                              void* d_out, int out_size)
{
    const float* X   = (const float*)d_in[0];
    const int*   S   = (const int*)  d_in[1];
    const float* t   = (const float*)d_in[2];
    const float* emb = (const float*)d_in[3];
    const float* Wt1 = (const float*)d_in[4];
    const float* bt1 = (const float*)d_in[5];
    const float* Wt2 = (const float*)d_in[6];
    const float* bt2 = (const float*)d_in[7];
    const float* We1 = (const float*)d_in[8];
    const float* be1 = (const float*)d_in[9];
    const float* We2 = (const float*)d_in[10];
    const float* be2 = (const float*)d_in[11];
    const float* Wx1 = (const float*)d_in[12];
    const float* bx1 = (const float*)d_in[13];
    const float* Wx2 = (const float*)d_in[14];
    const float* bx2 = (const float*)d_in[15];
    const float* Wh1 = (const float*)d_in[16];
    const float* bh1 = (const float*)d_in[17];
    const float* Wh2 = (const float*)d_in[18];
    const float* bh2 = (const float*)d_in[19];
    const float* Wd1 = (const float*)d_in[20];
    const float* bd1 = (const float*)d_in[21];
    const float* Wd2 = (const float*)d_in[22];
    const float* bd2 = (const float*)d_in[23];
    const float* Wp1 = (const float*)d_in[24];
    const float* bp1 = (const float*)d_in[25];
    const float* Wr1 = (const float*)d_in[26];
    const float* br1 = (const float*)d_in[27];
    const float* Wr2 = (const float*)d_in[28];
    const float* br2 = (const float*)d_in[29];
    float* out = (float*)d_out;

    float *p;
    cudaGetSymbolAddress((void**)&p, g_tWt1);  k_tr<<<32,128>>>(Wt1, p, 0);
    cudaGetSymbolAddress((void**)&p, g_tWt2);  k_tr<<<32,128>>>(Wt2, p, 0);
    cudaGetSymbolAddress((void**)&p, g_tWe1c); k_tr<<<32,128>>>(We1, p, 0);
    cudaGetSymbolAddress((void**)&p, g_tWe1m); k_tr<<<32,128>>>(We1, p, 128);
    cudaGetSymbolAddress((void**)&p, g_tWe2);  k_tr<<<32,128>>>(We2, p, 0);
    cudaGetSymbolAddress((void**)&p, g_tWx1);  k_tr<<<32,128>>>(Wx1, p, 0);
    cudaGetSymbolAddress((void**)&p, g_tWh1);  k_tr<<<64,128>>>(Wh1, p, 0);
    cudaGetSymbolAddress((void**)&p, g_tWh2);  k_tr<<<32,128>>>(Wh2, p, 0);
    cudaGetSymbolAddress((void**)&p, g_tWp1);  k_tr<<<32,128>>>(Wp1, p, 0);
    cudaGetSymbolAddress((void**)&p, g_tWd1);  k_tr<<<64,128>>>(Wd1, p, 0);
    cudaGetSymbolAddress((void**)&p, g_tWr1);  k_tr<<<32,128>>>(Wr1, p, 0);
    k_wsym<<<NSYM, 128>>>(We1);
    k_hh<<<NODES/2, 128>>>(t, S, emb, bt1, bt2);
    k_knn<<<BB*(NN/128), 128>>>(X);
    k_edge<<<NODES/2, 128>>>(X, be1, be2, bx1, Wx2, bx2, out);
    k_node<<<NODES/NB, 128>>>(S, emb, bh1, bh2, bp1, br1, Wr2, br2, out);
    k_pd<<<NODES/2, 128>>>(bd1, Wd2, bd2, out);
}